// round 6
// baseline (speedup 1.0000x reference)
#include <cuda_runtime.h>
#include <cuda_bf16.h>
#include <cstdint>
#include <math.h>

// Problem constants
#define B_   2
#define S_   2048
#define D_   2048
#define H_   16
#define HD_  128
#define M_   (B_ * S_)     // 4096
#define F_   (H_ * HD_)    // 2048
#define NQKV (3 * F_)      // 6144

typedef unsigned long long u64;
typedef unsigned int u32;

__device__ __forceinline__ u32 smem_u32(const void* p) {
    u32 a; asm("{ .reg .u64 t; cvta.to.shared.u64 t, %1; cvt.u32.u64 %0, t; }" : "=r"(a) : "l"(p));
    return a;
}

// ---- mma.sync / ldmatrix / cp.async ----
__device__ __forceinline__ void ldsm4(u32* r, u32 addr) {
    asm volatile("ldmatrix.sync.aligned.m8n8.x4.shared.b16 {%0,%1,%2,%3}, [%4];"
        : "=r"(r[0]), "=r"(r[1]), "=r"(r[2]), "=r"(r[3]) : "r"(addr));
}
__device__ __forceinline__ void ldsm4t(u32* r, u32 addr) {
    asm volatile("ldmatrix.sync.aligned.m8n8.x4.trans.shared.b16 {%0,%1,%2,%3}, [%4];"
        : "=r"(r[0]), "=r"(r[1]), "=r"(r[2]), "=r"(r[3]) : "r"(addr));
}
__device__ __forceinline__ void mma16816(float* d, const u32* a, const u32* b) {
    asm volatile("mma.sync.aligned.m16n8k16.row.col.f32.bf16.bf16.f32 "
        "{%0,%1,%2,%3}, {%4,%5,%6,%7}, {%8,%9}, {%0,%1,%2,%3};"
        : "+f"(d[0]), "+f"(d[1]), "+f"(d[2]), "+f"(d[3])
        : "r"(a[0]), "r"(a[1]), "r"(a[2]), "r"(a[3]), "r"(b[0]), "r"(b[1]));
}
__device__ __forceinline__ void cp_async16(u32 dst, const void* src) {
    asm volatile("cp.async.cg.shared.global [%0], [%1], 16;" :: "r"(dst), "l"(src));
}
#define CP_COMMIT() asm volatile("cp.async.commit_group;" ::: "memory")
#define CP_WAIT0()  asm volatile("cp.async.wait_group 0;" ::: "memory")
#define CP_WAIT1()  asm volatile("cp.async.wait_group 1;" ::: "memory")

// split f32 pair -> packed bf16x2 hi (returned) and lo (out-param)
__device__ __forceinline__ u32 split_pack(float x, float y, u32& lo) {
    float hx = __bfloat162float(__float2bfloat16(x));
    float hy = __bfloat162float(__float2bfloat16(y));
    u32 hi;
    asm("cvt.rn.bf16x2.f32 %0, %1, %2;" : "=r"(hi) : "f"(hy), "f"(hx));
    asm("cvt.rn.bf16x2.f32 %0, %1, %2;" : "=r"(lo) : "f"(y - hy), "f"(x - hx));
    return hi;
}

// ---------------- device scratch ----------------
__device__ __nv_bfloat16 g_Qhi[(size_t)B_ * H_ * S_ * HD_], g_Qlo[(size_t)B_ * H_ * S_ * HD_];
__device__ __nv_bfloat16 g_Khi[(size_t)B_ * H_ * S_ * HD_], g_Klo[(size_t)B_ * H_ * S_ * HD_];
__device__ __nv_bfloat16 g_Vhi[(size_t)B_ * H_ * S_ * HD_], g_Vlo[(size_t)B_ * H_ * S_ * HD_];
__device__ __nv_bfloat16 g_Ahi[(size_t)M_ * D_],   g_Alo[(size_t)M_ * D_];
__device__ __nv_bfloat16 g_Whi[(size_t)NQKV * D_], g_Wlo[(size_t)NQKV * D_];
__device__ __nv_bfloat16 g_Wohi[(size_t)D_ * F_],  g_Wolo[(size_t)D_ * F_];
__device__ __nv_bfloat16 g_AThi[(size_t)M_ * F_],  g_ATlo[(size_t)M_ * F_];

// ---------------------------------------------------------------------------
// Split fp32 -> bf16 (hi, lo)
// ---------------------------------------------------------------------------
__global__ void split_bf16_kernel(const float4* __restrict__ x,
                                  uint2* __restrict__ hi, uint2* __restrict__ lo, int n4)
{
    int i = blockIdx.x * blockDim.x + threadIdx.x;
    if (i >= n4) return;
    float4 v = x[i];
    u32 l0, l1, h0, h1;
    h0 = split_pack(v.x, v.y, l0);
    h1 = split_pack(v.z, v.w, l1);
    hi[i] = make_uint2(h0, h1);
    lo[i] = make_uint2(l0, l1);
}

// ---------------------------------------------------------------------------
// bf16x3 GEMM via mma.sync m16n8k16. Tile 128(M) x 256(N), K chunks of 64.
// 8 warps: warp grid 2(m) x 4(n), warp tile 64x64.
// Stage: Ahi 16K | Alo 16K | Bhi 32K | Blo 32K = 96KB; 2 stages = 192KB.
// MODE 0: QKV + RoPE -> Q/K/V bf16 hi/lo.  MODE 1: out proj -> fp32 out.
// ---------------------------------------------------------------------------
#define NCHUNK 32
#define AT_B 16384
#define BT_B 32768
#define STAGEB (2 * AT_B + 2 * BT_B)      // 96KB
#define MMA_SMEM_BYTES (2 * STAGEB)       // 192KB

__device__ __forceinline__ u32 swz(u32 row, u32 cb) {
    return row * 128u + (cb ^ ((row & 7u) << 4));
}

template <int MODE>
__global__ void __launch_bounds__(256, 1) mma_gemm_kernel(
    const __nv_bfloat16* __restrict__ Ahi, const __nv_bfloat16* __restrict__ Alo,
    const __nv_bfloat16* __restrict__ Bhi, const __nv_bfloat16* __restrict__ Blo,
    const float* __restrict__ cs, const float* __restrict__ sn,
    float* __restrict__ out)
{
    extern __shared__ char dyn_smem[];
    const u32 smb = smem_u32(dyn_smem);

    const int tid = threadIdx.x;
    const int wid = tid >> 5;
    const int lane = tid & 31;
    const int wm = wid >> 2, wn = wid & 3;
    const int m0 = blockIdx.y << 7;
    const int n0 = blockIdx.x << 8;

    // loader: issue one chunk (A 2x1024 units, B 2x2048 units)
    auto load_chunk = [&](int st, int k0) {
        const u32 sb = smb + (u32)st * STAGEB;
#pragma unroll
        for (int rep = 0; rep < 4; rep++) {         // Ahi / Alo
            int lin = rep * 256 + tid;
            int row = lin >> 3, u = lin & 7;
            const size_t go = (size_t)(m0 + row) * 2048 + k0 + u * 8;
            cp_async16(sb + swz(row, u * 16), Ahi + go);
            cp_async16(sb + AT_B + swz(row, u * 16), Alo + go);
        }
#pragma unroll
        for (int rep = 0; rep < 8; rep++) {         // Bhi / Blo (256 rows)
            int lin = rep * 256 + tid;
            int row = lin >> 3, u = lin & 7;
            const size_t go = (size_t)(n0 + row) * 2048 + k0 + u * 8;
            cp_async16(sb + 2 * AT_B + swz(row, u * 16), Bhi + go);
            cp_async16(sb + 2 * AT_B + BT_B + swz(row, u * 16), Blo + go);
        }
    };

    load_chunk(0, 0);
    CP_COMMIT(); CP_WAIT0();
    __syncthreads();

    // fragment addressing
    const u32 aRow = (u32)(wm * 64 + (lane & 15));
    const u32 aSw = (aRow & 7u) << 4;
    const u32 aColSel = (u32)((lane >> 4) << 4);
    u32 aOff[4];
#pragma unroll
    for (int fm = 0; fm < 4; fm++) aOff[fm] = (aRow + fm * 16) * 128u;

    u32 bOff[4], bSw[4];
#pragma unroll
    for (int p = 0; p < 4; p++) {
        u32 brow = (u32)(wn * 64 + p * 16 + ((lane >> 4) << 3) + (lane & 7));
        bOff[p] = brow * 128u;
        bSw[p] = (brow & 7u) << 4;
    }
    const u32 bColSel = (u32)(((lane >> 3) & 1) << 4);

    float acc[4][8][4];
#pragma unroll
    for (int i = 0; i < 4; i++)
#pragma unroll
        for (int j = 0; j < 8; j++)
#pragma unroll
            for (int q = 0; q < 4; q++) acc[i][j][q] = 0.f;

    for (int c = 0; c < NCHUNK; c++) {
        const u32 stage = smb + (u32)(c & 1) * STAGEB;
        if (c + 1 < NCHUNK) {
            load_chunk((c + 1) & 1, (c + 1) * 64);
            CP_COMMIT();
        }
#pragma unroll
        for (int ks = 0; ks < 4; ks++) {
            const u32 cbA = (u32)(ks * 32) + aColSel;
            const u32 cbB = (u32)(ks * 32) + bColSel;
            u32 ah[4][4], al[4][4];
#pragma unroll
            for (int fm = 0; fm < 4; fm++) {
                ldsm4(ah[fm], stage + aOff[fm] + (cbA ^ aSw));
                ldsm4(al[fm], stage + AT_B + aOff[fm] + (cbA ^ aSw));
            }
#pragma unroll
            for (int p = 0; p < 4; p++) {
                u32 bh[4], bl[4];
                ldsm4(bh, stage + 2 * AT_B + bOff[p] + (cbB ^ bSw[p]));
                ldsm4(bl, stage + 2 * AT_B + BT_B + bOff[p] + (cbB ^ bSw[p]));
#pragma unroll
                for (int fm = 0; fm < 4; fm++)
#pragma unroll
                    for (int q = 0; q < 2; q++) {
                        float* d = acc[fm][p * 2 + q];
                        mma16816(d, ah[fm], &bh[q * 2]);
                        mma16816(d, ah[fm], &bl[q * 2]);
                        mma16816(d, al[fm], &bh[q * 2]);
                    }
            }
        }
        CP_WAIT0();
        __syncthreads();
    }

    // epilogue: accum -> smem fp32 (pitch 260), then scatter
    float* S = (float*)dyn_smem;
    const int er = lane >> 2, ec = (lane & 3) << 1;
#pragma unroll
    for (int fm = 0; fm < 4; fm++)
#pragma unroll
        for (int fn = 0; fn < 8; fn++) {
            const int r0 = wm * 64 + fm * 16 + er;
            const int c0 = wn * 64 + fn * 8 + ec;
            S[r0 * 260 + c0] = acc[fm][fn][0];
            S[r0 * 260 + c0 + 1] = acc[fm][fn][1];
            S[(r0 + 8) * 260 + c0] = acc[fm][fn][2];
            S[(r0 + 8) * 260 + c0 + 1] = acc[fm][fn][3];
        }
    __syncthreads();

    const int r = tid >> 1, t2 = tid & 1;
    const int m = m0 + r;
#pragma unroll
    for (int g = 0; g < 2; g++) {
        const int gc = g * 128;                      // column group base in tile
        if (MODE == 0) {
            const int nabs = n0 + gc;
            const int h = nabs / 384;
            const int sub = (nabs % 384) >> 7;       // 0=q,1=k,2=v
            const int b = m >> 11, s = m & 2047;
            const size_t doff = ((size_t)(b * H_ + h) * S_ + s) * HD_;
            if (sub == 2) {
                const int cb = t2 * 64;
#pragma unroll
                for (int gg = 0; gg < 8; gg++) {
                    u32 hw[4], lw[4];
#pragma unroll
                    for (int p = 0; p < 4; p++) {
                        float x = S[r * 260 + gc + cb + gg * 8 + p * 2];
                        float y = S[r * 260 + gc + cb + gg * 8 + p * 2 + 1];
                        hw[p] = split_pack(x, y, lw[p]);
                    }
                    *(uint4*)(g_Vhi + doff + cb + gg * 8) = make_uint4(hw[0], hw[1], hw[2], hw[3]);
                    *(uint4*)(g_Vlo + doff + cb + gg * 8) = make_uint4(lw[0], lw[1], lw[2], lw[3]);
                }
            } else {
                const float scl = (sub == 0) ? 0.08838834764831845f : 1.0f;
                __nv_bfloat16* dhi = (sub == 0) ? g_Qhi : g_Khi;
                __nv_bfloat16* dlo = (sub == 0) ? g_Qlo : g_Klo;
                const float* crow = cs + (size_t)s * HD_;
                const float* srow = sn + (size_t)s * HD_;
#pragma unroll
                for (int gg = 0; gg < 4; gg++) {
                    const int cA = t2 * 32 + gg * 8;
                    const int cB = cA + 64;
                    u32 hA[4], lA[4], hB[4], lB[4];
#pragma unroll
                    for (int p = 0; p < 4; p++) {
                        const int c0 = cA + p * 2, c1 = cA + p * 2 + 1;
                        float xa0 = S[r * 260 + gc + c0], xa1 = S[r * 260 + gc + c1];
                        float xb0 = S[r * 260 + gc + c0 + 64], xb1 = S[r * 260 + gc + c1 + 64];
                        float oa0 = (xa0 * crow[c0] - xb0 * srow[c0]) * scl;
                        float oa1 = (xa1 * crow[c1] - xb1 * srow[c1]) * scl;
                        float ob0 = (xb0 * crow[c0 + 64] + xa0 * srow[c0 + 64]) * scl;
                        float ob1 = (xb1 * crow[c1 + 64] + xa1 * srow[c1 + 64]) * scl;
                        hA[p] = split_pack(oa0, oa1, lA[p]);
                        hB[p] = split_pack(ob0, ob1, lB[p]);
                    }
                    *(uint4*)(dhi + doff + cA) = make_uint4(hA[0], hA[1], hA[2], hA[3]);
                    *(uint4*)(dlo + doff + cA) = make_uint4(lA[0], lA[1], lA[2], lA[3]);
                    *(uint4*)(dhi + doff + cB) = make_uint4(hB[0], hB[1], hB[2], hB[3]);
                    *(uint4*)(dlo + doff + cB) = make_uint4(lB[0], lB[1], lB[2], lB[3]);
                }
            }
        } else {
            float* dst = out + (size_t)m * D_ + n0 + gc;
            const int cbase = t2 * 64;
#pragma unroll
            for (int q4 = 0; q4 < 16; q4++) {
                float4 w = *(const float4*)(S + r * 260 + gc + cbase + q4 * 4);
                *(float4*)(dst + cbase + q4 * 4) = w;
            }
        }
    }
}

// ---------------------------------------------------------------------------
// Tensor-core causal flash attention (unchanged from R5).
// ---------------------------------------------------------------------------
#define ATT_SMEM_BYTES (192 * 1024)
#define AQLO 32768
#define ASTG 65536
#define AKLO 16384
#define AVHI 32768
#define AVLO 49152

__device__ __forceinline__ u32 aswz(u32 row, u32 cb) {
    return row * 256u + (cb ^ ((row & 7u) << 4));
}

__global__ void __launch_bounds__(256, 1) attn_mma_kernel()
{
    extern __shared__ char dyn_smem[];
    const u32 smb = smem_u32(dyn_smem);
    const int tid = threadIdx.x, wid = tid >> 5, lane = tid & 31;
    const int qt = blockIdx.x, h = blockIdx.y, b = blockIdx.z;
    const int qg0 = qt << 7;
    const size_t bh = (size_t)(b * H_ + h) * S_;

    {
        const __nv_bfloat16* qh = g_Qhi + (bh + qg0) * HD_;
        const __nv_bfloat16* ql = g_Qlo + (bh + qg0) * HD_;
#pragma unroll
        for (int rep = 0; rep < 8; rep++) {
            int lin = rep * 256 + tid;
            int row = lin >> 4, u = lin & 15;
            u32 so = aswz(row, u * 16);
            cp_async16(smb + so, qh + (size_t)row * HD_ + u * 8);
            cp_async16(smb + AQLO + so, ql + (size_t)row * HD_ + u * 8);
        }
        CP_COMMIT();
    }

    const __nv_bfloat16* khg = g_Khi + bh * HD_;
    const __nv_bfloat16* klg = g_Klo + bh * HD_;
    const __nv_bfloat16* vhg = g_Vhi + bh * HD_;
    const __nv_bfloat16* vlg = g_Vlo + bh * HD_;

    auto load_stage = [&](int st, int kg0) {
        const u32 dst = smb + ASTG + (u32)st * ASTG;
        const __nv_bfloat16* srcs[4] = {khg + (size_t)kg0 * HD_, klg + (size_t)kg0 * HD_,
                                        vhg + (size_t)kg0 * HD_, vlg + (size_t)kg0 * HD_};
#pragma unroll
        for (int op = 0; op < 4; op++) {
#pragma unroll
            for (int rep = 0; rep < 4; rep++) {
                int lin = rep * 256 + tid;
                int row = lin >> 4, u = lin & 15;
                cp_async16(dst + op * 16384 + aswz(row, u * 16),
                           srcs[op] + (size_t)row * HD_ + u * 8);
            }
        }
    };

    const int nkt = 2 * qt + 2;
    load_stage(0, 0);
    CP_COMMIT();

    const u32 aRow = (u32)(wid * 16 + (lane & 15));
    const u32 aSw = (aRow & 7u) << 4;
    const u32 aCol = (u32)((lane >> 4) << 4);
    const u32 aBase = aRow * 256u;
    const u32 kRow = (u32)(((lane >> 4) << 3) + (lane & 7));
    const u32 kSw = (u32)((lane & 7) << 4);
    const u32 kColT = (u32)(((lane >> 3) & 1) << 4);
    const u32 vRow = (u32)(lane & 15);
    const u32 vColT = (u32)((lane >> 4) << 4);

    u32 qhf[8][4], qlf[8][4];
    float o[16][4];
#pragma unroll
    for (int f = 0; f < 16; f++)
#pragma unroll
        for (int q = 0; q < 4; q++) o[f][q] = 0.f;
    float m0r = -1e30f, m1r = -1e30f, l0 = 0.f, l1 = 0.f;

    for (int kt = 0; kt < nkt; kt++) {
        if (kt + 1 < nkt) {
            load_stage((kt + 1) & 1, (kt + 1) * 64);
            CP_COMMIT();
            CP_WAIT1();
        } else {
            CP_WAIT0();
        }
        __syncthreads();
        if (kt == 0) {
#pragma unroll
            for (int ks = 0; ks < 8; ks++) {
                u32 qa = smb + aBase + (((u32)(ks * 32) + aCol) ^ aSw);
                ldsm4(qhf[ks], qa);
                ldsm4(qlf[ks], qa + AQLO);
            }
        }
        const int kg0 = kt * 64;
        const bool skip = kg0 > qg0 + wid * 16 + 15;
        if (!skip) {
            const u32 stg = smb + ASTG + (u32)(kt & 1) * ASTG;
            float s[8][4];
#pragma unroll
            for (int f = 0; f < 8; f++)
#pragma unroll
                for (int q = 0; q < 4; q++) s[f][q] = 0.f;

#pragma unroll
            for (int ks = 0; ks < 8; ks++) {
#pragma unroll
                for (int p = 0; p < 4; p++) {
                    u32 addr = stg + (u32)(p * 16 + kRow) * 256u + (((u32)(ks * 32) + kColT) ^ kSw);
                    u32 kh4[4], kl4[4];
                    ldsm4(kh4, addr);
                    ldsm4(kl4, addr + AKLO);
                    mma16816(s[2 * p], qhf[ks], &kh4[0]);
                    mma16816(s[2 * p], qhf[ks], &kl4[0]);
                    mma16816(s[2 * p], qlf[ks], &kh4[0]);
                    mma16816(s[2 * p + 1], qhf[ks], &kh4[2]);
                    mma16816(s[2 * p + 1], qhf[ks], &kl4[2]);
                    mma16816(s[2 * p + 1], qlf[ks], &kh4[2]);
                }
            }

            const int row0 = qg0 + wid * 16 + (lane >> 2);
            if (kg0 + 63 > qg0 + wid * 16) {
#pragma unroll
                for (int f = 0; f < 8; f++) {
                    const int col = kg0 + f * 8 + (lane & 3) * 2;
                    if (col > row0)     s[f][0] = -1e30f;
                    if (col + 1 > row0) s[f][1] = -1e30f;
                    if (col > row0 + 8)     s[f][2] = -1e30f;
                    if (col + 1 > row0 + 8) s[f][3] = -1e30f;
                }
            }

            float mx0 = -1e30f, mx1 = -1e30f;
#pragma unroll
            for (int f = 0; f < 8; f++) {
                mx0 = fmaxf(mx0, fmaxf(s[f][0], s[f][1]));
                mx1 = fmaxf(mx1, fmaxf(s[f][2], s[f][3]));
            }
            mx0 = fmaxf(mx0, __shfl_xor_sync(0xffffffffu, mx0, 1));
            mx0 = fmaxf(mx0, __shfl_xor_sync(0xffffffffu, mx0, 2));
            mx1 = fmaxf(mx1, __shfl_xor_sync(0xffffffffu, mx1, 1));
            mx1 = fmaxf(mx1, __shfl_xor_sync(0xffffffffu, mx1, 2));
            const float mn0 = fmaxf(m0r, mx0), mn1 = fmaxf(m1r, mx1);
            const float al0 = __expf(m0r - mn0), al1 = __expf(m1r - mn1);
            m0r = mn0; m1r = mn1;
            float s0 = 0.f, s1 = 0.f;
#pragma unroll
            for (int f = 0; f < 8; f++) {
                s[f][0] = __expf(s[f][0] - mn0);
                s[f][1] = __expf(s[f][1] - mn0);
                s[f][2] = __expf(s[f][2] - mn1);
                s[f][3] = __expf(s[f][3] - mn1);
                s0 += s[f][0] + s[f][1];
                s1 += s[f][2] + s[f][3];
            }
            s0 += __shfl_xor_sync(0xffffffffu, s0, 1);
            s0 += __shfl_xor_sync(0xffffffffu, s0, 2);
            s1 += __shfl_xor_sync(0xffffffffu, s1, 1);
            s1 += __shfl_xor_sync(0xffffffffu, s1, 2);
            l0 = l0 * al0 + s0;
            l1 = l1 * al1 + s1;
#pragma unroll
            for (int f = 0; f < 16; f++) {
                o[f][0] *= al0; o[f][1] *= al0;
                o[f][2] *= al1; o[f][3] *= al1;
            }

            u32 ph[4][4], pl[4][4];
#pragma unroll
            for (int j = 0; j < 4; j++) {
                ph[j][0] = split_pack(s[2 * j][0], s[2 * j][1], pl[j][0]);
                ph[j][1] = split_pack(s[2 * j][2], s[2 * j][3], pl[j][1]);
                ph[j][2] = split_pack(s[2 * j + 1][0], s[2 * j + 1][1], pl[j][2]);
                ph[j][3] = split_pack(s[2 * j + 1][2], s[2 * j + 1][3], pl[j][3]);
            }

#pragma unroll
            for (int j = 0; j < 4; j++) {
#pragma unroll
                for (int ep = 0; ep < 8; ep++) {
                    u32 va = stg + AVHI + (u32)(j * 16 + vRow) * 256u + (((u32)(ep * 32) + vColT) ^ kSw);
                    u32 vh4[4], vl4[4];
                    ldsm4t(vh4, va);
                    ldsm4t(vl4, va + 16384);
                    mma16816(o[2 * ep], ph[j], &vh4[0]);
                    mma16816(o[2 * ep], ph[j], &vl4[0]);
                    mma16816(o[2 * ep], pl[j], &vh4[0]);
                    mma16816(o[2 * ep + 1], ph[j], &vh4[2]);
                    mma16816(o[2 * ep + 1], ph[j], &vl4[2]);
                    mma16816(o[2 * ep + 1], pl[j], &vh4[2]);
                }
            }
        }
        __syncthreads();
    }

    const float inv0 = 1.0f / l0, inv1 = 1.0f / l1;
    const int srow0 = qg0 + wid * 16 + (lane >> 2);
    const size_t ro0 = ((size_t)b * S_ + srow0) * F_ + h * HD_;
    const size_t ro1 = ro0 + (size_t)8 * F_;
#pragma unroll
    for (int f = 0; f < 16; f++) {
        const int e = f * 8 + (lane & 3) * 2;
        u32 lo0, lo1;
        u32 hi0 = split_pack(o[f][0] * inv0, o[f][1] * inv0, lo0);
        u32 hi1 = split_pack(o[f][2] * inv1, o[f][3] * inv1, lo1);
        *(u32*)(g_AThi + ro0 + e) = hi0;
        *(u32*)(g_ATlo + ro0 + e) = lo0;
        *(u32*)(g_AThi + ro1 + e) = hi1;
        *(u32*)(g_ATlo + ro1 + e) = lo1;
    }
}

// ---------------------------------------------------------------------------
extern "C" void kernel_launch(void* const* d_in, const int* in_sizes, int n_in,
                              void* d_out, int out_size)
{
    const float* hs = (const float*)d_in[0];
    const float* cs = (const float*)d_in[1];
    const float* sn = (const float*)d_in[2];
    const float* wq = (const float*)d_in[3];
    const float* wo = (const float*)d_in[4];
    float* out = (float*)d_out;

    cudaFuncSetAttribute(mma_gemm_kernel<0>, cudaFuncAttributeMaxDynamicSharedMemorySize, MMA_SMEM_BYTES);
    cudaFuncSetAttribute(mma_gemm_kernel<1>, cudaFuncAttributeMaxDynamicSharedMemorySize, MMA_SMEM_BYTES);
    cudaFuncSetAttribute(attn_mma_kernel, cudaFuncAttributeMaxDynamicSharedMemorySize, ATT_SMEM_BYTES);

    __nv_bfloat16 *ahi, *alo, *whi, *wlo, *wohi, *wolo, *athi, *atlo;
    cudaGetSymbolAddress((void**)&ahi, g_Ahi);   cudaGetSymbolAddress((void**)&alo, g_Alo);
    cudaGetSymbolAddress((void**)&whi, g_Whi);   cudaGetSymbolAddress((void**)&wlo, g_Wlo);
    cudaGetSymbolAddress((void**)&wohi, g_Wohi); cudaGetSymbolAddress((void**)&wolo, g_Wolo);
    cudaGetSymbolAddress((void**)&athi, g_AThi); cudaGetSymbolAddress((void**)&atlo, g_ATlo);

    {
        int n4 = (M_ * D_) / 4;
        split_bf16_kernel<<<(n4 + 255) / 256, 256>>>((const float4*)hs, (uint2*)ahi, (uint2*)alo, n4);
        n4 = (NQKV * D_) / 4;
        split_bf16_kernel<<<(n4 + 255) / 256, 256>>>((const float4*)wq, (uint2*)whi, (uint2*)wlo, n4);
        n4 = (D_ * F_) / 4;
        split_bf16_kernel<<<(n4 + 255) / 256, 256>>>((const float4*)wo, (uint2*)wohi, (uint2*)wolo, n4);
    }

    // QKV projection: N tiles of 256 (NQKV/256 = 24)
    mma_gemm_kernel<0><<<dim3(NQKV / 256, M_ / 128), 256, MMA_SMEM_BYTES>>>(
        ahi, alo, whi, wlo, cs, sn, nullptr);

    attn_mma_kernel<<<dim3(S_ / 128, H_, B_), 256, ATT_SMEM_BYTES>>>();

    // Output projection: D/256 = 8
    mma_gemm_kernel<1><<<dim3(D_ / 256, M_ / 128), 256, MMA_SMEM_BYTES>>>(
        athi, atlo, wohi, wolo, nullptr, nullptr, out);
}

// round 7
// speedup vs baseline: 1.0106x; 1.0106x over previous
#include <cuda_runtime.h>
#include <cuda_bf16.h>
#include <cstdint>
#include <math.h>

// Problem constants
#define B_   2
#define S_   2048
#define D_   2048
#define H_   16
#define HD_  128
#define M_   (B_ * S_)     // 4096
#define F_   (H_ * HD_)    // 2048
#define NQKV (3 * F_)      // 6144

typedef unsigned long long u64;
typedef unsigned int u32;

__device__ __forceinline__ u32 smem_u32(const void* p) {
    u32 a; asm("{ .reg .u64 t; cvta.to.shared.u64 t, %1; cvt.u32.u64 %0, t; }" : "=r"(a) : "l"(p));
    return a;
}

// ---- mma.sync / ldmatrix / cp.async ----
__device__ __forceinline__ void ldsm4(u32* r, u32 addr) {
    asm volatile("ldmatrix.sync.aligned.m8n8.x4.shared.b16 {%0,%1,%2,%3}, [%4];"
        : "=r"(r[0]), "=r"(r[1]), "=r"(r[2]), "=r"(r[3]) : "r"(addr));
}
__device__ __forceinline__ void ldsm4t(u32* r, u32 addr) {
    asm volatile("ldmatrix.sync.aligned.m8n8.x4.trans.shared.b16 {%0,%1,%2,%3}, [%4];"
        : "=r"(r[0]), "=r"(r[1]), "=r"(r[2]), "=r"(r[3]) : "r"(addr));
}
__device__ __forceinline__ void mma16816(float* d, const u32* a, const u32* b) {
    asm volatile("mma.sync.aligned.m16n8k16.row.col.f32.bf16.bf16.f32 "
        "{%0,%1,%2,%3}, {%4,%5,%6,%7}, {%8,%9}, {%0,%1,%2,%3};"
        : "+f"(d[0]), "+f"(d[1]), "+f"(d[2]), "+f"(d[3])
        : "r"(a[0]), "r"(a[1]), "r"(a[2]), "r"(a[3]), "r"(b[0]), "r"(b[1]));
}
__device__ __forceinline__ void cp_async16(u32 dst, const void* src) {
    asm volatile("cp.async.cg.shared.global [%0], [%1], 16;" :: "r"(dst), "l"(src));
}
#define CP_COMMIT() asm volatile("cp.async.commit_group;" ::: "memory")
#define CP_WAIT0()  asm volatile("cp.async.wait_group 0;" ::: "memory")
#define CP_WAIT1()  asm volatile("cp.async.wait_group 1;" ::: "memory")

// split f32 pair -> packed bf16x2 hi (returned) and lo (out-param)
__device__ __forceinline__ u32 split_pack(float x, float y, u32& lo) {
    float hx = __bfloat162float(__float2bfloat16(x));
    float hy = __bfloat162float(__float2bfloat16(y));
    u32 hi;
    asm("cvt.rn.bf16x2.f32 %0, %1, %2;" : "=r"(hi) : "f"(hy), "f"(hx));
    asm("cvt.rn.bf16x2.f32 %0, %1, %2;" : "=r"(lo) : "f"(y - hy), "f"(x - hx));
    return hi;
}

// ---------------- device scratch ----------------
__device__ __nv_bfloat16 g_Qhi[(size_t)B_ * H_ * S_ * HD_], g_Qlo[(size_t)B_ * H_ * S_ * HD_];
__device__ __nv_bfloat16 g_Khi[(size_t)B_ * H_ * S_ * HD_], g_Klo[(size_t)B_ * H_ * S_ * HD_];
__device__ __nv_bfloat16 g_Vhi[(size_t)B_ * H_ * S_ * HD_], g_Vlo[(size_t)B_ * H_ * S_ * HD_];
__device__ __nv_bfloat16 g_Ahi[(size_t)M_ * D_],   g_Alo[(size_t)M_ * D_];
__device__ __nv_bfloat16 g_Whi[(size_t)NQKV * D_], g_Wlo[(size_t)NQKV * D_];
__device__ __nv_bfloat16 g_Wohi[(size_t)D_ * F_],  g_Wolo[(size_t)D_ * F_];
__device__ __nv_bfloat16 g_AThi[(size_t)M_ * F_],  g_ATlo[(size_t)M_ * F_];

// ---------------------------------------------------------------------------
// Split fp32 -> bf16 (hi, lo)
// ---------------------------------------------------------------------------
__global__ void split_bf16_kernel(const float4* __restrict__ x,
                                  uint2* __restrict__ hi, uint2* __restrict__ lo, int n4)
{
    int i = blockIdx.x * blockDim.x + threadIdx.x;
    if (i >= n4) return;
    float4 v = x[i];
    u32 l0, l1, h0, h1;
    h0 = split_pack(v.x, v.y, l0);
    h1 = split_pack(v.z, v.w, l1);
    hi[i] = make_uint2(h0, h1);
    lo[i] = make_uint2(l0, l1);
}

// ---------------------------------------------------------------------------
// bf16x3 GEMM via mma.sync m16n8k16. CTA tile 128(M) x 256(N), K chunks of 64.
// 512 threads / 16 warps: warp grid 4(m) x 4(n), warp tile 32x64.
// acc = 2x8x4 = 64 regs/thread -> no spills, 4 warps/SMSP.
// Stage: Ahi 16K | Alo 16K | Bhi 32K | Blo 32K = 96KB; 2 stages = 192KB.
// MODE 0: QKV + RoPE -> Q/K/V bf16 hi/lo.  MODE 1: out proj -> fp32 out.
// ---------------------------------------------------------------------------
#define NCHUNK 32
#define AT_B 16384
#define BT_B 32768
#define STAGEB (2 * AT_B + 2 * BT_B)      // 96KB
#define MMA_SMEM_BYTES (2 * STAGEB)       // 192KB

__device__ __forceinline__ u32 swz(u32 row, u32 cb) {
    return row * 128u + (cb ^ ((row & 7u) << 4));
}

template <int MODE>
__global__ void __launch_bounds__(512, 1) mma_gemm_kernel(
    const __nv_bfloat16* __restrict__ Ahi, const __nv_bfloat16* __restrict__ Alo,
    const __nv_bfloat16* __restrict__ Bhi, const __nv_bfloat16* __restrict__ Blo,
    const float* __restrict__ cs, const float* __restrict__ sn,
    float* __restrict__ out)
{
    extern __shared__ char dyn_smem[];
    const u32 smb = smem_u32(dyn_smem);

    const int tid = threadIdx.x;
    const int wid = tid >> 5;
    const int lane = tid & 31;
    const int wm = wid >> 2, wn = wid & 3;     // 4x4 warp grid
    const int m0 = blockIdx.y << 7;
    const int n0 = blockIdx.x << 8;

    // loader: one chunk = A hi/lo (2 x 1024 16B units) + B hi/lo (2 x 2048 units)
    auto load_chunk = [&](int st, int k0) {
        const u32 sb = smb + (u32)st * STAGEB;
#pragma unroll
        for (int rep = 0; rep < 2; rep++) {         // A hi/lo: 1024 units, 512 thr
            int lin = rep * 512 + tid;
            int row = lin >> 3, u = lin & 7;
            const size_t go = (size_t)(m0 + row) * 2048 + k0 + u * 8;
            cp_async16(sb + swz(row, u * 16), Ahi + go);
            cp_async16(sb + AT_B + swz(row, u * 16), Alo + go);
        }
#pragma unroll
        for (int rep = 0; rep < 4; rep++) {         // B hi/lo: 2048 units
            int lin = rep * 512 + tid;
            int row = lin >> 3, u = lin & 7;
            const size_t go = (size_t)(n0 + row) * 2048 + k0 + u * 8;
            cp_async16(sb + 2 * AT_B + swz(row, u * 16), Bhi + go);
            cp_async16(sb + 2 * AT_B + BT_B + swz(row, u * 16), Blo + go);
        }
    };

    load_chunk(0, 0);
    CP_COMMIT(); CP_WAIT0();
    __syncthreads();

    // fragment addressing
    const u32 aRow = (u32)(wm * 32 + (lane & 15));
    const u32 aSw = (aRow & 7u) << 4;
    const u32 aColSel = (u32)((lane >> 4) << 4);
    u32 aOff[2];
#pragma unroll
    for (int fm = 0; fm < 2; fm++) aOff[fm] = (aRow + fm * 16) * 128u;

    u32 bOff[4], bSw[4];
#pragma unroll
    for (int p = 0; p < 4; p++) {
        u32 brow = (u32)(wn * 64 + p * 16 + ((lane >> 4) << 3) + (lane & 7));
        bOff[p] = brow * 128u;
        bSw[p] = (brow & 7u) << 4;
    }
    const u32 bColSel = (u32)(((lane >> 3) & 1) << 4);

    float acc[2][8][4];
#pragma unroll
    for (int i = 0; i < 2; i++)
#pragma unroll
        for (int j = 0; j < 8; j++)
#pragma unroll
            for (int q = 0; q < 4; q++) acc[i][j][q] = 0.f;

    for (int c = 0; c < NCHUNK; c++) {
        const u32 stage = smb + (u32)(c & 1) * STAGEB;
        if (c + 1 < NCHUNK) {
            load_chunk((c + 1) & 1, (c + 1) * 64);
            CP_COMMIT();
        }
#pragma unroll
        for (int ks = 0; ks < 4; ks++) {
            const u32 cbA = (u32)(ks * 32) + aColSel;
            const u32 cbB = (u32)(ks * 32) + bColSel;
            u32 ah[2][4], al[2][4];
#pragma unroll
            for (int fm = 0; fm < 2; fm++) {
                ldsm4(ah[fm], stage + aOff[fm] + (cbA ^ aSw));
                ldsm4(al[fm], stage + AT_B + aOff[fm] + (cbA ^ aSw));
            }
#pragma unroll
            for (int p = 0; p < 4; p++) {
                u32 bh[4], bl[4];
                ldsm4(bh, stage + 2 * AT_B + bOff[p] + (cbB ^ bSw[p]));
                ldsm4(bl, stage + 2 * AT_B + BT_B + bOff[p] + (cbB ^ bSw[p]));
#pragma unroll
                for (int fm = 0; fm < 2; fm++)
#pragma unroll
                    for (int q = 0; q < 2; q++) {
                        float* d = acc[fm][p * 2 + q];
                        mma16816(d, ah[fm], &bh[q * 2]);
                        mma16816(d, ah[fm], &bl[q * 2]);
                        mma16816(d, al[fm], &bh[q * 2]);
                    }
            }
        }
        CP_WAIT0();
        __syncthreads();
    }

    // epilogue: accum -> smem fp32 (pitch 260), then scatter
    float* S = (float*)dyn_smem;
    const int er = lane >> 2, ec = (lane & 3) << 1;
#pragma unroll
    for (int fm = 0; fm < 2; fm++)
#pragma unroll
        for (int fn = 0; fn < 8; fn++) {
            const int r0 = wm * 32 + fm * 16 + er;
            const int c0 = wn * 64 + fn * 8 + ec;
            S[r0 * 260 + c0] = acc[fm][fn][0];
            S[r0 * 260 + c0 + 1] = acc[fm][fn][1];
            S[(r0 + 8) * 260 + c0] = acc[fm][fn][2];
            S[(r0 + 8) * 260 + c0 + 1] = acc[fm][fn][3];
        }
    __syncthreads();

    // 512 threads: r = tid>>2 (row), q = tid&3 (64-col quarter)
    const int r = tid >> 2, qq = tid & 3;
    const int g = qq >> 1, t2 = qq & 1;
    const int gc = g * 128;
    const int m = m0 + r;
    if (MODE == 0) {
        const int nabs = n0 + gc;
        const int h = nabs / 384;
        const int sub = (nabs % 384) >> 7;       // 0=q,1=k,2=v
        const int b = m >> 11, s = m & 2047;
        const size_t doff = ((size_t)(b * H_ + h) * S_ + s) * HD_;
        if (sub == 2) {
            const int cb = t2 * 64;
#pragma unroll
            for (int gg = 0; gg < 8; gg++) {
                u32 hw[4], lw[4];
#pragma unroll
                for (int p = 0; p < 4; p++) {
                    float x = S[r * 260 + gc + cb + gg * 8 + p * 2];
                    float y = S[r * 260 + gc + cb + gg * 8 + p * 2 + 1];
                    hw[p] = split_pack(x, y, lw[p]);
                }
                *(uint4*)(g_Vhi + doff + cb + gg * 8) = make_uint4(hw[0], hw[1], hw[2], hw[3]);
                *(uint4*)(g_Vlo + doff + cb + gg * 8) = make_uint4(lw[0], lw[1], lw[2], lw[3]);
            }
        } else {
            const float scl = (sub == 0) ? 0.08838834764831845f : 1.0f;
            __nv_bfloat16* dhi = (sub == 0) ? g_Qhi : g_Khi;
            __nv_bfloat16* dlo = (sub == 0) ? g_Qlo : g_Klo;
            const float* crow = cs + (size_t)s * HD_;
            const float* srow = sn + (size_t)s * HD_;
#pragma unroll
            for (int gg = 0; gg < 4; gg++) {
                const int cA = t2 * 32 + gg * 8;
                const int cB = cA + 64;
                u32 hA[4], lA[4], hB[4], lB[4];
#pragma unroll
                for (int p = 0; p < 4; p++) {
                    const int c0 = cA + p * 2, c1 = cA + p * 2 + 1;
                    float xa0 = S[r * 260 + gc + c0], xa1 = S[r * 260 + gc + c1];
                    float xb0 = S[r * 260 + gc + c0 + 64], xb1 = S[r * 260 + gc + c1 + 64];
                    float oa0 = (xa0 * crow[c0] - xb0 * srow[c0]) * scl;
                    float oa1 = (xa1 * crow[c1] - xb1 * srow[c1]) * scl;
                    float ob0 = (xb0 * crow[c0 + 64] + xa0 * srow[c0 + 64]) * scl;
                    float ob1 = (xb1 * crow[c1 + 64] + xa1 * srow[c1 + 64]) * scl;
                    hA[p] = split_pack(oa0, oa1, lA[p]);
                    hB[p] = split_pack(ob0, ob1, lB[p]);
                }
                *(uint4*)(dhi + doff + cA) = make_uint4(hA[0], hA[1], hA[2], hA[3]);
                *(uint4*)(dlo + doff + cA) = make_uint4(lA[0], lA[1], lA[2], lA[3]);
                *(uint4*)(dhi + doff + cB) = make_uint4(hB[0], hB[1], hB[2], hB[3]);
                *(uint4*)(dlo + doff + cB) = make_uint4(lB[0], lB[1], lB[2], lB[3]);
            }
        }
    } else {
        float* dst = out + (size_t)m * D_ + n0 + gc;
        const int cbase = t2 * 64;
#pragma unroll
        for (int q4 = 0; q4 < 16; q4++) {
            float4 w = *(const float4*)(S + r * 260 + gc + cbase + q4 * 4);
            *(float4*)(dst + cbase + q4 * 4) = w;
        }
    }
}

// ---------------------------------------------------------------------------
// Tensor-core causal flash attention (unchanged from R5 best).
// ---------------------------------------------------------------------------
#define ATT_SMEM_BYTES (192 * 1024)
#define AQLO 32768
#define ASTG 65536
#define AKLO 16384
#define AVHI 32768
#define AVLO 49152

__device__ __forceinline__ u32 aswz(u32 row, u32 cb) {
    return row * 256u + (cb ^ ((row & 7u) << 4));
}

__global__ void __launch_bounds__(256, 1) attn_mma_kernel()
{
    extern __shared__ char dyn_smem[];
    const u32 smb = smem_u32(dyn_smem);
    const int tid = threadIdx.x, wid = tid >> 5, lane = tid & 31;
    const int qt = blockIdx.x, h = blockIdx.y, b = blockIdx.z;
    const int qg0 = qt << 7;
    const size_t bh = (size_t)(b * H_ + h) * S_;

    {
        const __nv_bfloat16* qh = g_Qhi + (bh + qg0) * HD_;
        const __nv_bfloat16* ql = g_Qlo + (bh + qg0) * HD_;
#pragma unroll
        for (int rep = 0; rep < 8; rep++) {
            int lin = rep * 256 + tid;
            int row = lin >> 4, u = lin & 15;
            u32 so = aswz(row, u * 16);
            cp_async16(smb + so, qh + (size_t)row * HD_ + u * 8);
            cp_async16(smb + AQLO + so, ql + (size_t)row * HD_ + u * 8);
        }
        CP_COMMIT();
    }

    const __nv_bfloat16* khg = g_Khi + bh * HD_;
    const __nv_bfloat16* klg = g_Klo + bh * HD_;
    const __nv_bfloat16* vhg = g_Vhi + bh * HD_;
    const __nv_bfloat16* vlg = g_Vlo + bh * HD_;

    auto load_stage = [&](int st, int kg0) {
        const u32 dst = smb + ASTG + (u32)st * ASTG;
        const __nv_bfloat16* srcs[4] = {khg + (size_t)kg0 * HD_, klg + (size_t)kg0 * HD_,
                                        vhg + (size_t)kg0 * HD_, vlg + (size_t)kg0 * HD_};
#pragma unroll
        for (int op = 0; op < 4; op++) {
#pragma unroll
            for (int rep = 0; rep < 4; rep++) {
                int lin = rep * 256 + tid;
                int row = lin >> 4, u = lin & 15;
                cp_async16(dst + op * 16384 + aswz(row, u * 16),
                           srcs[op] + (size_t)row * HD_ + u * 8);
            }
        }
    };

    const int nkt = 2 * qt + 2;
    load_stage(0, 0);
    CP_COMMIT();

    const u32 aRow = (u32)(wid * 16 + (lane & 15));
    const u32 aSw = (aRow & 7u) << 4;
    const u32 aCol = (u32)((lane >> 4) << 4);
    const u32 aBase = aRow * 256u;
    const u32 kRow = (u32)(((lane >> 4) << 3) + (lane & 7));
    const u32 kSw = (u32)((lane & 7) << 4);
    const u32 kColT = (u32)(((lane >> 3) & 1) << 4);
    const u32 vRow = (u32)(lane & 15);
    const u32 vColT = (u32)((lane >> 4) << 4);

    u32 qhf[8][4], qlf[8][4];
    float o[16][4];
#pragma unroll
    for (int f = 0; f < 16; f++)
#pragma unroll
        for (int q = 0; q < 4; q++) o[f][q] = 0.f;
    float m0r = -1e30f, m1r = -1e30f, l0 = 0.f, l1 = 0.f;

    for (int kt = 0; kt < nkt; kt++) {
        if (kt + 1 < nkt) {
            load_stage((kt + 1) & 1, (kt + 1) * 64);
            CP_COMMIT();
            CP_WAIT1();
        } else {
            CP_WAIT0();
        }
        __syncthreads();
        if (kt == 0) {
#pragma unroll
            for (int ks = 0; ks < 8; ks++) {
                u32 qa = smb + aBase + (((u32)(ks * 32) + aCol) ^ aSw);
                ldsm4(qhf[ks], qa);
                ldsm4(qlf[ks], qa + AQLO);
            }
        }
        const int kg0 = kt * 64;
        const bool skip = kg0 > qg0 + wid * 16 + 15;
        if (!skip) {
            const u32 stg = smb + ASTG + (u32)(kt & 1) * ASTG;
            float s[8][4];
#pragma unroll
            for (int f = 0; f < 8; f++)
#pragma unroll
                for (int q = 0; q < 4; q++) s[f][q] = 0.f;

#pragma unroll
            for (int ks = 0; ks < 8; ks++) {
#pragma unroll
                for (int p = 0; p < 4; p++) {
                    u32 addr = stg + (u32)(p * 16 + kRow) * 256u + (((u32)(ks * 32) + kColT) ^ kSw);
                    u32 kh4[4], kl4[4];
                    ldsm4(kh4, addr);
                    ldsm4(kl4, addr + AKLO);
                    mma16816(s[2 * p], qhf[ks], &kh4[0]);
                    mma16816(s[2 * p], qhf[ks], &kl4[0]);
                    mma16816(s[2 * p], qlf[ks], &kh4[0]);
                    mma16816(s[2 * p + 1], qhf[ks], &kh4[2]);
                    mma16816(s[2 * p + 1], qhf[ks], &kl4[2]);
                    mma16816(s[2 * p + 1], qlf[ks], &kh4[2]);
                }
            }

            const int row0 = qg0 + wid * 16 + (lane >> 2);
            if (kg0 + 63 > qg0 + wid * 16) {
#pragma unroll
                for (int f = 0; f < 8; f++) {
                    const int col = kg0 + f * 8 + (lane & 3) * 2;
                    if (col > row0)     s[f][0] = -1e30f;
                    if (col + 1 > row0) s[f][1] = -1e30f;
                    if (col > row0 + 8)     s[f][2] = -1e30f;
                    if (col + 1 > row0 + 8) s[f][3] = -1e30f;
                }
            }

            float mx0 = -1e30f, mx1 = -1e30f;
#pragma unroll
            for (int f = 0; f < 8; f++) {
                mx0 = fmaxf(mx0, fmaxf(s[f][0], s[f][1]));
                mx1 = fmaxf(mx1, fmaxf(s[f][2], s[f][3]));
            }
            mx0 = fmaxf(mx0, __shfl_xor_sync(0xffffffffu, mx0, 1));
            mx0 = fmaxf(mx0, __shfl_xor_sync(0xffffffffu, mx0, 2));
            mx1 = fmaxf(mx1, __shfl_xor_sync(0xffffffffu, mx1, 1));
            mx1 = fmaxf(mx1, __shfl_xor_sync(0xffffffffu, mx1, 2));
            const float mn0 = fmaxf(m0r, mx0), mn1 = fmaxf(m1r, mx1);
            const float al0 = __expf(m0r - mn0), al1 = __expf(m1r - mn1);
            m0r = mn0; m1r = mn1;
            float s0 = 0.f, s1 = 0.f;
#pragma unroll
            for (int f = 0; f < 8; f++) {
                s[f][0] = __expf(s[f][0] - mn0);
                s[f][1] = __expf(s[f][1] - mn0);
                s[f][2] = __expf(s[f][2] - mn1);
                s[f][3] = __expf(s[f][3] - mn1);
                s0 += s[f][0] + s[f][1];
                s1 += s[f][2] + s[f][3];
            }
            s0 += __shfl_xor_sync(0xffffffffu, s0, 1);
            s0 += __shfl_xor_sync(0xffffffffu, s0, 2);
            s1 += __shfl_xor_sync(0xffffffffu, s1, 1);
            s1 += __shfl_xor_sync(0xffffffffu, s1, 2);
            l0 = l0 * al0 + s0;
            l1 = l1 * al1 + s1;
#pragma unroll
            for (int f = 0; f < 16; f++) {
                o[f][0] *= al0; o[f][1] *= al0;
                o[f][2] *= al1; o[f][3] *= al1;
            }

            u32 ph[4][4], pl[4][4];
#pragma unroll
            for (int j = 0; j < 4; j++) {
                ph[j][0] = split_pack(s[2 * j][0], s[2 * j][1], pl[j][0]);
                ph[j][1] = split_pack(s[2 * j][2], s[2 * j][3], pl[j][1]);
                ph[j][2] = split_pack(s[2 * j + 1][0], s[2 * j + 1][1], pl[j][2]);
                ph[j][3] = split_pack(s[2 * j + 1][2], s[2 * j + 1][3], pl[j][3]);
            }

#pragma unroll
            for (int j = 0; j < 4; j++) {
#pragma unroll
                for (int ep = 0; ep < 8; ep++) {
                    u32 va = stg + AVHI + (u32)(j * 16 + vRow) * 256u + (((u32)(ep * 32) + vColT) ^ kSw);
                    u32 vh4[4], vl4[4];
                    ldsm4t(vh4, va);
                    ldsm4t(vl4, va + 16384);
                    mma16816(o[2 * ep], ph[j], &vh4[0]);
                    mma16816(o[2 * ep], ph[j], &vl4[0]);
                    mma16816(o[2 * ep], pl[j], &vh4[0]);
                    mma16816(o[2 * ep + 1], ph[j], &vh4[2]);
                    mma16816(o[2 * ep + 1], ph[j], &vl4[2]);
                    mma16816(o[2 * ep + 1], pl[j], &vh4[2]);
                }
            }
        }
        __syncthreads();
    }

    const float inv0 = 1.0f / l0, inv1 = 1.0f / l1;
    const int srow0 = qg0 + wid * 16 + (lane >> 2);
    const size_t ro0 = ((size_t)b * S_ + srow0) * F_ + h * HD_;
    const size_t ro1 = ro0 + (size_t)8 * F_;
#pragma unroll
    for (int f = 0; f < 16; f++) {
        const int e = f * 8 + (lane & 3) * 2;
        u32 lo0, lo1;
        u32 hi0 = split_pack(o[f][0] * inv0, o[f][1] * inv0, lo0);
        u32 hi1 = split_pack(o[f][2] * inv1, o[f][3] * inv1, lo1);
        *(u32*)(g_AThi + ro0 + e) = hi0;
        *(u32*)(g_ATlo + ro0 + e) = lo0;
        *(u32*)(g_AThi + ro1 + e) = hi1;
        *(u32*)(g_ATlo + ro1 + e) = lo1;
    }
}

// ---------------------------------------------------------------------------
extern "C" void kernel_launch(void* const* d_in, const int* in_sizes, int n_in,
                              void* d_out, int out_size)
{
    const float* hs = (const float*)d_in[0];
    const float* cs = (const float*)d_in[1];
    const float* sn = (const float*)d_in[2];
    const float* wq = (const float*)d_in[3];
    const float* wo = (const float*)d_in[4];
    float* out = (float*)d_out;

    cudaFuncSetAttribute(mma_gemm_kernel<0>, cudaFuncAttributeMaxDynamicSharedMemorySize, MMA_SMEM_BYTES);
    cudaFuncSetAttribute(mma_gemm_kernel<1>, cudaFuncAttributeMaxDynamicSharedMemorySize, MMA_SMEM_BYTES);
    cudaFuncSetAttribute(attn_mma_kernel, cudaFuncAttributeMaxDynamicSharedMemorySize, ATT_SMEM_BYTES);

    __nv_bfloat16 *ahi, *alo, *whi, *wlo, *wohi, *wolo, *athi, *atlo;
    cudaGetSymbolAddress((void**)&ahi, g_Ahi);   cudaGetSymbolAddress((void**)&alo, g_Alo);
    cudaGetSymbolAddress((void**)&whi, g_Whi);   cudaGetSymbolAddress((void**)&wlo, g_Wlo);
    cudaGetSymbolAddress((void**)&wohi, g_Wohi); cudaGetSymbolAddress((void**)&wolo, g_Wolo);
    cudaGetSymbolAddress((void**)&athi, g_AThi); cudaGetSymbolAddress((void**)&atlo, g_ATlo);

    {
        int n4 = (M_ * D_) / 4;
        split_bf16_kernel<<<(n4 + 255) / 256, 256>>>((const float4*)hs, (uint2*)ahi, (uint2*)alo, n4);
        n4 = (NQKV * D_) / 4;
        split_bf16_kernel<<<(n4 + 255) / 256, 256>>>((const float4*)wq, (uint2*)whi, (uint2*)wlo, n4);
        n4 = (D_ * F_) / 4;
        split_bf16_kernel<<<(n4 + 255) / 256, 256>>>((const float4*)wo, (uint2*)wohi, (uint2*)wolo, n4);
    }

    // QKV projection: N tiles of 256 (NQKV/256 = 24)
    mma_gemm_kernel<0><<<dim3(NQKV / 256, M_ / 128), 512, MMA_SMEM_BYTES>>>(
        ahi, alo, whi, wlo, cs, sn, nullptr);

    attn_mma_kernel<<<dim3(S_ / 128, H_, B_), 256, ATT_SMEM_BYTES>>>();

    // Output projection: D/256 = 8
    mma_gemm_kernel<1><<<dim3(D_ / 256, M_ / 128), 512, MMA_SMEM_BYTES>>>(
        athi, atlo, wohi, wolo, nullptr, nullptr, out);
}

// round 8
// speedup vs baseline: 1.0437x; 1.0327x over previous
#include <cuda_runtime.h>
#include <cuda_bf16.h>
#include <cstdint>
#include <math.h>

// Problem constants
#define B_   2
#define S_   2048
#define D_   2048
#define H_   16
#define HD_  128
#define M_   (B_ * S_)     // 4096
#define F_   (H_ * HD_)    // 2048
#define NQKV (3 * F_)      // 6144

typedef unsigned long long u64;
typedef unsigned int u32;

__device__ __forceinline__ u32 smem_u32(const void* p) {
    u32 a; asm("{ .reg .u64 t; cvta.to.shared.u64 t, %1; cvt.u32.u64 %0, t; }" : "=r"(a) : "l"(p));
    return a;
}

// ---- mma.sync / ldmatrix / cp.async ----
__device__ __forceinline__ void ldsm4(u32* r, u32 addr) {
    asm volatile("ldmatrix.sync.aligned.m8n8.x4.shared.b16 {%0,%1,%2,%3}, [%4];"
        : "=r"(r[0]), "=r"(r[1]), "=r"(r[2]), "=r"(r[3]) : "r"(addr));
}
__device__ __forceinline__ void ldsm4t(u32* r, u32 addr) {
    asm volatile("ldmatrix.sync.aligned.m8n8.x4.trans.shared.b16 {%0,%1,%2,%3}, [%4];"
        : "=r"(r[0]), "=r"(r[1]), "=r"(r[2]), "=r"(r[3]) : "r"(addr));
}
__device__ __forceinline__ void mma16816(float* d, const u32* a, const u32* b) {
    asm volatile("mma.sync.aligned.m16n8k16.row.col.f32.bf16.bf16.f32 "
        "{%0,%1,%2,%3}, {%4,%5,%6,%7}, {%8,%9}, {%0,%1,%2,%3};"
        : "+f"(d[0]), "+f"(d[1]), "+f"(d[2]), "+f"(d[3])
        : "r"(a[0]), "r"(a[1]), "r"(a[2]), "r"(a[3]), "r"(b[0]), "r"(b[1]));
}
__device__ __forceinline__ void cp_async16(u32 dst, const void* src) {
    asm volatile("cp.async.cg.shared.global [%0], [%1], 16;" :: "r"(dst), "l"(src));
}
#define CP_COMMIT() asm volatile("cp.async.commit_group;" ::: "memory")
#define CP_WAIT0()  asm volatile("cp.async.wait_group 0;" ::: "memory")
#define CP_WAIT1()  asm volatile("cp.async.wait_group 1;" ::: "memory")

// split f32 pair -> packed bf16x2 hi (returned) and lo (out-param)
__device__ __forceinline__ u32 split_pack(float x, float y, u32& lo) {
    float hx = __bfloat162float(__float2bfloat16(x));
    float hy = __bfloat162float(__float2bfloat16(y));
    u32 hi;
    asm("cvt.rn.bf16x2.f32 %0, %1, %2;" : "=r"(hi) : "f"(hy), "f"(hx));
    asm("cvt.rn.bf16x2.f32 %0, %1, %2;" : "=r"(lo) : "f"(y - hy), "f"(x - hx));
    return hi;
}

// ---------------- device scratch ----------------
__device__ __nv_bfloat16 g_Qhi[(size_t)B_ * H_ * S_ * HD_], g_Qlo[(size_t)B_ * H_ * S_ * HD_];
__device__ __nv_bfloat16 g_Khi[(size_t)B_ * H_ * S_ * HD_], g_Klo[(size_t)B_ * H_ * S_ * HD_];
__device__ __nv_bfloat16 g_Vhi[(size_t)B_ * H_ * S_ * HD_], g_Vlo[(size_t)B_ * H_ * S_ * HD_];
__device__ __nv_bfloat16 g_Ahi[(size_t)M_ * D_],   g_Alo[(size_t)M_ * D_];
__device__ __nv_bfloat16 g_Whi[(size_t)NQKV * D_], g_Wlo[(size_t)NQKV * D_];
__device__ __nv_bfloat16 g_Wohi[(size_t)D_ * F_],  g_Wolo[(size_t)D_ * F_];
__device__ __nv_bfloat16 g_AThi[(size_t)M_ * F_],  g_ATlo[(size_t)M_ * F_];

// ---------------------------------------------------------------------------
// Split fp32 -> bf16 (hi, lo)
// ---------------------------------------------------------------------------
__global__ void split_bf16_kernel(const float4* __restrict__ x,
                                  uint2* __restrict__ hi, uint2* __restrict__ lo, int n4)
{
    int i = blockIdx.x * blockDim.x + threadIdx.x;
    if (i >= n4) return;
    float4 v = x[i];
    u32 l0, l1, h0, h1;
    h0 = split_pack(v.x, v.y, l0);
    h1 = split_pack(v.z, v.w, l1);
    hi[i] = make_uint2(h0, h1);
    lo[i] = make_uint2(l0, l1);
}

// ---------------------------------------------------------------------------
// bf16x3 GEMM via mma.sync m16n8k16. Tile 128x128, K=2048, chunks of 64.
// 8 warps (2m x 4n), warp tile 64x32. Term-major MMA ordering (RAW distance 16).
// 3-stage cp.async pipeline (3 x 64KB = 192KB).
// MODE 0: QKV + RoPE -> Q/K/V bf16 hi/lo.  MODE 1: out proj -> fp32 out.
// ---------------------------------------------------------------------------
#define NCHUNK 32
#define TILEB 16384
#define STAGEB (4 * TILEB)                 // 64KB
#define MMA_SMEM_BYTES (3 * STAGEB)        // 192KB

__device__ __forceinline__ u32 swz(u32 row, u32 cb) {
    return row * 128u + (cb ^ ((row & 7u) << 4));
}

template <int MODE>
__global__ void __launch_bounds__(256, 1) mma_gemm_kernel(
    const __nv_bfloat16* __restrict__ Ahi, const __nv_bfloat16* __restrict__ Alo,
    const __nv_bfloat16* __restrict__ Bhi, const __nv_bfloat16* __restrict__ Blo,
    const float* __restrict__ cs, const float* __restrict__ sn,
    float* __restrict__ out)
{
    extern __shared__ char dyn_smem[];
    const u32 smb = smem_u32(dyn_smem);

    const int tid = threadIdx.x;
    const int wid = tid >> 5;
    const int lane = tid & 31;
    const int wm = wid >> 2, wn = wid & 3;
    const int m0 = blockIdx.y << 7;
    const int n0 = blockIdx.x << 7;

    const __nv_bfloat16* srcOp[4] = {Ahi, Alo, Bhi, Blo};
    const int rowOff[4] = {m0, m0, n0, n0};

    auto load_chunk = [&](int st, int k0) {
        const u32 sb = smb + (u32)st * STAGEB;
#pragma unroll
        for (int op = 0; op < 4; op++) {
#pragma unroll
            for (int rep = 0; rep < 4; rep++) {
                int lin = rep * 256 + tid;
                int row = lin >> 3, u = lin & 7;
                cp_async16(sb + op * TILEB + swz(row, u * 16),
                           srcOp[op] + (size_t)(rowOff[op] + row) * 2048 + k0 + u * 8);
            }
        }
    };

    load_chunk(0, 0);  CP_COMMIT();
    load_chunk(1, 64); CP_COMMIT();
    CP_WAIT1();                 // chunk 0 ready
    __syncthreads();

    // fragment addressing
    const u32 aRow = (u32)(wm * 64 + (lane & 15));
    const u32 aSw = (aRow & 7u) << 4;
    const u32 aColSel = (u32)((lane >> 4) << 4);
    u32 aOff[4];
#pragma unroll
    for (int fm = 0; fm < 4; fm++) aOff[fm] = (aRow + fm * 16) * 128u;

    u32 bOff[2], bSw[2];
#pragma unroll
    for (int p = 0; p < 2; p++) {
        u32 brow = (u32)(wn * 32 + p * 16 + ((lane >> 4) << 3) + (lane & 7));
        bOff[p] = brow * 128u;
        bSw[p] = (brow & 7u) << 4;
    }
    const u32 bColSel = (u32)(((lane >> 3) & 1) << 4);

    float acc[4][4][4];
#pragma unroll
    for (int i = 0; i < 4; i++)
#pragma unroll
        for (int j = 0; j < 4; j++)
#pragma unroll
            for (int q = 0; q < 4; q++) acc[i][j][q] = 0.f;

    int stage_idx = 0;
    for (int c = 0; c < NCHUNK; c++) {
        if (c + 2 < NCHUNK) {
            int nst = stage_idx + 2; if (nst >= 3) nst -= 3;
            load_chunk(nst, (c + 2) * 64);
            CP_COMMIT();
        }
        const u32 stage = smb + (u32)stage_idx * STAGEB;
#pragma unroll
        for (int ks = 0; ks < 4; ks++) {
            const u32 cbA = (u32)(ks * 32) + aColSel;
            const u32 cbB = (u32)(ks * 32) + bColSel;
            u32 ah[4][4], al[4][4], bh[2][4], bl[2][4];
#pragma unroll
            for (int fm = 0; fm < 4; fm++) {
                ldsm4(ah[fm], stage + aOff[fm] + (cbA ^ aSw));
                ldsm4(al[fm], stage + TILEB + aOff[fm] + (cbA ^ aSw));
            }
#pragma unroll
            for (int p = 0; p < 2; p++) {
                ldsm4(bh[p], stage + 2 * TILEB + bOff[p] + (cbB ^ bSw[p]));
                ldsm4(bl[p], stage + 3 * TILEB + bOff[p] + (cbB ^ bSw[p]));
            }
            // term-major: 16 MMAs per term -> same-acc distance 16
#pragma unroll
            for (int fm = 0; fm < 4; fm++)
#pragma unroll
                for (int p = 0; p < 2; p++)
#pragma unroll
                    for (int q = 0; q < 2; q++)
                        mma16816(acc[fm][p * 2 + q], ah[fm], &bh[p][q * 2]);
#pragma unroll
            for (int fm = 0; fm < 4; fm++)
#pragma unroll
                for (int p = 0; p < 2; p++)
#pragma unroll
                    for (int q = 0; q < 2; q++)
                        mma16816(acc[fm][p * 2 + q], ah[fm], &bl[p][q * 2]);
#pragma unroll
            for (int fm = 0; fm < 4; fm++)
#pragma unroll
                for (int p = 0; p < 2; p++)
#pragma unroll
                    for (int q = 0; q < 2; q++)
                        mma16816(acc[fm][p * 2 + q], al[fm], &bh[p][q * 2]);
        }
        if (c + 2 < NCHUNK) { CP_WAIT1(); } else { CP_WAIT0(); }
        __syncthreads();
        stage_idx++; if (stage_idx >= 3) stage_idx = 0;
    }

    // epilogue: accum -> smem fp32 (pitch 132), then scatter
    float* S = (float*)dyn_smem;
    const int er = lane >> 2, ec = (lane & 3) << 1;
#pragma unroll
    for (int fm = 0; fm < 4; fm++)
#pragma unroll
        for (int fn = 0; fn < 4; fn++) {
            const int r0 = wm * 64 + fm * 16 + er;
            const int c0 = wn * 32 + fn * 8 + ec;
            S[r0 * 132 + c0] = acc[fm][fn][0];
            S[r0 * 132 + c0 + 1] = acc[fm][fn][1];
            S[(r0 + 8) * 132 + c0] = acc[fm][fn][2];
            S[(r0 + 8) * 132 + c0 + 1] = acc[fm][fn][3];
        }
    __syncthreads();

    const int r = tid >> 1, t2 = tid & 1;
    const int m = m0 + r;
    if (MODE == 0) {
        const int h = n0 / 384;
        const int sub = (n0 % 384) >> 7;          // 0=q,1=k,2=v
        const int b = m >> 11, s = m & 2047;
        const size_t doff = ((size_t)(b * H_ + h) * S_ + s) * HD_;
        if (sub == 2) {
            const int cb = t2 * 64;
#pragma unroll
            for (int g = 0; g < 8; g++) {
                u32 hw[4], lw[4];
#pragma unroll
                for (int p = 0; p < 4; p++) {
                    float x = S[r * 132 + cb + g * 8 + p * 2];
                    float y = S[r * 132 + cb + g * 8 + p * 2 + 1];
                    hw[p] = split_pack(x, y, lw[p]);
                }
                *(uint4*)(g_Vhi + doff + cb + g * 8) = make_uint4(hw[0], hw[1], hw[2], hw[3]);
                *(uint4*)(g_Vlo + doff + cb + g * 8) = make_uint4(lw[0], lw[1], lw[2], lw[3]);
            }
        } else {
            const float scl = (sub == 0) ? 0.08838834764831845f : 1.0f;
            __nv_bfloat16* dhi = (sub == 0) ? g_Qhi : g_Khi;
            __nv_bfloat16* dlo = (sub == 0) ? g_Qlo : g_Klo;
            const float* crow = cs + (size_t)s * HD_;
            const float* srow = sn + (size_t)s * HD_;
#pragma unroll
            for (int g = 0; g < 4; g++) {
                const int cA = t2 * 32 + g * 8;
                const int cB = cA + 64;
                u32 hA[4], lA[4], hB[4], lB[4];
#pragma unroll
                for (int p = 0; p < 4; p++) {
                    const int c0 = cA + p * 2, c1 = cA + p * 2 + 1;
                    float xa0 = S[r * 132 + c0], xa1 = S[r * 132 + c1];
                    float xb0 = S[r * 132 + c0 + 64], xb1 = S[r * 132 + c1 + 64];
                    float oa0 = (xa0 * crow[c0] - xb0 * srow[c0]) * scl;
                    float oa1 = (xa1 * crow[c1] - xb1 * srow[c1]) * scl;
                    float ob0 = (xb0 * crow[c0 + 64] + xa0 * srow[c0 + 64]) * scl;
                    float ob1 = (xb1 * crow[c1 + 64] + xa1 * srow[c1 + 64]) * scl;
                    hA[p] = split_pack(oa0, oa1, lA[p]);
                    hB[p] = split_pack(ob0, ob1, lB[p]);
                }
                *(uint4*)(dhi + doff + cA) = make_uint4(hA[0], hA[1], hA[2], hA[3]);
                *(uint4*)(dlo + doff + cA) = make_uint4(lA[0], lA[1], lA[2], lA[3]);
                *(uint4*)(dhi + doff + cB) = make_uint4(hB[0], hB[1], hB[2], hB[3]);
                *(uint4*)(dlo + doff + cB) = make_uint4(lB[0], lB[1], lB[2], lB[3]);
            }
        }
    } else {
        float* dst = out + (size_t)m * D_ + n0;
        const int cbase = t2 * 64;
#pragma unroll
        for (int q4 = 0; q4 < 16; q4++) {
            float4 w = *(const float4*)(S + r * 132 + cbase + q4 * 4);
            *(float4*)(dst + cbase + q4 * 4) = w;
        }
    }
}

// ---------------------------------------------------------------------------
// Tensor-core causal flash attention. Term-major MMA reordering in QK and
// ep-pair reordering in PV to break accumulator RAW chains.
// ---------------------------------------------------------------------------
#define ATT_SMEM_BYTES (192 * 1024)
#define AQLO 32768
#define ASTG 65536
#define AKLO 16384
#define AVHI 32768
#define AVLO 49152

__device__ __forceinline__ u32 aswz(u32 row, u32 cb) {
    return row * 256u + (cb ^ ((row & 7u) << 4));
}

__global__ void __launch_bounds__(256, 1) attn_mma_kernel()
{
    extern __shared__ char dyn_smem[];
    const u32 smb = smem_u32(dyn_smem);
    const int tid = threadIdx.x, wid = tid >> 5, lane = tid & 31;
    const int qt = blockIdx.x, h = blockIdx.y, b = blockIdx.z;
    const int qg0 = qt << 7;
    const size_t bh = (size_t)(b * H_ + h) * S_;

    {
        const __nv_bfloat16* qh = g_Qhi + (bh + qg0) * HD_;
        const __nv_bfloat16* ql = g_Qlo + (bh + qg0) * HD_;
#pragma unroll
        for (int rep = 0; rep < 8; rep++) {
            int lin = rep * 256 + tid;
            int row = lin >> 4, u = lin & 15;
            u32 so = aswz(row, u * 16);
            cp_async16(smb + so, qh + (size_t)row * HD_ + u * 8);
            cp_async16(smb + AQLO + so, ql + (size_t)row * HD_ + u * 8);
        }
        CP_COMMIT();
    }

    const __nv_bfloat16* khg = g_Khi + bh * HD_;
    const __nv_bfloat16* klg = g_Klo + bh * HD_;
    const __nv_bfloat16* vhg = g_Vhi + bh * HD_;
    const __nv_bfloat16* vlg = g_Vlo + bh * HD_;

    auto load_stage = [&](int st, int kg0) {
        const u32 dst = smb + ASTG + (u32)st * ASTG;
        const __nv_bfloat16* srcs[4] = {khg + (size_t)kg0 * HD_, klg + (size_t)kg0 * HD_,
                                        vhg + (size_t)kg0 * HD_, vlg + (size_t)kg0 * HD_};
#pragma unroll
        for (int op = 0; op < 4; op++) {
#pragma unroll
            for (int rep = 0; rep < 4; rep++) {
                int lin = rep * 256 + tid;
                int row = lin >> 4, u = lin & 15;
                cp_async16(dst + op * 16384 + aswz(row, u * 16),
                           srcs[op] + (size_t)row * HD_ + u * 8);
            }
        }
    };

    const int nkt = 2 * qt + 2;
    load_stage(0, 0);
    CP_COMMIT();

    const u32 aRow = (u32)(wid * 16 + (lane & 15));
    const u32 aSw = (aRow & 7u) << 4;
    const u32 aCol = (u32)((lane >> 4) << 4);
    const u32 aBase = aRow * 256u;
    const u32 kRow = (u32)(((lane >> 4) << 3) + (lane & 7));
    const u32 kSw = (u32)((lane & 7) << 4);
    const u32 kColT = (u32)(((lane >> 3) & 1) << 4);
    const u32 vRow = (u32)(lane & 15);
    const u32 vColT = (u32)((lane >> 4) << 4);

    u32 qhf[8][4], qlf[8][4];
    float o[16][4];
#pragma unroll
    for (int f = 0; f < 16; f++)
#pragma unroll
        for (int q = 0; q < 4; q++) o[f][q] = 0.f;
    float m0r = -1e30f, m1r = -1e30f, l0 = 0.f, l1 = 0.f;

    for (int kt = 0; kt < nkt; kt++) {
        if (kt + 1 < nkt) {
            load_stage((kt + 1) & 1, (kt + 1) * 64);
            CP_COMMIT();
            CP_WAIT1();
        } else {
            CP_WAIT0();
        }
        __syncthreads();
        if (kt == 0) {
#pragma unroll
            for (int ks = 0; ks < 8; ks++) {
                u32 qa = smb + aBase + (((u32)(ks * 32) + aCol) ^ aSw);
                ldsm4(qhf[ks], qa);
                ldsm4(qlf[ks], qa + AQLO);
            }
        }
        const int kg0 = kt * 64;
        const bool skip = kg0 > qg0 + wid * 16 + 15;
        if (!skip) {
            const u32 stg = smb + ASTG + (u32)(kt & 1) * ASTG;
            float s[8][4];
#pragma unroll
            for (int f = 0; f < 8; f++)
#pragma unroll
                for (int q = 0; q < 4; q++) s[f][q] = 0.f;

            // QK^T (bf16x3), term-major per ks (same-acc distance 8)
#pragma unroll
            for (int ks = 0; ks < 8; ks++) {
                u32 kh[4][4], kl[4][4];
#pragma unroll
                for (int p = 0; p < 4; p++) {
                    u32 addr = stg + (u32)(p * 16 + kRow) * 256u + (((u32)(ks * 32) + kColT) ^ kSw);
                    ldsm4(kh[p], addr);
                    ldsm4(kl[p], addr + AKLO);
                }
#pragma unroll
                for (int p = 0; p < 4; p++) {
                    mma16816(s[2 * p], qhf[ks], &kh[p][0]);
                    mma16816(s[2 * p + 1], qhf[ks], &kh[p][2]);
                }
#pragma unroll
                for (int p = 0; p < 4; p++) {
                    mma16816(s[2 * p], qhf[ks], &kl[p][0]);
                    mma16816(s[2 * p + 1], qhf[ks], &kl[p][2]);
                }
#pragma unroll
                for (int p = 0; p < 4; p++) {
                    mma16816(s[2 * p], qlf[ks], &kh[p][0]);
                    mma16816(s[2 * p + 1], qlf[ks], &kh[p][2]);
                }
            }

            const int row0 = qg0 + wid * 16 + (lane >> 2);
            if (kg0 + 63 > qg0 + wid * 16) {
#pragma unroll
                for (int f = 0; f < 8; f++) {
                    const int col = kg0 + f * 8 + (lane & 3) * 2;
                    if (col > row0)     s[f][0] = -1e30f;
                    if (col + 1 > row0) s[f][1] = -1e30f;
                    if (col > row0 + 8)     s[f][2] = -1e30f;
                    if (col + 1 > row0 + 8) s[f][3] = -1e30f;
                }
            }

            float mx0 = -1e30f, mx1 = -1e30f;
#pragma unroll
            for (int f = 0; f < 8; f++) {
                mx0 = fmaxf(mx0, fmaxf(s[f][0], s[f][1]));
                mx1 = fmaxf(mx1, fmaxf(s[f][2], s[f][3]));
            }
            mx0 = fmaxf(mx0, __shfl_xor_sync(0xffffffffu, mx0, 1));
            mx0 = fmaxf(mx0, __shfl_xor_sync(0xffffffffu, mx0, 2));
            mx1 = fmaxf(mx1, __shfl_xor_sync(0xffffffffu, mx1, 1));
            mx1 = fmaxf(mx1, __shfl_xor_sync(0xffffffffu, mx1, 2));
            const float mn0 = fmaxf(m0r, mx0), mn1 = fmaxf(m1r, mx1);
            const float al0 = __expf(m0r - mn0), al1 = __expf(m1r - mn1);
            m0r = mn0; m1r = mn1;
            float s0 = 0.f, s1 = 0.f;
#pragma unroll
            for (int f = 0; f < 8; f++) {
                s[f][0] = __expf(s[f][0] - mn0);
                s[f][1] = __expf(s[f][1] - mn0);
                s[f][2] = __expf(s[f][2] - mn1);
                s[f][3] = __expf(s[f][3] - mn1);
                s0 += s[f][0] + s[f][1];
                s1 += s[f][2] + s[f][3];
            }
            s0 += __shfl_xor_sync(0xffffffffu, s0, 1);
            s0 += __shfl_xor_sync(0xffffffffu, s0, 2);
            s1 += __shfl_xor_sync(0xffffffffu, s1, 1);
            s1 += __shfl_xor_sync(0xffffffffu, s1, 2);
            l0 = l0 * al0 + s0;
            l1 = l1 * al1 + s1;
#pragma unroll
            for (int f = 0; f < 16; f++) {
                o[f][0] *= al0; o[f][1] *= al0;
                o[f][2] *= al1; o[f][3] *= al1;
            }

            u32 ph[4][4], pl[4][4];
#pragma unroll
            for (int j = 0; j < 4; j++) {
                ph[j][0] = split_pack(s[2 * j][0], s[2 * j][1], pl[j][0]);
                ph[j][1] = split_pack(s[2 * j][2], s[2 * j][3], pl[j][1]);
                ph[j][2] = split_pack(s[2 * j + 1][0], s[2 * j + 1][1], pl[j][2]);
                ph[j][3] = split_pack(s[2 * j + 1][2], s[2 * j + 1][3], pl[j][3]);
            }

            // PV (bf16x3), ep-pair term-major (same-acc distance 4)
#pragma unroll
            for (int j = 0; j < 4; j++) {
#pragma unroll
                for (int epp = 0; epp < 4; epp++) {
                    u32 vh[2][4], vl[2][4];
#pragma unroll
                    for (int e2 = 0; e2 < 2; e2++) {
                        const int ep = epp * 2 + e2;
                        u32 va = stg + AVHI + (u32)(j * 16 + vRow) * 256u + (((u32)(ep * 32) + vColT) ^ kSw);
                        ldsm4t(vh[e2], va);
                        ldsm4t(vl[e2], va + 16384);
                    }
                    mma16816(o[4 * epp + 0], ph[j], &vh[0][0]);
                    mma16816(o[4 * epp + 1], ph[j], &vh[0][2]);
                    mma16816(o[4 * epp + 2], ph[j], &vh[1][0]);
                    mma16816(o[4 * epp + 3], ph[j], &vh[1][2]);
                    mma16816(o[4 * epp + 0], ph[j], &vl[0][0]);
                    mma16816(o[4 * epp + 1], ph[j], &vl[0][2]);
                    mma16816(o[4 * epp + 2], ph[j], &vl[1][0]);
                    mma16816(o[4 * epp + 3], ph[j], &vl[1][2]);
                    mma16816(o[4 * epp + 0], pl[j], &vh[0][0]);
                    mma16816(o[4 * epp + 1], pl[j], &vh[0][2]);
                    mma16816(o[4 * epp + 2], pl[j], &vh[1][0]);
                    mma16816(o[4 * epp + 3], pl[j], &vh[1][2]);
                }
            }
        }
        __syncthreads();
    }

    const float inv0 = 1.0f / l0, inv1 = 1.0f / l1;
    const int srow0 = qg0 + wid * 16 + (lane >> 2);
    const size_t ro0 = ((size_t)b * S_ + srow0) * F_ + h * HD_;
    const size_t ro1 = ro0 + (size_t)8 * F_;
#pragma unroll
    for (int f = 0; f < 16; f++) {
        const int e = f * 8 + (lane & 3) * 2;
        u32 lo0, lo1;
        u32 hi0 = split_pack(o[f][0] * inv0, o[f][1] * inv0, lo0);
        u32 hi1 = split_pack(o[f][2] * inv1, o[f][3] * inv1, lo1);
        *(u32*)(g_AThi + ro0 + e) = hi0;
        *(u32*)(g_ATlo + ro0 + e) = lo0;
        *(u32*)(g_AThi + ro1 + e) = hi1;
        *(u32*)(g_ATlo + ro1 + e) = lo1;
    }
}

// ---------------------------------------------------------------------------
extern "C" void kernel_launch(void* const* d_in, const int* in_sizes, int n_in,
                              void* d_out, int out_size)
{
    const float* hs = (const float*)d_in[0];
    const float* cs = (const float*)d_in[1];
    const float* sn = (const float*)d_in[2];
    const float* wq = (const float*)d_in[3];
    const float* wo = (const float*)d_in[4];
    float* out = (float*)d_out;

    cudaFuncSetAttribute(mma_gemm_kernel<0>, cudaFuncAttributeMaxDynamicSharedMemorySize, MMA_SMEM_BYTES);
    cudaFuncSetAttribute(mma_gemm_kernel<1>, cudaFuncAttributeMaxDynamicSharedMemorySize, MMA_SMEM_BYTES);
    cudaFuncSetAttribute(attn_mma_kernel, cudaFuncAttributeMaxDynamicSharedMemorySize, ATT_SMEM_BYTES);

    __nv_bfloat16 *ahi, *alo, *whi, *wlo, *wohi, *wolo, *athi, *atlo;
    cudaGetSymbolAddress((void**)&ahi, g_Ahi);   cudaGetSymbolAddress((void**)&alo, g_Alo);
    cudaGetSymbolAddress((void**)&whi, g_Whi);   cudaGetSymbolAddress((void**)&wlo, g_Wlo);
    cudaGetSymbolAddress((void**)&wohi, g_Wohi); cudaGetSymbolAddress((void**)&wolo, g_Wolo);
    cudaGetSymbolAddress((void**)&athi, g_AThi); cudaGetSymbolAddress((void**)&atlo, g_ATlo);

    {
        int n4 = (M_ * D_) / 4;
        split_bf16_kernel<<<(n4 + 255) / 256, 256>>>((const float4*)hs, (uint2*)ahi, (uint2*)alo, n4);
        n4 = (NQKV * D_) / 4;
        split_bf16_kernel<<<(n4 + 255) / 256, 256>>>((const float4*)wq, (uint2*)whi, (uint2*)wlo, n4);
        n4 = (D_ * F_) / 4;
        split_bf16_kernel<<<(n4 + 255) / 256, 256>>>((const float4*)wo, (uint2*)wohi, (uint2*)wolo, n4);
    }

    // QKV projection (tile 128x128, grid 48x32)
    mma_gemm_kernel<0><<<dim3(NQKV / 128, M_ / 128), 256, MMA_SMEM_BYTES>>>(
        ahi, alo, whi, wlo, cs, sn, nullptr);

    attn_mma_kernel<<<dim3(S_ / 128, H_, B_), 256, ATT_SMEM_BYTES>>>();

    // Output projection (grid 16x32)
    mma_gemm_kernel<1><<<dim3(D_ / 128, M_ / 128), 256, MMA_SMEM_BYTES>>>(
        athi, atlo, wohi, wolo, nullptr, nullptr, out);
}

// round 9
// speedup vs baseline: 1.2975x; 1.2433x over previous
#include <cuda_runtime.h>
#include <cuda_fp16.h>
#include <cstdint>
#include <math.h>

// Problem constants
#define B_   2
#define S_   2048
#define D_   2048
#define H_   16
#define HD_  128
#define M_   (B_ * S_)     // 4096
#define F_   (H_ * HD_)    // 2048
#define NQKV (3 * F_)      // 6144

typedef unsigned long long u64;
typedef unsigned int u32;

__device__ __forceinline__ u32 smem_u32(const void* p) {
    u32 a; asm("{ .reg .u64 t; cvta.to.shared.u64 t, %1; cvt.u32.u64 %0, t; }" : "=r"(a) : "l"(p));
    return a;
}

// ---- mma.sync / ldmatrix / cp.async ----
__device__ __forceinline__ void ldsm4(u32* r, u32 addr) {
    asm volatile("ldmatrix.sync.aligned.m8n8.x4.shared.b16 {%0,%1,%2,%3}, [%4];"
        : "=r"(r[0]), "=r"(r[1]), "=r"(r[2]), "=r"(r[3]) : "r"(addr));
}
__device__ __forceinline__ void ldsm4t(u32* r, u32 addr) {
    asm volatile("ldmatrix.sync.aligned.m8n8.x4.trans.shared.b16 {%0,%1,%2,%3}, [%4];"
        : "=r"(r[0]), "=r"(r[1]), "=r"(r[2]), "=r"(r[3]) : "r"(addr));
}
__device__ __forceinline__ void mma16816(float* d, const u32* a, const u32* b) {
    asm volatile("mma.sync.aligned.m16n8k16.row.col.f32.f16.f16.f32 "
        "{%0,%1,%2,%3}, {%4,%5,%6,%7}, {%8,%9}, {%0,%1,%2,%3};"
        : "+f"(d[0]), "+f"(d[1]), "+f"(d[2]), "+f"(d[3])
        : "r"(a[0]), "r"(a[1]), "r"(a[2]), "r"(a[3]), "r"(b[0]), "r"(b[1]));
}
__device__ __forceinline__ void cp_async16(u32 dst, const void* src) {
    asm volatile("cp.async.cg.shared.global [%0], [%1], 16;" :: "r"(dst), "l"(src));
}
#define CP_COMMIT() asm volatile("cp.async.commit_group;" ::: "memory")
#define CP_WAIT0()  asm volatile("cp.async.wait_group 0;" ::: "memory")
#define CP_WAIT1()  asm volatile("cp.async.wait_group 1;" ::: "memory")

// split f32 pair -> packed f16x2 hi (returned) and lo (out-param)
__device__ __forceinline__ u32 split_pack(float x, float y, u32& lo) {
    float hx = __half2float(__float2half_rn(x));
    float hy = __half2float(__float2half_rn(y));
    u32 hi;
    asm("cvt.rn.f16x2.f32 %0, %1, %2;" : "=r"(hi) : "f"(hy), "f"(hx));
    asm("cvt.rn.f16x2.f32 %0, %1, %2;" : "=r"(lo) : "f"(y - hy), "f"(x - hx));
    return hi;
}
// round f32 pair -> packed f16x2 (hi only)
__device__ __forceinline__ u32 round_pack(float x, float y) {
    u32 hi;
    asm("cvt.rn.f16x2.f32 %0, %1, %2;" : "=r"(hi) : "f"(y), "f"(x));
    return hi;
}

// ---------------- device scratch ----------------
__device__ __half g_Qhi[(size_t)B_ * H_ * S_ * HD_], g_Qlo[(size_t)B_ * H_ * S_ * HD_];
__device__ __half g_Khi[(size_t)B_ * H_ * S_ * HD_], g_Klo[(size_t)B_ * H_ * S_ * HD_];
__device__ __half g_Vhi[(size_t)B_ * H_ * S_ * HD_], g_Vlo[(size_t)B_ * H_ * S_ * HD_];
__device__ __half g_Ahi[(size_t)M_ * D_],   g_Alo[(size_t)M_ * D_];
__device__ __half g_Whi[(size_t)NQKV * D_];
__device__ __half g_Wohi[(size_t)D_ * F_];
__device__ __half g_AThi[(size_t)M_ * F_],  g_ATlo[(size_t)M_ * F_];

// ---------------------------------------------------------------------------
// Split fp32 -> fp16 (hi, lo) ; and hi-only variant for weights
// ---------------------------------------------------------------------------
__global__ void split_f16_kernel(const float4* __restrict__ x,
                                 uint2* __restrict__ hi, uint2* __restrict__ lo, int n4)
{
    int i = blockIdx.x * blockDim.x + threadIdx.x;
    if (i >= n4) return;
    float4 v = x[i];
    u32 l0, l1, h0, h1;
    h0 = split_pack(v.x, v.y, l0);
    h1 = split_pack(v.z, v.w, l1);
    hi[i] = make_uint2(h0, h1);
    lo[i] = make_uint2(l0, l1);
}
__global__ void round_f16_kernel(const float4* __restrict__ x,
                                 uint2* __restrict__ hi, int n4)
{
    int i = blockIdx.x * blockDim.x + threadIdx.x;
    if (i >= n4) return;
    float4 v = x[i];
    hi[i] = make_uint2(round_pack(v.x, v.y), round_pack(v.z, v.w));
}

// ---------------------------------------------------------------------------
// fp16x2 GEMM (2 products: ahi*bhi + alo*bhi). Tile 128x128, K chunks of 64.
// 8 warps (2m x 4n), warp tile 64x32, term-major (RAW distance 16).
// Stage: Ahi | Alo | Bhi = 48KB; 3 stages = 144KB.
// MODE 0: QKV + RoPE -> Q/K/V f16 hi/lo.  MODE 1: out proj -> fp32 out.
// ---------------------------------------------------------------------------
#define NCHUNK 32
#define TILEB 16384
#define STAGEB (3 * TILEB)                 // 48KB
#define MMA_SMEM_BYTES (3 * STAGEB)        // 144KB

__device__ __forceinline__ u32 swz(u32 row, u32 cb) {
    return row * 128u + (cb ^ ((row & 7u) << 4));
}

template <int MODE>
__global__ void __launch_bounds__(256, 1) mma_gemm_kernel(
    const __half* __restrict__ Ahi, const __half* __restrict__ Alo,
    const __half* __restrict__ Bhi,
    const float* __restrict__ cs, const float* __restrict__ sn,
    float* __restrict__ out)
{
    extern __shared__ char dyn_smem[];
    const u32 smb = smem_u32(dyn_smem);

    const int tid = threadIdx.x;
    const int wid = tid >> 5;
    const int lane = tid & 31;
    const int wm = wid >> 2, wn = wid & 3;
    const int m0 = blockIdx.y << 7;
    const int n0 = blockIdx.x << 7;

    const __half* srcOp[3] = {Ahi, Alo, Bhi};
    const int rowOff[3] = {m0, m0, n0};

    auto load_chunk = [&](int st, int k0) {
        const u32 sb = smb + (u32)st * STAGEB;
#pragma unroll
        for (int op = 0; op < 3; op++) {
#pragma unroll
            for (int rep = 0; rep < 4; rep++) {
                int lin = rep * 256 + tid;
                int row = lin >> 3, u = lin & 7;
                cp_async16(sb + op * TILEB + swz(row, u * 16),
                           srcOp[op] + (size_t)(rowOff[op] + row) * 2048 + k0 + u * 8);
            }
        }
    };

    load_chunk(0, 0);  CP_COMMIT();
    load_chunk(1, 64); CP_COMMIT();
    CP_WAIT1();
    __syncthreads();

    const u32 aRow = (u32)(wm * 64 + (lane & 15));
    const u32 aSw = (aRow & 7u) << 4;
    const u32 aColSel = (u32)((lane >> 4) << 4);
    u32 aOff[4];
#pragma unroll
    for (int fm = 0; fm < 4; fm++) aOff[fm] = (aRow + fm * 16) * 128u;

    u32 bOff[2], bSw[2];
#pragma unroll
    for (int p = 0; p < 2; p++) {
        u32 brow = (u32)(wn * 32 + p * 16 + ((lane >> 4) << 3) + (lane & 7));
        bOff[p] = brow * 128u;
        bSw[p] = (brow & 7u) << 4;
    }
    const u32 bColSel = (u32)(((lane >> 3) & 1) << 4);

    float acc[4][4][4];
#pragma unroll
    for (int i = 0; i < 4; i++)
#pragma unroll
        for (int j = 0; j < 4; j++)
#pragma unroll
            for (int q = 0; q < 4; q++) acc[i][j][q] = 0.f;

    int stage_idx = 0;
    for (int c = 0; c < NCHUNK; c++) {
        if (c + 2 < NCHUNK) {
            int nst = stage_idx + 2; if (nst >= 3) nst -= 3;
            load_chunk(nst, (c + 2) * 64);
            CP_COMMIT();
        }
        const u32 stage = smb + (u32)stage_idx * STAGEB;
#pragma unroll
        for (int ks = 0; ks < 4; ks++) {
            const u32 cbA = (u32)(ks * 32) + aColSel;
            const u32 cbB = (u32)(ks * 32) + bColSel;
            u32 ah[4][4], al[4][4], bh[2][4];
#pragma unroll
            for (int fm = 0; fm < 4; fm++) {
                ldsm4(ah[fm], stage + aOff[fm] + (cbA ^ aSw));
                ldsm4(al[fm], stage + TILEB + aOff[fm] + (cbA ^ aSw));
            }
#pragma unroll
            for (int p = 0; p < 2; p++)
                ldsm4(bh[p], stage + 2 * TILEB + bOff[p] + (cbB ^ bSw[p]));
            // term-major: 16 MMAs per term -> same-acc distance 16
#pragma unroll
            for (int fm = 0; fm < 4; fm++)
#pragma unroll
                for (int p = 0; p < 2; p++)
#pragma unroll
                    for (int q = 0; q < 2; q++)
                        mma16816(acc[fm][p * 2 + q], ah[fm], &bh[p][q * 2]);
#pragma unroll
            for (int fm = 0; fm < 4; fm++)
#pragma unroll
                for (int p = 0; p < 2; p++)
#pragma unroll
                    for (int q = 0; q < 2; q++)
                        mma16816(acc[fm][p * 2 + q], al[fm], &bh[p][q * 2]);
        }
        if (c + 2 < NCHUNK) { CP_WAIT1(); } else { CP_WAIT0(); }
        __syncthreads();
        stage_idx++; if (stage_idx >= 3) stage_idx = 0;
    }

    // epilogue: accum -> smem fp32 (pitch 132), then scatter
    float* S = (float*)dyn_smem;
    const int er = lane >> 2, ec = (lane & 3) << 1;
#pragma unroll
    for (int fm = 0; fm < 4; fm++)
#pragma unroll
        for (int fn = 0; fn < 4; fn++) {
            const int r0 = wm * 64 + fm * 16 + er;
            const int c0 = wn * 32 + fn * 8 + ec;
            S[r0 * 132 + c0] = acc[fm][fn][0];
            S[r0 * 132 + c0 + 1] = acc[fm][fn][1];
            S[(r0 + 8) * 132 + c0] = acc[fm][fn][2];
            S[(r0 + 8) * 132 + c0 + 1] = acc[fm][fn][3];
        }
    __syncthreads();

    const int r = tid >> 1, t2 = tid & 1;
    const int m = m0 + r;
    if (MODE == 0) {
        const int h = n0 / 384;
        const int sub = (n0 % 384) >> 7;          // 0=q,1=k,2=v
        const int b = m >> 11, s = m & 2047;
        const size_t doff = ((size_t)(b * H_ + h) * S_ + s) * HD_;
        if (sub == 2) {
            const int cb = t2 * 64;
#pragma unroll
            for (int g = 0; g < 8; g++) {
                u32 hw[4], lw[4];
#pragma unroll
                for (int p = 0; p < 4; p++) {
                    float x = S[r * 132 + cb + g * 8 + p * 2];
                    float y = S[r * 132 + cb + g * 8 + p * 2 + 1];
                    hw[p] = split_pack(x, y, lw[p]);
                }
                *(uint4*)(g_Vhi + doff + cb + g * 8) = make_uint4(hw[0], hw[1], hw[2], hw[3]);
                *(uint4*)(g_Vlo + doff + cb + g * 8) = make_uint4(lw[0], lw[1], lw[2], lw[3]);
            }
        } else {
            const float scl = (sub == 0) ? 0.08838834764831845f : 1.0f;
            __half* dhi = (sub == 0) ? g_Qhi : g_Khi;
            __half* dlo = (sub == 0) ? g_Qlo : g_Klo;
            const float* crow = cs + (size_t)s * HD_;
            const float* srow = sn + (size_t)s * HD_;
#pragma unroll
            for (int g = 0; g < 4; g++) {
                const int cA = t2 * 32 + g * 8;
                const int cB = cA + 64;
                u32 hA[4], lA[4], hB[4], lB[4];
#pragma unroll
                for (int p = 0; p < 4; p++) {
                    const int c0 = cA + p * 2, c1 = cA + p * 2 + 1;
                    float xa0 = S[r * 132 + c0], xa1 = S[r * 132 + c1];
                    float xb0 = S[r * 132 + c0 + 64], xb1 = S[r * 132 + c1 + 64];
                    float oa0 = (xa0 * crow[c0] - xb0 * srow[c0]) * scl;
                    float oa1 = (xa1 * crow[c1] - xb1 * srow[c1]) * scl;
                    float ob0 = (xb0 * crow[c0 + 64] + xa0 * srow[c0 + 64]) * scl;
                    float ob1 = (xb1 * crow[c1 + 64] + xa1 * srow[c1 + 64]) * scl;
                    hA[p] = split_pack(oa0, oa1, lA[p]);
                    hB[p] = split_pack(ob0, ob1, lB[p]);
                }
                *(uint4*)(dhi + doff + cA) = make_uint4(hA[0], hA[1], hA[2], hA[3]);
                *(uint4*)(dlo + doff + cA) = make_uint4(lA[0], lA[1], lA[2], lA[3]);
                *(uint4*)(dhi + doff + cB) = make_uint4(hB[0], hB[1], hB[2], hB[3]);
                *(uint4*)(dlo + doff + cB) = make_uint4(lB[0], lB[1], lB[2], lB[3]);
            }
        }
    } else {
        float* dst = out + (size_t)m * D_ + n0;
        const int cbase = t2 * 64;
#pragma unroll
        for (int q4 = 0; q4 < 16; q4++) {
            float4 w = *(const float4*)(S + r * 132 + cbase + q4 * 4);
            *(float4*)(dst + cbase + q4 * 4) = w;
        }
    }
}

// ---------------------------------------------------------------------------
// Tensor-core causal flash attention (fp16x3, structure from R8).
// ---------------------------------------------------------------------------
#define ATT_SMEM_BYTES (192 * 1024)
#define AQLO 32768
#define ASTG 65536
#define AKLO 16384
#define AVHI 32768
#define AVLO 49152

__device__ __forceinline__ u32 aswz(u32 row, u32 cb) {
    return row * 256u + (cb ^ ((row & 7u) << 4));
}

__global__ void __launch_bounds__(256, 1) attn_mma_kernel()
{
    extern __shared__ char dyn_smem[];
    const u32 smb = smem_u32(dyn_smem);
    const int tid = threadIdx.x, wid = tid >> 5, lane = tid & 31;
    const int qt = blockIdx.x, h = blockIdx.y, b = blockIdx.z;
    const int qg0 = qt << 7;
    const size_t bh = (size_t)(b * H_ + h) * S_;

    {
        const __half* qh = g_Qhi + (bh + qg0) * HD_;
        const __half* ql = g_Qlo + (bh + qg0) * HD_;
#pragma unroll
        for (int rep = 0; rep < 8; rep++) {
            int lin = rep * 256 + tid;
            int row = lin >> 4, u = lin & 15;
            u32 so = aswz(row, u * 16);
            cp_async16(smb + so, qh + (size_t)row * HD_ + u * 8);
            cp_async16(smb + AQLO + so, ql + (size_t)row * HD_ + u * 8);
        }
        CP_COMMIT();
    }

    const __half* khg = g_Khi + bh * HD_;
    const __half* klg = g_Klo + bh * HD_;
    const __half* vhg = g_Vhi + bh * HD_;
    const __half* vlg = g_Vlo + bh * HD_;

    auto load_stage = [&](int st, int kg0) {
        const u32 dst = smb + ASTG + (u32)st * ASTG;
        const __half* srcs[4] = {khg + (size_t)kg0 * HD_, klg + (size_t)kg0 * HD_,
                                 vhg + (size_t)kg0 * HD_, vlg + (size_t)kg0 * HD_};
#pragma unroll
        for (int op = 0; op < 4; op++) {
#pragma unroll
            for (int rep = 0; rep < 4; rep++) {
                int lin = rep * 256 + tid;
                int row = lin >> 4, u = lin & 15;
                cp_async16(dst + op * 16384 + aswz(row, u * 16),
                           srcs[op] + (size_t)row * HD_ + u * 8);
            }
        }
    };

    const int nkt = 2 * qt + 2;
    load_stage(0, 0);
    CP_COMMIT();

    const u32 aRow = (u32)(wid * 16 + (lane & 15));
    const u32 aSw = (aRow & 7u) << 4;
    const u32 aCol = (u32)((lane >> 4) << 4);
    const u32 aBase = aRow * 256u;
    const u32 kRow = (u32)(((lane >> 4) << 3) + (lane & 7));
    const u32 kSw = (u32)((lane & 7) << 4);
    const u32 kColT = (u32)(((lane >> 3) & 1) << 4);
    const u32 vRow = (u32)(lane & 15);
    const u32 vColT = (u32)((lane >> 4) << 4);

    u32 qhf[8][4], qlf[8][4];
    float o[16][4];
#pragma unroll
    for (int f = 0; f < 16; f++)
#pragma unroll
        for (int q = 0; q < 4; q++) o[f][q] = 0.f;
    float m0r = -1e30f, m1r = -1e30f, l0 = 0.f, l1 = 0.f;

    for (int kt = 0; kt < nkt; kt++) {
        if (kt + 1 < nkt) {
            load_stage((kt + 1) & 1, (kt + 1) * 64);
            CP_COMMIT();
            CP_WAIT1();
        } else {
            CP_WAIT0();
        }
        __syncthreads();
        if (kt == 0) {
#pragma unroll
            for (int ks = 0; ks < 8; ks++) {
                u32 qa = smb + aBase + (((u32)(ks * 32) + aCol) ^ aSw);
                ldsm4(qhf[ks], qa);
                ldsm4(qlf[ks], qa + AQLO);
            }
        }
        const int kg0 = kt * 64;
        const bool skip = kg0 > qg0 + wid * 16 + 15;
        if (!skip) {
            const u32 stg = smb + ASTG + (u32)(kt & 1) * ASTG;
            float s[8][4];
#pragma unroll
            for (int f = 0; f < 8; f++)
#pragma unroll
                for (int q = 0; q < 4; q++) s[f][q] = 0.f;

            // QK^T (fp16x3), term-major per ks
#pragma unroll
            for (int ks = 0; ks < 8; ks++) {
                u32 kh[4][4], kl[4][4];
#pragma unroll
                for (int p = 0; p < 4; p++) {
                    u32 addr = stg + (u32)(p * 16 + kRow) * 256u + (((u32)(ks * 32) + kColT) ^ kSw);
                    ldsm4(kh[p], addr);
                    ldsm4(kl[p], addr + AKLO);
                }
#pragma unroll
                for (int p = 0; p < 4; p++) {
                    mma16816(s[2 * p], qhf[ks], &kh[p][0]);
                    mma16816(s[2 * p + 1], qhf[ks], &kh[p][2]);
                }
#pragma unroll
                for (int p = 0; p < 4; p++) {
                    mma16816(s[2 * p], qhf[ks], &kl[p][0]);
                    mma16816(s[2 * p + 1], qhf[ks], &kl[p][2]);
                }
#pragma unroll
                for (int p = 0; p < 4; p++) {
                    mma16816(s[2 * p], qlf[ks], &kh[p][0]);
                    mma16816(s[2 * p + 1], qlf[ks], &kh[p][2]);
                }
            }

            const int row0 = qg0 + wid * 16 + (lane >> 2);
            if (kg0 + 63 > qg0 + wid * 16) {
#pragma unroll
                for (int f = 0; f < 8; f++) {
                    const int col = kg0 + f * 8 + (lane & 3) * 2;
                    if (col > row0)     s[f][0] = -1e30f;
                    if (col + 1 > row0) s[f][1] = -1e30f;
                    if (col > row0 + 8)     s[f][2] = -1e30f;
                    if (col + 1 > row0 + 8) s[f][3] = -1e30f;
                }
            }

            float mx0 = -1e30f, mx1 = -1e30f;
#pragma unroll
            for (int f = 0; f < 8; f++) {
                mx0 = fmaxf(mx0, fmaxf(s[f][0], s[f][1]));
                mx1 = fmaxf(mx1, fmaxf(s[f][2], s[f][3]));
            }
            mx0 = fmaxf(mx0, __shfl_xor_sync(0xffffffffu, mx0, 1));
            mx0 = fmaxf(mx0, __shfl_xor_sync(0xffffffffu, mx0, 2));
            mx1 = fmaxf(mx1, __shfl_xor_sync(0xffffffffu, mx1, 1));
            mx1 = fmaxf(mx1, __shfl_xor_sync(0xffffffffu, mx1, 2));
            const float mn0 = fmaxf(m0r, mx0), mn1 = fmaxf(m1r, mx1);
            const float al0 = __expf(m0r - mn0), al1 = __expf(m1r - mn1);
            m0r = mn0; m1r = mn1;
            float s0 = 0.f, s1 = 0.f;
#pragma unroll
            for (int f = 0; f < 8; f++) {
                s[f][0] = __expf(s[f][0] - mn0);
                s[f][1] = __expf(s[f][1] - mn0);
                s[f][2] = __expf(s[f][2] - mn1);
                s[f][3] = __expf(s[f][3] - mn1);
                s0 += s[f][0] + s[f][1];
                s1 += s[f][2] + s[f][3];
            }
            s0 += __shfl_xor_sync(0xffffffffu, s0, 1);
            s0 += __shfl_xor_sync(0xffffffffu, s0, 2);
            s1 += __shfl_xor_sync(0xffffffffu, s1, 1);
            s1 += __shfl_xor_sync(0xffffffffu, s1, 2);
            l0 = l0 * al0 + s0;
            l1 = l1 * al1 + s1;
#pragma unroll
            for (int f = 0; f < 16; f++) {
                o[f][0] *= al0; o[f][1] *= al0;
                o[f][2] *= al1; o[f][3] *= al1;
            }

            u32 ph[4][4], pl[4][4];
#pragma unroll
            for (int j = 0; j < 4; j++) {
                ph[j][0] = split_pack(s[2 * j][0], s[2 * j][1], pl[j][0]);
                ph[j][1] = split_pack(s[2 * j][2], s[2 * j][3], pl[j][1]);
                ph[j][2] = split_pack(s[2 * j + 1][0], s[2 * j + 1][1], pl[j][2]);
                ph[j][3] = split_pack(s[2 * j + 1][2], s[2 * j + 1][3], pl[j][3]);
            }

            // PV (fp16x3), ep-pair term-major
#pragma unroll
            for (int j = 0; j < 4; j++) {
#pragma unroll
                for (int epp = 0; epp < 4; epp++) {
                    u32 vh[2][4], vl[2][4];
#pragma unroll
                    for (int e2 = 0; e2 < 2; e2++) {
                        const int ep = epp * 2 + e2;
                        u32 va = stg + AVHI + (u32)(j * 16 + vRow) * 256u + (((u32)(ep * 32) + vColT) ^ kSw);
                        ldsm4t(vh[e2], va);
                        ldsm4t(vl[e2], va + 16384);
                    }
                    mma16816(o[4 * epp + 0], ph[j], &vh[0][0]);
                    mma16816(o[4 * epp + 1], ph[j], &vh[0][2]);
                    mma16816(o[4 * epp + 2], ph[j], &vh[1][0]);
                    mma16816(o[4 * epp + 3], ph[j], &vh[1][2]);
                    mma16816(o[4 * epp + 0], ph[j], &vl[0][0]);
                    mma16816(o[4 * epp + 1], ph[j], &vl[0][2]);
                    mma16816(o[4 * epp + 2], ph[j], &vl[1][0]);
                    mma16816(o[4 * epp + 3], ph[j], &vl[1][2]);
                    mma16816(o[4 * epp + 0], pl[j], &vh[0][0]);
                    mma16816(o[4 * epp + 1], pl[j], &vh[0][2]);
                    mma16816(o[4 * epp + 2], pl[j], &vh[1][0]);
                    mma16816(o[4 * epp + 3], pl[j], &vh[1][2]);
                }
            }
        }
        __syncthreads();
    }

    const float inv0 = 1.0f / l0, inv1 = 1.0f / l1;
    const int srow0 = qg0 + wid * 16 + (lane >> 2);
    const size_t ro0 = ((size_t)b * S_ + srow0) * F_ + h * HD_;
    const size_t ro1 = ro0 + (size_t)8 * F_;
#pragma unroll
    for (int f = 0; f < 16; f++) {
        const int e = f * 8 + (lane & 3) * 2;
        u32 lo0, lo1;
        u32 hi0 = split_pack(o[f][0] * inv0, o[f][1] * inv0, lo0);
        u32 hi1 = split_pack(o[f][2] * inv1, o[f][3] * inv1, lo1);
        *(u32*)(g_AThi + ro0 + e) = hi0;
        *(u32*)(g_ATlo + ro0 + e) = lo0;
        *(u32*)(g_AThi + ro1 + e) = hi1;
        *(u32*)(g_ATlo + ro1 + e) = lo1;
    }
}

// ---------------------------------------------------------------------------
extern "C" void kernel_launch(void* const* d_in, const int* in_sizes, int n_in,
                              void* d_out, int out_size)
{
    const float* hs = (const float*)d_in[0];
    const float* cs = (const float*)d_in[1];
    const float* sn = (const float*)d_in[2];
    const float* wq = (const float*)d_in[3];
    const float* wo = (const float*)d_in[4];
    float* out = (float*)d_out;

    cudaFuncSetAttribute(mma_gemm_kernel<0>, cudaFuncAttributeMaxDynamicSharedMemorySize, MMA_SMEM_BYTES);
    cudaFuncSetAttribute(mma_gemm_kernel<1>, cudaFuncAttributeMaxDynamicSharedMemorySize, MMA_SMEM_BYTES);
    cudaFuncSetAttribute(attn_mma_kernel, cudaFuncAttributeMaxDynamicSharedMemorySize, ATT_SMEM_BYTES);

    __half *ahi, *alo, *whi, *wohi, *athi, *atlo;
    cudaGetSymbolAddress((void**)&ahi, g_Ahi);   cudaGetSymbolAddress((void**)&alo, g_Alo);
    cudaGetSymbolAddress((void**)&whi, g_Whi);
    cudaGetSymbolAddress((void**)&wohi, g_Wohi);
    cudaGetSymbolAddress((void**)&athi, g_AThi); cudaGetSymbolAddress((void**)&atlo, g_ATlo);

    {
        int n4 = (M_ * D_) / 4;
        split_f16_kernel<<<(n4 + 255) / 256, 256>>>((const float4*)hs, (uint2*)ahi, (uint2*)alo, n4);
        n4 = (NQKV * D_) / 4;
        round_f16_kernel<<<(n4 + 255) / 256, 256>>>((const float4*)wq, (uint2*)whi, n4);
        n4 = (D_ * F_) / 4;
        round_f16_kernel<<<(n4 + 255) / 256, 256>>>((const float4*)wo, (uint2*)wohi, n4);
    }

    // QKV projection (fp16x2 HMMA) + RoPE -> Q/K/V f16 hi/lo
    mma_gemm_kernel<0><<<dim3(NQKV / 128, M_ / 128), 256, MMA_SMEM_BYTES>>>(
        ahi, alo, whi, cs, sn, nullptr);

    // Causal flash attention (fp16x3 HMMA) -> g_AThi/g_ATlo
    attn_mma_kernel<<<dim3(S_ / 128, H_, B_), 256, ATT_SMEM_BYTES>>>();

    // Output projection (fp16x2 HMMA) -> d_out
    mma_gemm_kernel<1><<<dim3(D_ / 128, M_ / 128), 256, MMA_SMEM_BYTES>>>(
        athi, atlo, wohi, nullptr, nullptr, out);
}

// round 10
// speedup vs baseline: 1.3677x; 1.0541x over previous
#include <cuda_runtime.h>
#include <cuda_fp16.h>
#include <cstdint>
#include <math.h>

// Problem constants
#define B_   2
#define S_   2048
#define D_   2048
#define H_   16
#define HD_  128
#define M_   (B_ * S_)     // 4096
#define F_   (H_ * HD_)    // 2048
#define NQKV (3 * F_)      // 6144

typedef unsigned long long u64;
typedef unsigned int u32;

__device__ __forceinline__ u32 smem_u32(const void* p) {
    u32 a; asm("{ .reg .u64 t; cvta.to.shared.u64 t, %1; cvt.u32.u64 %0, t; }" : "=r"(a) : "l"(p));
    return a;
}

// ---- mma.sync / ldmatrix / cp.async ----
__device__ __forceinline__ void ldsm4(u32* r, u32 addr) {
    asm volatile("ldmatrix.sync.aligned.m8n8.x4.shared.b16 {%0,%1,%2,%3}, [%4];"
        : "=r"(r[0]), "=r"(r[1]), "=r"(r[2]), "=r"(r[3]) : "r"(addr));
}
__device__ __forceinline__ void ldsm4t(u32* r, u32 addr) {
    asm volatile("ldmatrix.sync.aligned.m8n8.x4.trans.shared.b16 {%0,%1,%2,%3}, [%4];"
        : "=r"(r[0]), "=r"(r[1]), "=r"(r[2]), "=r"(r[3]) : "r"(addr));
}
__device__ __forceinline__ void mma16816(float* d, const u32* a, const u32* b) {
    asm volatile("mma.sync.aligned.m16n8k16.row.col.f32.f16.f16.f32 "
        "{%0,%1,%2,%3}, {%4,%5,%6,%7}, {%8,%9}, {%0,%1,%2,%3};"
        : "+f"(d[0]), "+f"(d[1]), "+f"(d[2]), "+f"(d[3])
        : "r"(a[0]), "r"(a[1]), "r"(a[2]), "r"(a[3]), "r"(b[0]), "r"(b[1]));
}
__device__ __forceinline__ void cp_async16(u32 dst, const void* src) {
    asm volatile("cp.async.cg.shared.global [%0], [%1], 16;" :: "r"(dst), "l"(src));
}
#define CP_COMMIT() asm volatile("cp.async.commit_group;" ::: "memory")
#define CP_WAIT0()  asm volatile("cp.async.wait_group 0;" ::: "memory")
#define CP_WAIT1()  asm volatile("cp.async.wait_group 1;" ::: "memory")

// split f32 pair -> packed f16x2 hi (returned) and lo (out-param)
__device__ __forceinline__ u32 split_pack(float x, float y, u32& lo) {
    float hx = __half2float(__float2half_rn(x));
    float hy = __half2float(__float2half_rn(y));
    u32 hi;
    asm("cvt.rn.f16x2.f32 %0, %1, %2;" : "=r"(hi) : "f"(hy), "f"(hx));
    asm("cvt.rn.f16x2.f32 %0, %1, %2;" : "=r"(lo) : "f"(y - hy), "f"(x - hx));
    return hi;
}
// round f32 pair -> packed f16x2 (hi only)
__device__ __forceinline__ u32 round_pack(float x, float y) {
    u32 hi;
    asm("cvt.rn.f16x2.f32 %0, %1, %2;" : "=r"(hi) : "f"(y), "f"(x));
    return hi;
}

// ---------------- device scratch ----------------
__device__ __half g_Qhi[(size_t)B_ * H_ * S_ * HD_], g_Qlo[(size_t)B_ * H_ * S_ * HD_];
__device__ __half g_Khi[(size_t)B_ * H_ * S_ * HD_], g_Klo[(size_t)B_ * H_ * S_ * HD_];
__device__ __half g_Vhi[(size_t)B_ * H_ * S_ * HD_], g_Vlo[(size_t)B_ * H_ * S_ * HD_];
__device__ __half g_Ahi[(size_t)M_ * D_],   g_Alo[(size_t)M_ * D_];
__device__ __half g_Whi[(size_t)NQKV * D_];
__device__ __half g_Wohi[(size_t)D_ * F_];
__device__ __half g_AThi[(size_t)M_ * F_],  g_ATlo[(size_t)M_ * F_];

// ---------------------------------------------------------------------------
// Split fp32 -> fp16 (hi, lo) ; and hi-only variant for weights
// ---------------------------------------------------------------------------
__global__ void split_f16_kernel(const float4* __restrict__ x,
                                 uint2* __restrict__ hi, uint2* __restrict__ lo, int n4)
{
    int i = blockIdx.x * blockDim.x + threadIdx.x;
    if (i >= n4) return;
    float4 v = x[i];
    u32 l0, l1, h0, h1;
    h0 = split_pack(v.x, v.y, l0);
    h1 = split_pack(v.z, v.w, l1);
    hi[i] = make_uint2(h0, h1);
    lo[i] = make_uint2(l0, l1);
}
__global__ void round_f16_kernel(const float4* __restrict__ x,
                                 uint2* __restrict__ hi, int n4)
{
    int i = blockIdx.x * blockDim.x + threadIdx.x;
    if (i >= n4) return;
    float4 v = x[i];
    hi[i] = make_uint2(round_pack(v.x, v.y), round_pack(v.z, v.w));
}

// ---------------------------------------------------------------------------
// fp16x2 GEMM (2 products: ahi*bhi + alo*bhi). Tile 128x128, K chunks of 64.
// 8 warps (2m x 4n), warp tile 64x32, term-major (RAW distance 16).
// 2-stage pipeline, 96KB -> 2 CTAs/SM (independent CTAs fill drain bubbles).
// MODE 0: QKV + RoPE -> Q/K/V f16 hi/lo.  MODE 1: out proj -> fp32 out.
// ---------------------------------------------------------------------------
#define NCHUNK 32
#define TILEB 16384
#define STAGEB (3 * TILEB)                 // 48KB
#define MMA_SMEM_BYTES (2 * STAGEB)        // 96KB -> occ 2

__device__ __forceinline__ u32 swz(u32 row, u32 cb) {
    return row * 128u + (cb ^ ((row & 7u) << 4));
}

template <int MODE>
__global__ void __launch_bounds__(256, 2) mma_gemm_kernel(
    const __half* __restrict__ Ahi, const __half* __restrict__ Alo,
    const __half* __restrict__ Bhi,
    const float* __restrict__ cs, const float* __restrict__ sn,
    float* __restrict__ out)
{
    extern __shared__ char dyn_smem[];
    const u32 smb = smem_u32(dyn_smem);

    const int tid = threadIdx.x;
    const int wid = tid >> 5;
    const int lane = tid & 31;
    const int wm = wid >> 2, wn = wid & 3;
    const int m0 = blockIdx.y << 7;
    const int n0 = blockIdx.x << 7;

    const __half* srcOp[3] = {Ahi, Alo, Bhi};
    const int rowOff[3] = {m0, m0, n0};

    auto load_chunk = [&](int st, int k0) {
        const u32 sb = smb + (u32)st * STAGEB;
#pragma unroll
        for (int op = 0; op < 3; op++) {
#pragma unroll
            for (int rep = 0; rep < 4; rep++) {
                int lin = rep * 256 + tid;
                int row = lin >> 3, u = lin & 7;
                cp_async16(sb + op * TILEB + swz(row, u * 16),
                           srcOp[op] + (size_t)(rowOff[op] + row) * 2048 + k0 + u * 8);
            }
        }
    };

    load_chunk(0, 0);  CP_COMMIT();
    load_chunk(1, 64); CP_COMMIT();

    const u32 aRow = (u32)(wm * 64 + (lane & 15));
    const u32 aSw = (aRow & 7u) << 4;
    const u32 aColSel = (u32)((lane >> 4) << 4);
    u32 aOff[4];
#pragma unroll
    for (int fm = 0; fm < 4; fm++) aOff[fm] = (aRow + fm * 16) * 128u;

    u32 bOff[2], bSw[2];
#pragma unroll
    for (int p = 0; p < 2; p++) {
        u32 brow = (u32)(wn * 32 + p * 16 + ((lane >> 4) << 3) + (lane & 7));
        bOff[p] = brow * 128u;
        bSw[p] = (brow & 7u) << 4;
    }
    const u32 bColSel = (u32)(((lane >> 3) & 1) << 4);

    float acc[4][4][4];
#pragma unroll
    for (int i = 0; i < 4; i++)
#pragma unroll
        for (int j = 0; j < 4; j++)
#pragma unroll
            for (int q = 0; q < 4; q++) acc[i][j][q] = 0.f;

    for (int c = 0; c < NCHUNK; c++) {
        // wait for chunk c (newer pending: chunk c+1 if it exists)
        if (c + 1 < NCHUNK) { CP_WAIT1(); } else { CP_WAIT0(); }
        __syncthreads();
        const u32 stage = smb + (u32)(c & 1) * STAGEB;
#pragma unroll
        for (int ks = 0; ks < 4; ks++) {
            const u32 cbA = (u32)(ks * 32) + aColSel;
            const u32 cbB = (u32)(ks * 32) + bColSel;
            u32 ah[4][4], al[4][4], bh[2][4];
#pragma unroll
            for (int fm = 0; fm < 4; fm++) {
                ldsm4(ah[fm], stage + aOff[fm] + (cbA ^ aSw));
                ldsm4(al[fm], stage + TILEB + aOff[fm] + (cbA ^ aSw));
            }
#pragma unroll
            for (int p = 0; p < 2; p++)
                ldsm4(bh[p], stage + 2 * TILEB + bOff[p] + (cbB ^ bSw[p]));
            // term-major: 16 MMAs per term -> same-acc distance 16
#pragma unroll
            for (int fm = 0; fm < 4; fm++)
#pragma unroll
                for (int p = 0; p < 2; p++)
#pragma unroll
                    for (int q = 0; q < 2; q++)
                        mma16816(acc[fm][p * 2 + q], ah[fm], &bh[p][q * 2]);
#pragma unroll
            for (int fm = 0; fm < 4; fm++)
#pragma unroll
                for (int p = 0; p < 2; p++)
#pragma unroll
                    for (int q = 0; q < 2; q++)
                        mma16816(acc[fm][p * 2 + q], al[fm], &bh[p][q * 2]);
        }
        __syncthreads();            // all warps done reading stage c&1
        if (c + 2 < NCHUNK) {
            load_chunk(c & 1, (c + 2) * 64);
            CP_COMMIT();
        }
    }

    // epilogue: accum -> smem fp32 (pitch 132), then scatter
    float* S = (float*)dyn_smem;
    const int er = lane >> 2, ec = (lane & 3) << 1;
#pragma unroll
    for (int fm = 0; fm < 4; fm++)
#pragma unroll
        for (int fn = 0; fn < 4; fn++) {
            const int r0 = wm * 64 + fm * 16 + er;
            const int c0 = wn * 32 + fn * 8 + ec;
            S[r0 * 132 + c0] = acc[fm][fn][0];
            S[r0 * 132 + c0 + 1] = acc[fm][fn][1];
            S[(r0 + 8) * 132 + c0] = acc[fm][fn][2];
            S[(r0 + 8) * 132 + c0 + 1] = acc[fm][fn][3];
        }
    __syncthreads();

    const int r = tid >> 1, t2 = tid & 1;
    const int m = m0 + r;
    if (MODE == 0) {
        const int h = n0 / 384;
        const int sub = (n0 % 384) >> 7;          // 0=q,1=k,2=v
        const int b = m >> 11, s = m & 2047;
        const size_t doff = ((size_t)(b * H_ + h) * S_ + s) * HD_;
        if (sub == 2) {
            const int cb = t2 * 64;
#pragma unroll
            for (int g = 0; g < 8; g++) {
                u32 hw[4], lw[4];
#pragma unroll
                for (int p = 0; p < 4; p++) {
                    float x = S[r * 132 + cb + g * 8 + p * 2];
                    float y = S[r * 132 + cb + g * 8 + p * 2 + 1];
                    hw[p] = split_pack(x, y, lw[p]);
                }
                *(uint4*)(g_Vhi + doff + cb + g * 8) = make_uint4(hw[0], hw[1], hw[2], hw[3]);
                *(uint4*)(g_Vlo + doff + cb + g * 8) = make_uint4(lw[0], lw[1], lw[2], lw[3]);
            }
        } else {
            const float scl = (sub == 0) ? 0.08838834764831845f : 1.0f;
            __half* dhi = (sub == 0) ? g_Qhi : g_Khi;
            __half* dlo = (sub == 0) ? g_Qlo : g_Klo;
            const float* crow = cs + (size_t)s * HD_;
            const float* srow = sn + (size_t)s * HD_;
#pragma unroll
            for (int g = 0; g < 4; g++) {
                const int cA = t2 * 32 + g * 8;
                const int cB = cA + 64;
                u32 hA[4], lA[4], hB[4], lB[4];
#pragma unroll
                for (int p = 0; p < 4; p++) {
                    const int c0 = cA + p * 2, c1 = cA + p * 2 + 1;
                    float xa0 = S[r * 132 + c0], xa1 = S[r * 132 + c1];
                    float xb0 = S[r * 132 + c0 + 64], xb1 = S[r * 132 + c1 + 64];
                    float oa0 = (xa0 * crow[c0] - xb0 * srow[c0]) * scl;
                    float oa1 = (xa1 * crow[c1] - xb1 * srow[c1]) * scl;
                    float ob0 = (xb0 * crow[c0 + 64] + xa0 * srow[c0 + 64]) * scl;
                    float ob1 = (xb1 * crow[c1 + 64] + xa1 * srow[c1 + 64]) * scl;
                    hA[p] = split_pack(oa0, oa1, lA[p]);
                    hB[p] = split_pack(ob0, ob1, lB[p]);
                }
                *(uint4*)(dhi + doff + cA) = make_uint4(hA[0], hA[1], hA[2], hA[3]);
                *(uint4*)(dlo + doff + cA) = make_uint4(lA[0], lA[1], lA[2], lA[3]);
                *(uint4*)(dhi + doff + cB) = make_uint4(hB[0], hB[1], hB[2], hB[3]);
                *(uint4*)(dlo + doff + cB) = make_uint4(lB[0], lB[1], lB[2], lB[3]);
            }
        }
    } else {
        float* dst = out + (size_t)m * D_ + n0;
        const int cbase = t2 * 64;
#pragma unroll
        for (int q4 = 0; q4 < 16; q4++) {
            float4 w = *(const float4*)(S + r * 132 + cbase + q4 * 4);
            *(float4*)(dst + cbase + q4 * 4) = w;
        }
    }
}

// ---------------------------------------------------------------------------
// Tensor-core causal flash attention (fp16x3, unchanged from R9).
// ---------------------------------------------------------------------------
#define ATT_SMEM_BYTES (192 * 1024)
#define AQLO 32768
#define ASTG 65536
#define AKLO 16384
#define AVHI 32768
#define AVLO 49152

__device__ __forceinline__ u32 aswz(u32 row, u32 cb) {
    return row * 256u + (cb ^ ((row & 7u) << 4));
}

__global__ void __launch_bounds__(256, 1) attn_mma_kernel()
{
    extern __shared__ char dyn_smem[];
    const u32 smb = smem_u32(dyn_smem);
    const int tid = threadIdx.x, wid = tid >> 5, lane = tid & 31;
    const int qt = blockIdx.x, h = blockIdx.y, b = blockIdx.z;
    const int qg0 = qt << 7;
    const size_t bh = (size_t)(b * H_ + h) * S_;

    {
        const __half* qh = g_Qhi + (bh + qg0) * HD_;
        const __half* ql = g_Qlo + (bh + qg0) * HD_;
#pragma unroll
        for (int rep = 0; rep < 8; rep++) {
            int lin = rep * 256 + tid;
            int row = lin >> 4, u = lin & 15;
            u32 so = aswz(row, u * 16);
            cp_async16(smb + so, qh + (size_t)row * HD_ + u * 8);
            cp_async16(smb + AQLO + so, ql + (size_t)row * HD_ + u * 8);
        }
        CP_COMMIT();
    }

    const __half* khg = g_Khi + bh * HD_;
    const __half* klg = g_Klo + bh * HD_;
    const __half* vhg = g_Vhi + bh * HD_;
    const __half* vlg = g_Vlo + bh * HD_;

    auto load_stage = [&](int st, int kg0) {
        const u32 dst = smb + ASTG + (u32)st * ASTG;
        const __half* srcs[4] = {khg + (size_t)kg0 * HD_, klg + (size_t)kg0 * HD_,
                                 vhg + (size_t)kg0 * HD_, vlg + (size_t)kg0 * HD_};
#pragma unroll
        for (int op = 0; op < 4; op++) {
#pragma unroll
            for (int rep = 0; rep < 4; rep++) {
                int lin = rep * 256 + tid;
                int row = lin >> 4, u = lin & 15;
                cp_async16(dst + op * 16384 + aswz(row, u * 16),
                           srcs[op] + (size_t)row * HD_ + u * 8);
            }
        }
    };

    const int nkt = 2 * qt + 2;
    load_stage(0, 0);
    CP_COMMIT();

    const u32 aRow = (u32)(wid * 16 + (lane & 15));
    const u32 aSw = (aRow & 7u) << 4;
    const u32 aCol = (u32)((lane >> 4) << 4);
    const u32 aBase = aRow * 256u;
    const u32 kRow = (u32)(((lane >> 4) << 3) + (lane & 7));
    const u32 kSw = (u32)((lane & 7) << 4);
    const u32 kColT = (u32)(((lane >> 3) & 1) << 4);
    const u32 vRow = (u32)(lane & 15);
    const u32 vColT = (u32)((lane >> 4) << 4);

    u32 qhf[8][4], qlf[8][4];
    float o[16][4];
#pragma unroll
    for (int f = 0; f < 16; f++)
#pragma unroll
        for (int q = 0; q < 4; q++) o[f][q] = 0.f;
    float m0r = -1e30f, m1r = -1e30f, l0 = 0.f, l1 = 0.f;

    for (int kt = 0; kt < nkt; kt++) {
        if (kt + 1 < nkt) {
            load_stage((kt + 1) & 1, (kt + 1) * 64);
            CP_COMMIT();
            CP_WAIT1();
        } else {
            CP_WAIT0();
        }
        __syncthreads();
        if (kt == 0) {
#pragma unroll
            for (int ks = 0; ks < 8; ks++) {
                u32 qa = smb + aBase + (((u32)(ks * 32) + aCol) ^ aSw);
                ldsm4(qhf[ks], qa);
                ldsm4(qlf[ks], qa + AQLO);
            }
        }
        const int kg0 = kt * 64;
        const bool skip = kg0 > qg0 + wid * 16 + 15;
        if (!skip) {
            const u32 stg = smb + ASTG + (u32)(kt & 1) * ASTG;
            float s[8][4];
#pragma unroll
            for (int f = 0; f < 8; f++)
#pragma unroll
                for (int q = 0; q < 4; q++) s[f][q] = 0.f;

            // QK^T (fp16x3), term-major per ks
#pragma unroll
            for (int ks = 0; ks < 8; ks++) {
                u32 kh[4][4], kl[4][4];
#pragma unroll
                for (int p = 0; p < 4; p++) {
                    u32 addr = stg + (u32)(p * 16 + kRow) * 256u + (((u32)(ks * 32) + kColT) ^ kSw);
                    ldsm4(kh[p], addr);
                    ldsm4(kl[p], addr + AKLO);
                }
#pragma unroll
                for (int p = 0; p < 4; p++) {
                    mma16816(s[2 * p], qhf[ks], &kh[p][0]);
                    mma16816(s[2 * p + 1], qhf[ks], &kh[p][2]);
                }
#pragma unroll
                for (int p = 0; p < 4; p++) {
                    mma16816(s[2 * p], qhf[ks], &kl[p][0]);
                    mma16816(s[2 * p + 1], qhf[ks], &kl[p][2]);
                }
#pragma unroll
                for (int p = 0; p < 4; p++) {
                    mma16816(s[2 * p], qlf[ks], &kh[p][0]);
                    mma16816(s[2 * p + 1], qlf[ks], &kh[p][2]);
                }
            }

            const int row0 = qg0 + wid * 16 + (lane >> 2);
            if (kg0 + 63 > qg0 + wid * 16) {
#pragma unroll
                for (int f = 0; f < 8; f++) {
                    const int col = kg0 + f * 8 + (lane & 3) * 2;
                    if (col > row0)     s[f][0] = -1e30f;
                    if (col + 1 > row0) s[f][1] = -1e30f;
                    if (col > row0 + 8)     s[f][2] = -1e30f;
                    if (col + 1 > row0 + 8) s[f][3] = -1e30f;
                }
            }

            float mx0 = -1e30f, mx1 = -1e30f;
#pragma unroll
            for (int f = 0; f < 8; f++) {
                mx0 = fmaxf(mx0, fmaxf(s[f][0], s[f][1]));
                mx1 = fmaxf(mx1, fmaxf(s[f][2], s[f][3]));
            }
            mx0 = fmaxf(mx0, __shfl_xor_sync(0xffffffffu, mx0, 1));
            mx0 = fmaxf(mx0, __shfl_xor_sync(0xffffffffu, mx0, 2));
            mx1 = fmaxf(mx1, __shfl_xor_sync(0xffffffffu, mx1, 1));
            mx1 = fmaxf(mx1, __shfl_xor_sync(0xffffffffu, mx1, 2));
            const float mn0 = fmaxf(m0r, mx0), mn1 = fmaxf(m1r, mx1);
            const float al0 = __expf(m0r - mn0), al1 = __expf(m1r - mn1);
            m0r = mn0; m1r = mn1;
            float s0 = 0.f, s1 = 0.f;
#pragma unroll
            for (int f = 0; f < 8; f++) {
                s[f][0] = __expf(s[f][0] - mn0);
                s[f][1] = __expf(s[f][1] - mn0);
                s[f][2] = __expf(s[f][2] - mn1);
                s[f][3] = __expf(s[f][3] - mn1);
                s0 += s[f][0] + s[f][1];
                s1 += s[f][2] + s[f][3];
            }
            s0 += __shfl_xor_sync(0xffffffffu, s0, 1);
            s0 += __shfl_xor_sync(0xffffffffu, s0, 2);
            s1 += __shfl_xor_sync(0xffffffffu, s1, 1);
            s1 += __shfl_xor_sync(0xffffffffu, s1, 2);
            l0 = l0 * al0 + s0;
            l1 = l1 * al1 + s1;
#pragma unroll
            for (int f = 0; f < 16; f++) {
                o[f][0] *= al0; o[f][1] *= al0;
                o[f][2] *= al1; o[f][3] *= al1;
            }

            u32 ph[4][4], pl[4][4];
#pragma unroll
            for (int j = 0; j < 4; j++) {
                ph[j][0] = split_pack(s[2 * j][0], s[2 * j][1], pl[j][0]);
                ph[j][1] = split_pack(s[2 * j][2], s[2 * j][3], pl[j][1]);
                ph[j][2] = split_pack(s[2 * j + 1][0], s[2 * j + 1][1], pl[j][2]);
                ph[j][3] = split_pack(s[2 * j + 1][2], s[2 * j + 1][3], pl[j][3]);
            }

            // PV (fp16x3), ep-pair term-major
#pragma unroll
            for (int j = 0; j < 4; j++) {
#pragma unroll
                for (int epp = 0; epp < 4; epp++) {
                    u32 vh[2][4], vl[2][4];
#pragma unroll
                    for (int e2 = 0; e2 < 2; e2++) {
                        const int ep = epp * 2 + e2;
                        u32 va = stg + AVHI + (u32)(j * 16 + vRow) * 256u + (((u32)(ep * 32) + vColT) ^ kSw);
                        ldsm4t(vh[e2], va);
                        ldsm4t(vl[e2], va + 16384);
                    }
                    mma16816(o[4 * epp + 0], ph[j], &vh[0][0]);
                    mma16816(o[4 * epp + 1], ph[j], &vh[0][2]);
                    mma16816(o[4 * epp + 2], ph[j], &vh[1][0]);
                    mma16816(o[4 * epp + 3], ph[j], &vh[1][2]);
                    mma16816(o[4 * epp + 0], ph[j], &vl[0][0]);
                    mma16816(o[4 * epp + 1], ph[j], &vl[0][2]);
                    mma16816(o[4 * epp + 2], ph[j], &vl[1][0]);
                    mma16816(o[4 * epp + 3], ph[j], &vl[1][2]);
                    mma16816(o[4 * epp + 0], pl[j], &vh[0][0]);
                    mma16816(o[4 * epp + 1], pl[j], &vh[0][2]);
                    mma16816(o[4 * epp + 2], pl[j], &vh[1][0]);
                    mma16816(o[4 * epp + 3], pl[j], &vh[1][2]);
                }
            }
        }
        __syncthreads();
    }

    const float inv0 = 1.0f / l0, inv1 = 1.0f / l1;
    const int srow0 = qg0 + wid * 16 + (lane >> 2);
    const size_t ro0 = ((size_t)b * S_ + srow0) * F_ + h * HD_;
    const size_t ro1 = ro0 + (size_t)8 * F_;
#pragma unroll
    for (int f = 0; f < 16; f++) {
        const int e = f * 8 + (lane & 3) * 2;
        u32 lo0, lo1;
        u32 hi0 = split_pack(o[f][0] * inv0, o[f][1] * inv0, lo0);
        u32 hi1 = split_pack(o[f][2] * inv1, o[f][3] * inv1, lo1);
        *(u32*)(g_AThi + ro0 + e) = hi0;
        *(u32*)(g_ATlo + ro0 + e) = lo0;
        *(u32*)(g_AThi + ro1 + e) = hi1;
        *(u32*)(g_ATlo + ro1 + e) = lo1;
    }
}

// ---------------------------------------------------------------------------
extern "C" void kernel_launch(void* const* d_in, const int* in_sizes, int n_in,
                              void* d_out, int out_size)
{
    const float* hs = (const float*)d_in[0];
    const float* cs = (const float*)d_in[1];
    const float* sn = (const float*)d_in[2];
    const float* wq = (const float*)d_in[3];
    const float* wo = (const float*)d_in[4];
    float* out = (float*)d_out;

    cudaFuncSetAttribute(mma_gemm_kernel<0>, cudaFuncAttributeMaxDynamicSharedMemorySize, MMA_SMEM_BYTES);
    cudaFuncSetAttribute(mma_gemm_kernel<1>, cudaFuncAttributeMaxDynamicSharedMemorySize, MMA_SMEM_BYTES);
    cudaFuncSetAttribute(attn_mma_kernel, cudaFuncAttributeMaxDynamicSharedMemorySize, ATT_SMEM_BYTES);

    __half *ahi, *alo, *whi, *wohi, *athi, *atlo;
    cudaGetSymbolAddress((void**)&ahi, g_Ahi);   cudaGetSymbolAddress((void**)&alo, g_Alo);
    cudaGetSymbolAddress((void**)&whi, g_Whi);
    cudaGetSymbolAddress((void**)&wohi, g_Wohi);
    cudaGetSymbolAddress((void**)&athi, g_AThi); cudaGetSymbolAddress((void**)&atlo, g_ATlo);

    {
        int n4 = (M_ * D_) / 4;
        split_f16_kernel<<<(n4 + 255) / 256, 256>>>((const float4*)hs, (uint2*)ahi, (uint2*)alo, n4);
        n4 = (NQKV * D_) / 4;
        round_f16_kernel<<<(n4 + 255) / 256, 256>>>((const float4*)wq, (uint2*)whi, n4);
        n4 = (D_ * F_) / 4;
        round_f16_kernel<<<(n4 + 255) / 256, 256>>>((const float4*)wo, (uint2*)wohi, n4);
    }

    // QKV projection (fp16x2 HMMA) + RoPE -> Q/K/V f16 hi/lo
    mma_gemm_kernel<0><<<dim3(NQKV / 128, M_ / 128), 256, MMA_SMEM_BYTES>>>(
        ahi, alo, whi, cs, sn, nullptr);

    // Causal flash attention (fp16x3 HMMA) -> g_AThi/g_ATlo
    attn_mma_kernel<<<dim3(S_ / 128, H_, B_), 256, ATT_SMEM_BYTES>>>();

    // Output projection (fp16x2 HMMA) -> d_out
    mma_gemm_kernel<1><<<dim3(D_ / 128, M_ / 128), 256, MMA_SMEM_BYTES>>>(
        athi, atlo, wohi, nullptr, nullptr, out);
}

// round 11
// speedup vs baseline: 1.5338x; 1.1214x over previous
#include <cuda_runtime.h>
#include <cuda_fp16.h>
#include <cstdint>
#include <math.h>

// Problem constants
#define B_   2
#define S_   2048
#define D_   2048
#define H_   16
#define HD_  128
#define M_   (B_ * S_)     // 4096
#define F_   (H_ * HD_)    // 2048
#define NQKV (3 * F_)      // 6144

typedef unsigned long long u64;
typedef unsigned int u32;

__device__ __forceinline__ u32 smem_u32(const void* p) {
    u32 a; asm("{ .reg .u64 t; cvta.to.shared.u64 t, %1; cvt.u32.u64 %0, t; }" : "=r"(a) : "l"(p));
    return a;
}

// ---- mma.sync / ldmatrix / cp.async ----
__device__ __forceinline__ void ldsm4(u32* r, u32 addr) {
    asm volatile("ldmatrix.sync.aligned.m8n8.x4.shared.b16 {%0,%1,%2,%3}, [%4];"
        : "=r"(r[0]), "=r"(r[1]), "=r"(r[2]), "=r"(r[3]) : "r"(addr));
}
__device__ __forceinline__ void ldsm4t(u32* r, u32 addr) {
    asm volatile("ldmatrix.sync.aligned.m8n8.x4.trans.shared.b16 {%0,%1,%2,%3}, [%4];"
        : "=r"(r[0]), "=r"(r[1]), "=r"(r[2]), "=r"(r[3]) : "r"(addr));
}
__device__ __forceinline__ void mma16816(float* d, const u32* a, const u32* b) {
    asm volatile("mma.sync.aligned.m16n8k16.row.col.f32.f16.f16.f32 "
        "{%0,%1,%2,%3}, {%4,%5,%6,%7}, {%8,%9}, {%0,%1,%2,%3};"
        : "+f"(d[0]), "+f"(d[1]), "+f"(d[2]), "+f"(d[3])
        : "r"(a[0]), "r"(a[1]), "r"(a[2]), "r"(a[3]), "r"(b[0]), "r"(b[1]));
}
__device__ __forceinline__ void cp_async16(u32 dst, const void* src) {
    asm volatile("cp.async.cg.shared.global [%0], [%1], 16;" :: "r"(dst), "l"(src));
}
#define CP_COMMIT() asm volatile("cp.async.commit_group;" ::: "memory")
#define CP_WAIT0()  asm volatile("cp.async.wait_group 0;" ::: "memory")
#define CP_WAIT1()  asm volatile("cp.async.wait_group 1;" ::: "memory")

// split f32 pair -> packed f16x2 hi (returned) and lo (out-param)
__device__ __forceinline__ u32 split_pack(float x, float y, u32& lo) {
    float hx = __half2float(__float2half_rn(x));
    float hy = __half2float(__float2half_rn(y));
    u32 hi;
    asm("cvt.rn.f16x2.f32 %0, %1, %2;" : "=r"(hi) : "f"(hy), "f"(hx));
    asm("cvt.rn.f16x2.f32 %0, %1, %2;" : "=r"(lo) : "f"(y - hy), "f"(x - hx));
    return hi;
}
// round f32 pair -> packed f16x2 (hi only)
__device__ __forceinline__ u32 round_pack(float x, float y) {
    u32 hi;
    asm("cvt.rn.f16x2.f32 %0, %1, %2;" : "=r"(hi) : "f"(y), "f"(x));
    return hi;
}

// ---------------- device scratch ----------------
__device__ __half g_Qhi[(size_t)B_ * H_ * S_ * HD_], g_Qlo[(size_t)B_ * H_ * S_ * HD_];
__device__ __half g_Khi[(size_t)B_ * H_ * S_ * HD_], g_Klo[(size_t)B_ * H_ * S_ * HD_];
__device__ __half g_Vhi[(size_t)B_ * H_ * S_ * HD_], g_Vlo[(size_t)B_ * H_ * S_ * HD_];
__device__ __half g_Ahi[(size_t)M_ * D_],   g_Alo[(size_t)M_ * D_];
__device__ __half g_Whi[(size_t)NQKV * D_];
__device__ __half g_Wohi[(size_t)D_ * F_];
__device__ __half g_AThi[(size_t)M_ * F_];

// ---------------------------------------------------------------------------
// Split fp32 -> fp16 (hi, lo) ; and hi-only variant for weights
// ---------------------------------------------------------------------------
__global__ void split_f16_kernel(const float4* __restrict__ x,
                                 uint2* __restrict__ hi, uint2* __restrict__ lo, int n4)
{
    int i = blockIdx.x * blockDim.x + threadIdx.x;
    if (i >= n4) return;
    float4 v = x[i];
    u32 l0, l1, h0, h1;
    h0 = split_pack(v.x, v.y, l0);
    h1 = split_pack(v.z, v.w, l1);
    hi[i] = make_uint2(h0, h1);
    lo[i] = make_uint2(l0, l1);
}
__global__ void round_f16_kernel(const float4* __restrict__ x,
                                 uint2* __restrict__ hi, int n4)
{
    int i = blockIdx.x * blockDim.x + threadIdx.x;
    if (i >= n4) return;
    float4 v = x[i];
    hi[i] = make_uint2(round_pack(v.x, v.y), round_pack(v.z, v.w));
}

// ---------------------------------------------------------------------------
// fp16 GEMM via mma.sync. Tile 128x128, K chunks of 64. 8 warps (2m x 4n),
// warp tile 64x32, term-major. 2-stage pipeline, 96KB -> 2 CTAs/SM.
// Products: Ahi*Bhi (+ Alo*Bhi when useAlo).
//   MODE 0 (QKV + RoPE): useAlo = (tile is q or k); V tiles single-product.
//   MODE 1 (out proj):   useAlo = false (attention output fp16-rounded).
// ---------------------------------------------------------------------------
#define NCHUNK 32
#define TILEB 16384
#define STAGEB (3 * TILEB)                 // 48KB
#define MMA_SMEM_BYTES (2 * STAGEB)        // 96KB -> occ 2

__device__ __forceinline__ u32 swz(u32 row, u32 cb) {
    return row * 128u + (cb ^ ((row & 7u) << 4));
}

template <int MODE>
__global__ void __launch_bounds__(256, 2) mma_gemm_kernel(
    const __half* __restrict__ Ahi, const __half* __restrict__ Alo,
    const __half* __restrict__ Bhi,
    const float* __restrict__ cs, const float* __restrict__ sn,
    float* __restrict__ out)
{
    extern __shared__ char dyn_smem[];
    const u32 smb = smem_u32(dyn_smem);

    const int tid = threadIdx.x;
    const int wid = tid >> 5;
    const int lane = tid & 31;
    const int wm = wid >> 2, wn = wid & 3;
    const int m0 = blockIdx.y << 7;
    const int n0 = blockIdx.x << 7;

    const int sub = (MODE == 0) ? ((n0 % 384) >> 7) : 3;   // 0=q,1=k,2=v
    const bool useAlo = (MODE == 0) && (sub != 2);

    auto load_chunk = [&](int st, int k0) {
        const u32 sb = smb + (u32)st * STAGEB;
#pragma unroll
        for (int rep = 0; rep < 4; rep++) {
            int lin = rep * 256 + tid;
            int row = lin >> 3, u = lin & 7;
            const u32 so = swz(row, u * 16);
            cp_async16(sb + so, Ahi + (size_t)(m0 + row) * 2048 + k0 + u * 8);
            if (useAlo)
                cp_async16(sb + TILEB + so, Alo + (size_t)(m0 + row) * 2048 + k0 + u * 8);
            cp_async16(sb + 2 * TILEB + so, Bhi + (size_t)(n0 + row) * 2048 + k0 + u * 8);
        }
    };

    load_chunk(0, 0);  CP_COMMIT();
    load_chunk(1, 64); CP_COMMIT();

    const u32 aRow = (u32)(wm * 64 + (lane & 15));
    const u32 aSw = (aRow & 7u) << 4;
    const u32 aColSel = (u32)((lane >> 4) << 4);
    u32 aOff[4];
#pragma unroll
    for (int fm = 0; fm < 4; fm++) aOff[fm] = (aRow + fm * 16) * 128u;

    u32 bOff[2], bSw[2];
#pragma unroll
    for (int p = 0; p < 2; p++) {
        u32 brow = (u32)(wn * 32 + p * 16 + ((lane >> 4) << 3) + (lane & 7));
        bOff[p] = brow * 128u;
        bSw[p] = (brow & 7u) << 4;
    }
    const u32 bColSel = (u32)(((lane >> 3) & 1) << 4);

    float acc[4][4][4];
#pragma unroll
    for (int i = 0; i < 4; i++)
#pragma unroll
        for (int j = 0; j < 4; j++)
#pragma unroll
            for (int q = 0; q < 4; q++) acc[i][j][q] = 0.f;

    for (int c = 0; c < NCHUNK; c++) {
        if (c + 1 < NCHUNK) { CP_WAIT1(); } else { CP_WAIT0(); }
        __syncthreads();
        const u32 stage = smb + (u32)(c & 1) * STAGEB;
#pragma unroll
        for (int ks = 0; ks < 4; ks++) {
            const u32 cbA = (u32)(ks * 32) + aColSel;
            const u32 cbB = (u32)(ks * 32) + bColSel;
            u32 ah[4][4], al[4][4], bh[2][4];
#pragma unroll
            for (int fm = 0; fm < 4; fm++)
                ldsm4(ah[fm], stage + aOff[fm] + (cbA ^ aSw));
            if (useAlo) {
#pragma unroll
                for (int fm = 0; fm < 4; fm++)
                    ldsm4(al[fm], stage + TILEB + aOff[fm] + (cbA ^ aSw));
            }
#pragma unroll
            for (int p = 0; p < 2; p++)
                ldsm4(bh[p], stage + 2 * TILEB + bOff[p] + (cbB ^ bSw[p]));
            // term-major: 16 MMAs per term -> same-acc distance 16
#pragma unroll
            for (int fm = 0; fm < 4; fm++)
#pragma unroll
                for (int p = 0; p < 2; p++)
#pragma unroll
                    for (int q = 0; q < 2; q++)
                        mma16816(acc[fm][p * 2 + q], ah[fm], &bh[p][q * 2]);
            if (useAlo) {
#pragma unroll
                for (int fm = 0; fm < 4; fm++)
#pragma unroll
                    for (int p = 0; p < 2; p++)
#pragma unroll
                        for (int q = 0; q < 2; q++)
                            mma16816(acc[fm][p * 2 + q], al[fm], &bh[p][q * 2]);
            }
        }
        __syncthreads();            // all warps done reading this stage
        if (c + 2 < NCHUNK) {
            load_chunk(c & 1, (c + 2) * 64);
            CP_COMMIT();
        }
    }

    // epilogue: accum -> smem fp32 (pitch 132), then scatter
    float* S = (float*)dyn_smem;
    const int er = lane >> 2, ec = (lane & 3) << 1;
#pragma unroll
    for (int fm = 0; fm < 4; fm++)
#pragma unroll
        for (int fn = 0; fn < 4; fn++) {
            const int r0 = wm * 64 + fm * 16 + er;
            const int c0 = wn * 32 + fn * 8 + ec;
            S[r0 * 132 + c0] = acc[fm][fn][0];
            S[r0 * 132 + c0 + 1] = acc[fm][fn][1];
            S[(r0 + 8) * 132 + c0] = acc[fm][fn][2];
            S[(r0 + 8) * 132 + c0 + 1] = acc[fm][fn][3];
        }
    __syncthreads();

    const int r = tid >> 1, t2 = tid & 1;
    const int m = m0 + r;
    if (MODE == 0) {
        const int h = n0 / 384;
        const int b = m >> 11, s = m & 2047;
        const size_t doff = ((size_t)(b * H_ + h) * S_ + s) * HD_;
        if (sub == 2) {
            const int cb = t2 * 64;
#pragma unroll
            for (int g = 0; g < 8; g++) {
                u32 hw[4], lw[4];
#pragma unroll
                for (int p = 0; p < 4; p++) {
                    float x = S[r * 132 + cb + g * 8 + p * 2];
                    float y = S[r * 132 + cb + g * 8 + p * 2 + 1];
                    hw[p] = split_pack(x, y, lw[p]);
                }
                *(uint4*)(g_Vhi + doff + cb + g * 8) = make_uint4(hw[0], hw[1], hw[2], hw[3]);
                *(uint4*)(g_Vlo + doff + cb + g * 8) = make_uint4(lw[0], lw[1], lw[2], lw[3]);
            }
        } else {
            const float scl = (sub == 0) ? 0.08838834764831845f : 1.0f;
            __half* dhi = (sub == 0) ? g_Qhi : g_Khi;
            __half* dlo = (sub == 0) ? g_Qlo : g_Klo;
            const float* crow = cs + (size_t)s * HD_;
            const float* srow = sn + (size_t)s * HD_;
#pragma unroll
            for (int g = 0; g < 4; g++) {
                const int cA = t2 * 32 + g * 8;
                const int cB = cA + 64;
                u32 hA[4], lA[4], hB[4], lB[4];
#pragma unroll
                for (int p = 0; p < 4; p++) {
                    const int c0 = cA + p * 2, c1 = cA + p * 2 + 1;
                    float xa0 = S[r * 132 + c0], xa1 = S[r * 132 + c1];
                    float xb0 = S[r * 132 + c0 + 64], xb1 = S[r * 132 + c1 + 64];
                    float oa0 = (xa0 * crow[c0] - xb0 * srow[c0]) * scl;
                    float oa1 = (xa1 * crow[c1] - xb1 * srow[c1]) * scl;
                    float ob0 = (xb0 * crow[c0 + 64] + xa0 * srow[c0 + 64]) * scl;
                    float ob1 = (xb1 * crow[c1 + 64] + xa1 * srow[c1 + 64]) * scl;
                    hA[p] = split_pack(oa0, oa1, lA[p]);
                    hB[p] = split_pack(ob0, ob1, lB[p]);
                }
                *(uint4*)(dhi + doff + cA) = make_uint4(hA[0], hA[1], hA[2], hA[3]);
                *(uint4*)(dlo + doff + cA) = make_uint4(lA[0], lA[1], lA[2], lA[3]);
                *(uint4*)(dhi + doff + cB) = make_uint4(hB[0], hB[1], hB[2], hB[3]);
                *(uint4*)(dlo + doff + cB) = make_uint4(lB[0], lB[1], lB[2], lB[3]);
            }
        }
    } else {
        float* dst = out + (size_t)m * D_ + n0;
        const int cbase = t2 * 64;
#pragma unroll
        for (int q4 = 0; q4 < 16; q4++) {
            float4 w = *(const float4*)(S + r * 132 + cbase + q4 * 4);
            *(float4*)(dst + cbase + q4 * 4) = w;
        }
    }
}

// ---------------------------------------------------------------------------
// Tensor-core causal flash attention (fp16x3). LPT: longest q-tiles first.
// Epilogue emits fp16 (hi only) for the single-product out-proj.
// ---------------------------------------------------------------------------
#define ATT_SMEM_BYTES (192 * 1024)
#define AQLO 32768
#define ASTG 65536
#define AKLO 16384
#define AVHI 32768
#define AVLO 49152

__device__ __forceinline__ u32 aswz(u32 row, u32 cb) {
    return row * 256u + (cb ^ ((row & 7u) << 4));
}

__global__ void __launch_bounds__(256, 1) attn_mma_kernel()
{
    extern __shared__ char dyn_smem[];
    const u32 smb = smem_u32(dyn_smem);
    const int tid = threadIdx.x, wid = tid >> 5, lane = tid & 31;
    const int qt = (int)gridDim.x - 1 - (int)blockIdx.x;   // LPT: longest first
    const int h = blockIdx.y, b = blockIdx.z;
    const int qg0 = qt << 7;
    const size_t bh = (size_t)(b * H_ + h) * S_;

    {
        const __half* qh = g_Qhi + (bh + qg0) * HD_;
        const __half* ql = g_Qlo + (bh + qg0) * HD_;
#pragma unroll
        for (int rep = 0; rep < 8; rep++) {
            int lin = rep * 256 + tid;
            int row = lin >> 4, u = lin & 15;
            u32 so = aswz(row, u * 16);
            cp_async16(smb + so, qh + (size_t)row * HD_ + u * 8);
            cp_async16(smb + AQLO + so, ql + (size_t)row * HD_ + u * 8);
        }
        CP_COMMIT();
    }

    const __half* khg = g_Khi + bh * HD_;
    const __half* klg = g_Klo + bh * HD_;
    const __half* vhg = g_Vhi + bh * HD_;
    const __half* vlg = g_Vlo + bh * HD_;

    auto load_stage = [&](int st, int kg0) {
        const u32 dst = smb + ASTG + (u32)st * ASTG;
        const __half* srcs[4] = {khg + (size_t)kg0 * HD_, klg + (size_t)kg0 * HD_,
                                 vhg + (size_t)kg0 * HD_, vlg + (size_t)kg0 * HD_};
#pragma unroll
        for (int op = 0; op < 4; op++) {
#pragma unroll
            for (int rep = 0; rep < 4; rep++) {
                int lin = rep * 256 + tid;
                int row = lin >> 4, u = lin & 15;
                cp_async16(dst + op * 16384 + aswz(row, u * 16),
                           srcs[op] + (size_t)row * HD_ + u * 8);
            }
        }
    };

    const int nkt = 2 * qt + 2;
    load_stage(0, 0);
    CP_COMMIT();

    const u32 aRow = (u32)(wid * 16 + (lane & 15));
    const u32 aSw = (aRow & 7u) << 4;
    const u32 aCol = (u32)((lane >> 4) << 4);
    const u32 aBase = aRow * 256u;
    const u32 kRow = (u32)(((lane >> 4) << 3) + (lane & 7));
    const u32 kSw = (u32)((lane & 7) << 4);
    const u32 kColT = (u32)(((lane >> 3) & 1) << 4);
    const u32 vRow = (u32)(lane & 15);
    const u32 vColT = (u32)((lane >> 4) << 4);

    u32 qhf[8][4], qlf[8][4];
    float o[16][4];
#pragma unroll
    for (int f = 0; f < 16; f++)
#pragma unroll
        for (int q = 0; q < 4; q++) o[f][q] = 0.f;
    float m0r = -1e30f, m1r = -1e30f, l0 = 0.f, l1 = 0.f;

    for (int kt = 0; kt < nkt; kt++) {
        if (kt + 1 < nkt) {
            load_stage((kt + 1) & 1, (kt + 1) * 64);
            CP_COMMIT();
            CP_WAIT1();
        } else {
            CP_WAIT0();
        }
        __syncthreads();
        if (kt == 0) {
#pragma unroll
            for (int ks = 0; ks < 8; ks++) {
                u32 qa = smb + aBase + (((u32)(ks * 32) + aCol) ^ aSw);
                ldsm4(qhf[ks], qa);
                ldsm4(qlf[ks], qa + AQLO);
            }
        }
        const int kg0 = kt * 64;
        const bool skip = kg0 > qg0 + wid * 16 + 15;
        if (!skip) {
            const u32 stg = smb + ASTG + (u32)(kt & 1) * ASTG;
            float s[8][4];
#pragma unroll
            for (int f = 0; f < 8; f++)
#pragma unroll
                for (int q = 0; q < 4; q++) s[f][q] = 0.f;

            // QK^T (fp16x3), term-major per ks
#pragma unroll
            for (int ks = 0; ks < 8; ks++) {
                u32 kh[4][4], kl[4][4];
#pragma unroll
                for (int p = 0; p < 4; p++) {
                    u32 addr = stg + (u32)(p * 16 + kRow) * 256u + (((u32)(ks * 32) + kColT) ^ kSw);
                    ldsm4(kh[p], addr);
                    ldsm4(kl[p], addr + AKLO);
                }
#pragma unroll
                for (int p = 0; p < 4; p++) {
                    mma16816(s[2 * p], qhf[ks], &kh[p][0]);
                    mma16816(s[2 * p + 1], qhf[ks], &kh[p][2]);
                }
#pragma unroll
                for (int p = 0; p < 4; p++) {
                    mma16816(s[2 * p], qhf[ks], &kl[p][0]);
                    mma16816(s[2 * p + 1], qhf[ks], &kl[p][2]);
                }
#pragma unroll
                for (int p = 0; p < 4; p++) {
                    mma16816(s[2 * p], qlf[ks], &kh[p][0]);
                    mma16816(s[2 * p + 1], qlf[ks], &kh[p][2]);
                }
            }

            const int row0 = qg0 + wid * 16 + (lane >> 2);
            if (kg0 + 63 > qg0 + wid * 16) {
#pragma unroll
                for (int f = 0; f < 8; f++) {
                    const int col = kg0 + f * 8 + (lane & 3) * 2;
                    if (col > row0)     s[f][0] = -1e30f;
                    if (col + 1 > row0) s[f][1] = -1e30f;
                    if (col > row0 + 8)     s[f][2] = -1e30f;
                    if (col + 1 > row0 + 8) s[f][3] = -1e30f;
                }
            }

            float mx0 = -1e30f, mx1 = -1e30f;
#pragma unroll
            for (int f = 0; f < 8; f++) {
                mx0 = fmaxf(mx0, fmaxf(s[f][0], s[f][1]));
                mx1 = fmaxf(mx1, fmaxf(s[f][2], s[f][3]));
            }
            mx0 = fmaxf(mx0, __shfl_xor_sync(0xffffffffu, mx0, 1));
            mx0 = fmaxf(mx0, __shfl_xor_sync(0xffffffffu, mx0, 2));
            mx1 = fmaxf(mx1, __shfl_xor_sync(0xffffffffu, mx1, 1));
            mx1 = fmaxf(mx1, __shfl_xor_sync(0xffffffffu, mx1, 2));
            const float mn0 = fmaxf(m0r, mx0), mn1 = fmaxf(m1r, mx1);
            const float al0 = __expf(m0r - mn0), al1 = __expf(m1r - mn1);
            m0r = mn0; m1r = mn1;
            float s0 = 0.f, s1 = 0.f;
#pragma unroll
            for (int f = 0; f < 8; f++) {
                s[f][0] = __expf(s[f][0] - mn0);
                s[f][1] = __expf(s[f][1] - mn0);
                s[f][2] = __expf(s[f][2] - mn1);
                s[f][3] = __expf(s[f][3] - mn1);
                s0 += s[f][0] + s[f][1];
                s1 += s[f][2] + s[f][3];
            }
            s0 += __shfl_xor_sync(0xffffffffu, s0, 1);
            s0 += __shfl_xor_sync(0xffffffffu, s0, 2);
            s1 += __shfl_xor_sync(0xffffffffu, s1, 1);
            s1 += __shfl_xor_sync(0xffffffffu, s1, 2);
            l0 = l0 * al0 + s0;
            l1 = l1 * al1 + s1;
#pragma unroll
            for (int f = 0; f < 16; f++) {
                o[f][0] *= al0; o[f][1] *= al0;
                o[f][2] *= al1; o[f][3] *= al1;
            }

            u32 ph[4][4], pl[4][4];
#pragma unroll
            for (int j = 0; j < 4; j++) {
                ph[j][0] = split_pack(s[2 * j][0], s[2 * j][1], pl[j][0]);
                ph[j][1] = split_pack(s[2 * j][2], s[2 * j][3], pl[j][1]);
                ph[j][2] = split_pack(s[2 * j + 1][0], s[2 * j + 1][1], pl[j][2]);
                ph[j][3] = split_pack(s[2 * j + 1][2], s[2 * j + 1][3], pl[j][3]);
            }

            // PV (fp16x3), ep-pair term-major
#pragma unroll
            for (int j = 0; j < 4; j++) {
#pragma unroll
                for (int epp = 0; epp < 4; epp++) {
                    u32 vh[2][4], vl[2][4];
#pragma unroll
                    for (int e2 = 0; e2 < 2; e2++) {
                        const int ep = epp * 2 + e2;
                        u32 va = stg + AVHI + (u32)(j * 16 + vRow) * 256u + (((u32)(ep * 32) + vColT) ^ kSw);
                        ldsm4t(vh[e2], va);
                        ldsm4t(vl[e2], va + 16384);
                    }
                    mma16816(o[4 * epp + 0], ph[j], &vh[0][0]);
                    mma16816(o[4 * epp + 1], ph[j], &vh[0][2]);
                    mma16816(o[4 * epp + 2], ph[j], &vh[1][0]);
                    mma16816(o[4 * epp + 3], ph[j], &vh[1][2]);
                    mma16816(o[4 * epp + 0], ph[j], &vl[0][0]);
                    mma16816(o[4 * epp + 1], ph[j], &vl[0][2]);
                    mma16816(o[4 * epp + 2], ph[j], &vl[1][0]);
                    mma16816(o[4 * epp + 3], ph[j], &vl[1][2]);
                    mma16816(o[4 * epp + 0], pl[j], &vh[0][0]);
                    mma16816(o[4 * epp + 1], pl[j], &vh[0][2]);
                    mma16816(o[4 * epp + 2], pl[j], &vh[1][0]);
                    mma16816(o[4 * epp + 3], pl[j], &vh[1][2]);
                }
            }
        }
        __syncthreads();
    }

    // epilogue: normalize, round to fp16 (hi only), store
    const float inv0 = 1.0f / l0, inv1 = 1.0f / l1;
    const int srow0 = qg0 + wid * 16 + (lane >> 2);
    const size_t ro0 = ((size_t)b * S_ + srow0) * F_ + h * HD_;
    const size_t ro1 = ro0 + (size_t)8 * F_;
#pragma unroll
    for (int f = 0; f < 16; f++) {
        const int e = f * 8 + (lane & 3) * 2;
        *(u32*)(g_AThi + ro0 + e) = round_pack(o[f][0] * inv0, o[f][1] * inv0);
        *(u32*)(g_AThi + ro1 + e) = round_pack(o[f][2] * inv1, o[f][3] * inv1);
    }
}

// ---------------------------------------------------------------------------
extern "C" void kernel_launch(void* const* d_in, const int* in_sizes, int n_in,
                              void* d_out, int out_size)
{
    const float* hs = (const float*)d_in[0];
    const float* cs = (const float*)d_in[1];
    const float* sn = (const float*)d_in[2];
    const float* wq = (const float*)d_in[3];
    const float* wo = (const float*)d_in[4];
    float* out = (float*)d_out;

    cudaFuncSetAttribute(mma_gemm_kernel<0>, cudaFuncAttributeMaxDynamicSharedMemorySize, MMA_SMEM_BYTES);
    cudaFuncSetAttribute(mma_gemm_kernel<1>, cudaFuncAttributeMaxDynamicSharedMemorySize, MMA_SMEM_BYTES);
    cudaFuncSetAttribute(attn_mma_kernel, cudaFuncAttributeMaxDynamicSharedMemorySize, ATT_SMEM_BYTES);

    __half *ahi, *alo, *whi, *wohi, *athi;
    cudaGetSymbolAddress((void**)&ahi, g_Ahi);   cudaGetSymbolAddress((void**)&alo, g_Alo);
    cudaGetSymbolAddress((void**)&whi, g_Whi);
    cudaGetSymbolAddress((void**)&wohi, g_Wohi);
    cudaGetSymbolAddress((void**)&athi, g_AThi);

    {
        int n4 = (M_ * D_) / 4;
        split_f16_kernel<<<(n4 + 255) / 256, 256>>>((const float4*)hs, (uint2*)ahi, (uint2*)alo, n4);
        n4 = (NQKV * D_) / 4;
        round_f16_kernel<<<(n4 + 255) / 256, 256>>>((const float4*)wq, (uint2*)whi, n4);
        n4 = (D_ * F_) / 4;
        round_f16_kernel<<<(n4 + 255) / 256, 256>>>((const float4*)wo, (uint2*)wohi, n4);
    }

    // QKV projection (fp16, 2-prod for q/k tiles, 1-prod for v) + RoPE
    mma_gemm_kernel<0><<<dim3(NQKV / 128, M_ / 128), 256, MMA_SMEM_BYTES>>>(
        ahi, alo, whi, cs, sn, nullptr);

    // Causal flash attention (fp16x3) -> g_AThi (fp16)
    attn_mma_kernel<<<dim3(S_ / 128, H_, B_), 256, ATT_SMEM_BYTES>>>();

    // Output projection (fp16 single-product) -> d_out
    mma_gemm_kernel<1><<<dim3(D_ / 128, M_ / 128), 256, MMA_SMEM_BYTES>>>(
        athi, athi, wohi, nullptr, nullptr, out);
}

// round 12
// speedup vs baseline: 1.6350x; 1.0660x over previous
#include <cuda_runtime.h>
#include <cuda_fp16.h>
#include <cstdint>
#include <math.h>

// Problem constants
#define B_   2
#define S_   2048
#define D_   2048
#define H_   16
#define HD_  128
#define M_   (B_ * S_)     // 4096
#define F_   (H_ * HD_)    // 2048
#define NQKV (3 * F_)      // 6144

typedef unsigned long long u64;
typedef unsigned int u32;

__device__ __forceinline__ u32 smem_u32(const void* p) {
    u32 a; asm("{ .reg .u64 t; cvta.to.shared.u64 t, %1; cvt.u32.u64 %0, t; }" : "=r"(a) : "l"(p));
    return a;
}

// ---- mma.sync / ldmatrix / cp.async ----
__device__ __forceinline__ void ldsm4(u32* r, u32 addr) {
    asm volatile("ldmatrix.sync.aligned.m8n8.x4.shared.b16 {%0,%1,%2,%3}, [%4];"
        : "=r"(r[0]), "=r"(r[1]), "=r"(r[2]), "=r"(r[3]) : "r"(addr));
}
__device__ __forceinline__ void ldsm4t(u32* r, u32 addr) {
    asm volatile("ldmatrix.sync.aligned.m8n8.x4.trans.shared.b16 {%0,%1,%2,%3}, [%4];"
        : "=r"(r[0]), "=r"(r[1]), "=r"(r[2]), "=r"(r[3]) : "r"(addr));
}
__device__ __forceinline__ void mma16816(float* d, const u32* a, const u32* b) {
    asm volatile("mma.sync.aligned.m16n8k16.row.col.f32.f16.f16.f32 "
        "{%0,%1,%2,%3}, {%4,%5,%6,%7}, {%8,%9}, {%0,%1,%2,%3};"
        : "+f"(d[0]), "+f"(d[1]), "+f"(d[2]), "+f"(d[3])
        : "r"(a[0]), "r"(a[1]), "r"(a[2]), "r"(a[3]), "r"(b[0]), "r"(b[1]));
}
__device__ __forceinline__ void cp_async16(u32 dst, const void* src) {
    asm volatile("cp.async.cg.shared.global [%0], [%1], 16;" :: "r"(dst), "l"(src));
}
#define CP_COMMIT() asm volatile("cp.async.commit_group;" ::: "memory")
#define CP_WAIT0()  asm volatile("cp.async.wait_group 0;" ::: "memory")
#define CP_WAIT1()  asm volatile("cp.async.wait_group 1;" ::: "memory")

// split f32 pair -> packed f16x2 hi (returned) and lo (out-param)
__device__ __forceinline__ u32 split_pack(float x, float y, u32& lo) {
    float hx = __half2float(__float2half_rn(x));
    float hy = __half2float(__float2half_rn(y));
    u32 hi;
    asm("cvt.rn.f16x2.f32 %0, %1, %2;" : "=r"(hi) : "f"(hy), "f"(hx));
    asm("cvt.rn.f16x2.f32 %0, %1, %2;" : "=r"(lo) : "f"(y - hy), "f"(x - hx));
    return hi;
}
// round f32 pair -> packed f16x2 (hi only)
__device__ __forceinline__ u32 round_pack(float x, float y) {
    u32 hi;
    asm("cvt.rn.f16x2.f32 %0, %1, %2;" : "=r"(hi) : "f"(y), "f"(x));
    return hi;
}

// ---------------- device scratch ----------------
__device__ __half g_Qhi[(size_t)B_ * H_ * S_ * HD_], g_Qlo[(size_t)B_ * H_ * S_ * HD_];
__device__ __half g_Khi[(size_t)B_ * H_ * S_ * HD_], g_Klo[(size_t)B_ * H_ * S_ * HD_];
__device__ __half g_Vhi[(size_t)B_ * H_ * S_ * HD_];
__device__ __half g_Ahi[(size_t)M_ * D_],   g_Alo[(size_t)M_ * D_];
__device__ __half g_Whi[(size_t)NQKV * D_];
__device__ __half g_Wohi[(size_t)D_ * F_];
__device__ __half g_AThi[(size_t)M_ * F_];

// ---------------------------------------------------------------------------
// Split fp32 -> fp16 (hi, lo) ; and hi-only variant for weights
// ---------------------------------------------------------------------------
__global__ void split_f16_kernel(const float4* __restrict__ x,
                                 uint2* __restrict__ hi, uint2* __restrict__ lo, int n4)
{
    int i = blockIdx.x * blockDim.x + threadIdx.x;
    if (i >= n4) return;
    float4 v = x[i];
    u32 l0, l1, h0, h1;
    h0 = split_pack(v.x, v.y, l0);
    h1 = split_pack(v.z, v.w, l1);
    hi[i] = make_uint2(h0, h1);
    lo[i] = make_uint2(l0, l1);
}
__global__ void round_f16_kernel(const float4* __restrict__ x,
                                 uint2* __restrict__ hi, int n4)
{
    int i = blockIdx.x * blockDim.x + threadIdx.x;
    if (i >= n4) return;
    float4 v = x[i];
    hi[i] = make_uint2(round_pack(v.x, v.y), round_pack(v.z, v.w));
}

// ---------------------------------------------------------------------------
// fp16 GEMM via mma.sync. Tile 128x128, K chunks of 64. 8 warps (4m x 2n),
// warp tile 32x64 (A re-read x2, B x4 -> 64 ldsm/kstep vs 80), term-major.
// 2-stage pipeline, 96KB -> 2 CTAs/SM.
// Products: Ahi*Bhi (+ Alo*Bhi when useAlo).
//   MODE 0 (QKV + RoPE): useAlo = (tile is q or k); V tiles single-product.
//   MODE 1 (out proj):   useAlo = false.
// ---------------------------------------------------------------------------
#define NCHUNK 32
#define TILEB 16384
#define STAGEB (3 * TILEB)                 // 48KB
#define MMA_SMEM_BYTES (2 * STAGEB)        // 96KB -> occ 2

__device__ __forceinline__ u32 swz(u32 row, u32 cb) {
    return row * 128u + (cb ^ ((row & 7u) << 4));
}

template <int MODE>
__global__ void __launch_bounds__(256, 2) mma_gemm_kernel(
    const __half* __restrict__ Ahi, const __half* __restrict__ Alo,
    const __half* __restrict__ Bhi,
    const float* __restrict__ cs, const float* __restrict__ sn,
    float* __restrict__ out)
{
    extern __shared__ char dyn_smem[];
    const u32 smb = smem_u32(dyn_smem);

    const int tid = threadIdx.x;
    const int wid = tid >> 5;
    const int lane = tid & 31;
    const int wm = wid >> 1, wn = wid & 1;   // 4(m) x 2(n) warp grid
    const int m0 = blockIdx.y << 7;
    const int n0 = blockIdx.x << 7;

    const int sub = (MODE == 0) ? ((n0 % 384) >> 7) : 3;   // 0=q,1=k,2=v
    const bool useAlo = (MODE == 0) && (sub != 2);

    auto load_chunk = [&](int st, int k0) {
        const u32 sb = smb + (u32)st * STAGEB;
#pragma unroll
        for (int rep = 0; rep < 4; rep++) {
            int lin = rep * 256 + tid;
            int row = lin >> 3, u = lin & 7;
            const u32 so = swz(row, u * 16);
            cp_async16(sb + so, Ahi + (size_t)(m0 + row) * 2048 + k0 + u * 8);
            if (useAlo)
                cp_async16(sb + TILEB + so, Alo + (size_t)(m0 + row) * 2048 + k0 + u * 8);
            cp_async16(sb + 2 * TILEB + so, Bhi + (size_t)(n0 + row) * 2048 + k0 + u * 8);
        }
    };

    load_chunk(0, 0);  CP_COMMIT();
    load_chunk(1, 64); CP_COMMIT();

    // fragment addressing: A rows wm*32.., B rows wn*64..
    const u32 aRow = (u32)(wm * 32 + (lane & 15));
    const u32 aSw = (aRow & 7u) << 4;
    const u32 aColSel = (u32)((lane >> 4) << 4);
    u32 aOff[2];
#pragma unroll
    for (int fm = 0; fm < 2; fm++) aOff[fm] = (aRow + fm * 16) * 128u;

    u32 bOff[4], bSw[4];
#pragma unroll
    for (int p = 0; p < 4; p++) {
        u32 brow = (u32)(wn * 64 + p * 16 + ((lane >> 4) << 3) + (lane & 7));
        bOff[p] = brow * 128u;
        bSw[p] = (brow & 7u) << 4;
    }
    const u32 bColSel = (u32)(((lane >> 3) & 1) << 4);

    float acc[2][8][4];
#pragma unroll
    for (int i = 0; i < 2; i++)
#pragma unroll
        for (int j = 0; j < 8; j++)
#pragma unroll
            for (int q = 0; q < 4; q++) acc[i][j][q] = 0.f;

    for (int c = 0; c < NCHUNK; c++) {
        if (c + 1 < NCHUNK) { CP_WAIT1(); } else { CP_WAIT0(); }
        __syncthreads();
        const u32 stage = smb + (u32)(c & 1) * STAGEB;
#pragma unroll
        for (int ks = 0; ks < 4; ks++) {
            const u32 cbA = (u32)(ks * 32) + aColSel;
            const u32 cbB = (u32)(ks * 32) + bColSel;
            u32 ah[2][4], al[2][4], bh[4][4];
#pragma unroll
            for (int fm = 0; fm < 2; fm++)
                ldsm4(ah[fm], stage + aOff[fm] + (cbA ^ aSw));
            if (useAlo) {
#pragma unroll
                for (int fm = 0; fm < 2; fm++)
                    ldsm4(al[fm], stage + TILEB + aOff[fm] + (cbA ^ aSw));
            }
#pragma unroll
            for (int p = 0; p < 4; p++)
                ldsm4(bh[p], stage + 2 * TILEB + bOff[p] + (cbB ^ bSw[p]));
            // term-major: 16 MMAs per term -> same-acc distance 16
#pragma unroll
            for (int fm = 0; fm < 2; fm++)
#pragma unroll
                for (int p = 0; p < 4; p++)
#pragma unroll
                    for (int q = 0; q < 2; q++)
                        mma16816(acc[fm][p * 2 + q], ah[fm], &bh[p][q * 2]);
            if (useAlo) {
#pragma unroll
                for (int fm = 0; fm < 2; fm++)
#pragma unroll
                    for (int p = 0; p < 4; p++)
#pragma unroll
                        for (int q = 0; q < 2; q++)
                            mma16816(acc[fm][p * 2 + q], al[fm], &bh[p][q * 2]);
            }
        }
        __syncthreads();
        if (c + 2 < NCHUNK) {
            load_chunk(c & 1, (c + 2) * 64);
            CP_COMMIT();
        }
    }

    // epilogue: accum -> smem fp32 (pitch 132), then scatter
    float* S = (float*)dyn_smem;
    const int er = lane >> 2, ec = (lane & 3) << 1;
#pragma unroll
    for (int fm = 0; fm < 2; fm++)
#pragma unroll
        for (int fn = 0; fn < 8; fn++) {
            const int r0 = wm * 32 + fm * 16 + er;
            const int c0 = wn * 64 + fn * 8 + ec;
            S[r0 * 132 + c0] = acc[fm][fn][0];
            S[r0 * 132 + c0 + 1] = acc[fm][fn][1];
            S[(r0 + 8) * 132 + c0] = acc[fm][fn][2];
            S[(r0 + 8) * 132 + c0 + 1] = acc[fm][fn][3];
        }
    __syncthreads();

    const int r = tid >> 1, t2 = tid & 1;
    const int m = m0 + r;
    if (MODE == 0) {
        const int h = n0 / 384;
        const int b = m >> 11, s = m & 2047;
        const size_t doff = ((size_t)(b * H_ + h) * S_ + s) * HD_;
        if (sub == 2) {
            const int cb = t2 * 64;
#pragma unroll
            for (int g = 0; g < 8; g++) {
                u32 hw[4];
#pragma unroll
                for (int p = 0; p < 4; p++) {
                    float x = S[r * 132 + cb + g * 8 + p * 2];
                    float y = S[r * 132 + cb + g * 8 + p * 2 + 1];
                    hw[p] = round_pack(x, y);
                }
                *(uint4*)(g_Vhi + doff + cb + g * 8) = make_uint4(hw[0], hw[1], hw[2], hw[3]);
            }
        } else {
            const float scl = (sub == 0) ? 0.08838834764831845f : 1.0f;
            __half* dhi = (sub == 0) ? g_Qhi : g_Khi;
            __half* dlo = (sub == 0) ? g_Qlo : g_Klo;
            const float* crow = cs + (size_t)s * HD_;
            const float* srow = sn + (size_t)s * HD_;
#pragma unroll
            for (int g = 0; g < 4; g++) {
                const int cA = t2 * 32 + g * 8;
                const int cB = cA + 64;
                u32 hA[4], lA[4], hB[4], lB[4];
#pragma unroll
                for (int p = 0; p < 4; p++) {
                    const int c0 = cA + p * 2, c1 = cA + p * 2 + 1;
                    float xa0 = S[r * 132 + c0], xa1 = S[r * 132 + c1];
                    float xb0 = S[r * 132 + c0 + 64], xb1 = S[r * 132 + c1 + 64];
                    float oa0 = (xa0 * crow[c0] - xb0 * srow[c0]) * scl;
                    float oa1 = (xa1 * crow[c1] - xb1 * srow[c1]) * scl;
                    float ob0 = (xb0 * crow[c0 + 64] + xa0 * srow[c0 + 64]) * scl;
                    float ob1 = (xb1 * crow[c1 + 64] + xa1 * srow[c1 + 64]) * scl;
                    hA[p] = split_pack(oa0, oa1, lA[p]);
                    hB[p] = split_pack(ob0, ob1, lB[p]);
                }
                *(uint4*)(dhi + doff + cA) = make_uint4(hA[0], hA[1], hA[2], hA[3]);
                *(uint4*)(dlo + doff + cA) = make_uint4(lA[0], lA[1], lA[2], lA[3]);
                *(uint4*)(dhi + doff + cB) = make_uint4(hB[0], hB[1], hB[2], hB[3]);
                *(uint4*)(dlo + doff + cB) = make_uint4(lB[0], lB[1], lB[2], lB[3]);
            }
        }
    } else {
        float* dst = out + (size_t)m * D_ + n0;
        const int cbase = t2 * 64;
#pragma unroll
        for (int q4 = 0; q4 < 16; q4++) {
            float4 w = *(const float4*)(S + r * 132 + cbase + q4 * 4);
            *(float4*)(dst + cbase + q4 * 4) = w;
        }
    }
}

// ---------------------------------------------------------------------------
// Tensor-core causal flash attention. QK fp16x3; PV fp16x2 (V hi-only).
// LPT: longest q-tiles first. Epilogue emits fp16 (hi only).
// SMEM: Qhi 32K | Qlo 32K | 2 stages x (Khi|Klo|Vhi = 48K) = 160KB.
// ---------------------------------------------------------------------------
#define AQLO 32768
#define ASTG0 65536
#define ASTGB 49152
#define AKLO 16384
#define AVHI 32768
#define ATT_SMEM_BYTES (ASTG0 + 2 * ASTGB)   // 160KB

__device__ __forceinline__ u32 aswz(u32 row, u32 cb) {
    return row * 256u + (cb ^ ((row & 7u) << 4));
}

__global__ void __launch_bounds__(256, 1) attn_mma_kernel()
{
    extern __shared__ char dyn_smem[];
    const u32 smb = smem_u32(dyn_smem);
    const int tid = threadIdx.x, wid = tid >> 5, lane = tid & 31;
    const int qt = (int)gridDim.x - 1 - (int)blockIdx.x;   // LPT: longest first
    const int h = blockIdx.y, b = blockIdx.z;
    const int qg0 = qt << 7;
    const size_t bh = (size_t)(b * H_ + h) * S_;

    {
        const __half* qh = g_Qhi + (bh + qg0) * HD_;
        const __half* ql = g_Qlo + (bh + qg0) * HD_;
#pragma unroll
        for (int rep = 0; rep < 8; rep++) {
            int lin = rep * 256 + tid;
            int row = lin >> 4, u = lin & 15;
            u32 so = aswz(row, u * 16);
            cp_async16(smb + so, qh + (size_t)row * HD_ + u * 8);
            cp_async16(smb + AQLO + so, ql + (size_t)row * HD_ + u * 8);
        }
        CP_COMMIT();
    }

    const __half* khg = g_Khi + bh * HD_;
    const __half* klg = g_Klo + bh * HD_;
    const __half* vhg = g_Vhi + bh * HD_;

    auto load_stage = [&](int st, int kg0) {
        const u32 dst = smb + ASTG0 + (u32)st * ASTGB;
        const __half* srcs[3] = {khg + (size_t)kg0 * HD_, klg + (size_t)kg0 * HD_,
                                 vhg + (size_t)kg0 * HD_};
#pragma unroll
        for (int op = 0; op < 3; op++) {
#pragma unroll
            for (int rep = 0; rep < 4; rep++) {
                int lin = rep * 256 + tid;
                int row = lin >> 4, u = lin & 15;
                cp_async16(dst + op * 16384 + aswz(row, u * 16),
                           srcs[op] + (size_t)row * HD_ + u * 8);
            }
        }
    };

    const int nkt = 2 * qt + 2;
    load_stage(0, 0);
    CP_COMMIT();

    const u32 aRow = (u32)(wid * 16 + (lane & 15));
    const u32 aSw = (aRow & 7u) << 4;
    const u32 aCol = (u32)((lane >> 4) << 4);
    const u32 aBase = aRow * 256u;
    const u32 kRow = (u32)(((lane >> 4) << 3) + (lane & 7));
    const u32 kSw = (u32)((lane & 7) << 4);
    const u32 kColT = (u32)(((lane >> 3) & 1) << 4);
    const u32 vRow = (u32)(lane & 15);
    const u32 vColT = (u32)((lane >> 4) << 4);

    u32 qhf[8][4], qlf[8][4];
    float o[16][4];
#pragma unroll
    for (int f = 0; f < 16; f++)
#pragma unroll
        for (int q = 0; q < 4; q++) o[f][q] = 0.f;
    float m0r = -1e30f, m1r = -1e30f, l0 = 0.f, l1 = 0.f;

    for (int kt = 0; kt < nkt; kt++) {
        if (kt + 1 < nkt) {
            load_stage((kt + 1) & 1, (kt + 1) * 64);
            CP_COMMIT();
            CP_WAIT1();
        } else {
            CP_WAIT0();
        }
        __syncthreads();
        if (kt == 0) {
#pragma unroll
            for (int ks = 0; ks < 8; ks++) {
                u32 qa = smb + aBase + (((u32)(ks * 32) + aCol) ^ aSw);
                ldsm4(qhf[ks], qa);
                ldsm4(qlf[ks], qa + AQLO);
            }
        }
        const int kg0 = kt * 64;
        const bool skip = kg0 > qg0 + wid * 16 + 15;
        if (!skip) {
            const u32 stg = smb + ASTG0 + (u32)(kt & 1) * ASTGB;
            float s[8][4];
#pragma unroll
            for (int f = 0; f < 8; f++)
#pragma unroll
                for (int q = 0; q < 4; q++) s[f][q] = 0.f;

            // QK^T (fp16x3), term-major per ks
#pragma unroll
            for (int ks = 0; ks < 8; ks++) {
                u32 kh[4][4], kl[4][4];
#pragma unroll
                for (int p = 0; p < 4; p++) {
                    u32 addr = stg + (u32)(p * 16 + kRow) * 256u + (((u32)(ks * 32) + kColT) ^ kSw);
                    ldsm4(kh[p], addr);
                    ldsm4(kl[p], addr + AKLO);
                }
#pragma unroll
                for (int p = 0; p < 4; p++) {
                    mma16816(s[2 * p], qhf[ks], &kh[p][0]);
                    mma16816(s[2 * p + 1], qhf[ks], &kh[p][2]);
                }
#pragma unroll
                for (int p = 0; p < 4; p++) {
                    mma16816(s[2 * p], qhf[ks], &kl[p][0]);
                    mma16816(s[2 * p + 1], qhf[ks], &kl[p][2]);
                }
#pragma unroll
                for (int p = 0; p < 4; p++) {
                    mma16816(s[2 * p], qlf[ks], &kh[p][0]);
                    mma16816(s[2 * p + 1], qlf[ks], &kh[p][2]);
                }
            }

            const int row0 = qg0 + wid * 16 + (lane >> 2);
            if (kg0 + 63 > qg0 + wid * 16) {
#pragma unroll
                for (int f = 0; f < 8; f++) {
                    const int col = kg0 + f * 8 + (lane & 3) * 2;
                    if (col > row0)     s[f][0] = -1e30f;
                    if (col + 1 > row0) s[f][1] = -1e30f;
                    if (col > row0 + 8)     s[f][2] = -1e30f;
                    if (col + 1 > row0 + 8) s[f][3] = -1e30f;
                }
            }

            float mx0 = -1e30f, mx1 = -1e30f;
#pragma unroll
            for (int f = 0; f < 8; f++) {
                mx0 = fmaxf(mx0, fmaxf(s[f][0], s[f][1]));
                mx1 = fmaxf(mx1, fmaxf(s[f][2], s[f][3]));
            }
            mx0 = fmaxf(mx0, __shfl_xor_sync(0xffffffffu, mx0, 1));
            mx0 = fmaxf(mx0, __shfl_xor_sync(0xffffffffu, mx0, 2));
            mx1 = fmaxf(mx1, __shfl_xor_sync(0xffffffffu, mx1, 1));
            mx1 = fmaxf(mx1, __shfl_xor_sync(0xffffffffu, mx1, 2));
            const float mn0 = fmaxf(m0r, mx0), mn1 = fmaxf(m1r, mx1);
            const float al0 = __expf(m0r - mn0), al1 = __expf(m1r - mn1);
            m0r = mn0; m1r = mn1;
            float s0 = 0.f, s1 = 0.f;
#pragma unroll
            for (int f = 0; f < 8; f++) {
                s[f][0] = __expf(s[f][0] - mn0);
                s[f][1] = __expf(s[f][1] - mn0);
                s[f][2] = __expf(s[f][2] - mn1);
                s[f][3] = __expf(s[f][3] - mn1);
                s0 += s[f][0] + s[f][1];
                s1 += s[f][2] + s[f][3];
            }
            s0 += __shfl_xor_sync(0xffffffffu, s0, 1);
            s0 += __shfl_xor_sync(0xffffffffu, s0, 2);
            s1 += __shfl_xor_sync(0xffffffffu, s1, 1);
            s1 += __shfl_xor_sync(0xffffffffu, s1, 2);
            l0 = l0 * al0 + s0;
            l1 = l1 * al1 + s1;
#pragma unroll
            for (int f = 0; f < 16; f++) {
                o[f][0] *= al0; o[f][1] *= al0;
                o[f][2] *= al1; o[f][3] *= al1;
            }

            u32 ph[4][4], pl[4][4];
#pragma unroll
            for (int j = 0; j < 4; j++) {
                ph[j][0] = split_pack(s[2 * j][0], s[2 * j][1], pl[j][0]);
                ph[j][1] = split_pack(s[2 * j][2], s[2 * j][3], pl[j][1]);
                ph[j][2] = split_pack(s[2 * j + 1][0], s[2 * j + 1][1], pl[j][2]);
                ph[j][3] = split_pack(s[2 * j + 1][2], s[2 * j + 1][3], pl[j][3]);
            }

            // PV (fp16x2: Phi*Vhi + Plo*Vhi), ep-pair term-major
#pragma unroll
            for (int j = 0; j < 4; j++) {
#pragma unroll
                for (int epp = 0; epp < 4; epp++) {
                    u32 vh[2][4];
#pragma unroll
                    for (int e2 = 0; e2 < 2; e2++) {
                        const int ep = epp * 2 + e2;
                        u32 va = stg + AVHI + (u32)(j * 16 + vRow) * 256u + (((u32)(ep * 32) + vColT) ^ kSw);
                        ldsm4t(vh[e2], va);
                    }
                    mma16816(o[4 * epp + 0], ph[j], &vh[0][0]);
                    mma16816(o[4 * epp + 1], ph[j], &vh[0][2]);
                    mma16816(o[4 * epp + 2], ph[j], &vh[1][0]);
                    mma16816(o[4 * epp + 3], ph[j], &vh[1][2]);
                    mma16816(o[4 * epp + 0], pl[j], &vh[0][0]);
                    mma16816(o[4 * epp + 1], pl[j], &vh[0][2]);
                    mma16816(o[4 * epp + 2], pl[j], &vh[1][0]);
                    mma16816(o[4 * epp + 3], pl[j], &vh[1][2]);
                }
            }
        }
        __syncthreads();
    }

    // epilogue: normalize, round to fp16 (hi only), store
    const float inv0 = 1.0f / l0, inv1 = 1.0f / l1;
    const int srow0 = qg0 + wid * 16 + (lane >> 2);
    const size_t ro0 = ((size_t)b * S_ + srow0) * F_ + h * HD_;
    const size_t ro1 = ro0 + (size_t)8 * F_;
#pragma unroll
    for (int f = 0; f < 16; f++) {
        const int e = f * 8 + (lane & 3) * 2;
        *(u32*)(g_AThi + ro0 + e) = round_pack(o[f][0] * inv0, o[f][1] * inv0);
        *(u32*)(g_AThi + ro1 + e) = round_pack(o[f][2] * inv1, o[f][3] * inv1);
    }
}

// ---------------------------------------------------------------------------
extern "C" void kernel_launch(void* const* d_in, const int* in_sizes, int n_in,
                              void* d_out, int out_size)
{
    const float* hs = (const float*)d_in[0];
    const float* cs = (const float*)d_in[1];
    const float* sn = (const float*)d_in[2];
    const float* wq = (const float*)d_in[3];
    const float* wo = (const float*)d_in[4];
    float* out = (float*)d_out;

    cudaFuncSetAttribute(mma_gemm_kernel<0>, cudaFuncAttributeMaxDynamicSharedMemorySize, MMA_SMEM_BYTES);
    cudaFuncSetAttribute(mma_gemm_kernel<1>, cudaFuncAttributeMaxDynamicSharedMemorySize, MMA_SMEM_BYTES);
    cudaFuncSetAttribute(attn_mma_kernel, cudaFuncAttributeMaxDynamicSharedMemorySize, ATT_SMEM_BYTES);

    __half *ahi, *alo, *whi, *wohi, *athi;
    cudaGetSymbolAddress((void**)&ahi, g_Ahi);   cudaGetSymbolAddress((void**)&alo, g_Alo);
    cudaGetSymbolAddress((void**)&whi, g_Whi);
    cudaGetSymbolAddress((void**)&wohi, g_Wohi);
    cudaGetSymbolAddress((void**)&athi, g_AThi);

    {
        int n4 = (M_ * D_) / 4;
        split_f16_kernel<<<(n4 + 255) / 256, 256>>>((const float4*)hs, (uint2*)ahi, (uint2*)alo, n4);
        n4 = (NQKV * D_) / 4;
        round_f16_kernel<<<(n4 + 255) / 256, 256>>>((const float4*)wq, (uint2*)whi, n4);
        n4 = (D_ * F_) / 4;
        round_f16_kernel<<<(n4 + 255) / 256, 256>>>((const float4*)wo, (uint2*)wohi, n4);
    }

    // QKV projection (fp16, 2-prod q/k, 1-prod v) + RoPE
    mma_gemm_kernel<0><<<dim3(NQKV / 128, M_ / 128), 256, MMA_SMEM_BYTES>>>(
        ahi, alo, whi, cs, sn, nullptr);

    // Causal flash attention (QK fp16x3, PV fp16x2) -> g_AThi (fp16)
    attn_mma_kernel<<<dim3(S_ / 128, H_, B_), 256, ATT_SMEM_BYTES>>>();

    // Output projection (fp16 single-product) -> d_out
    mma_gemm_kernel<1><<<dim3(D_ / 128, M_ / 128), 256, MMA_SMEM_BYTES>>>(
        athi, athi, wohi, nullptr, nullptr, out);
}

// round 13
// speedup vs baseline: 1.8093x; 1.1066x over previous
#include <cuda_runtime.h>
#include <cuda_fp16.h>
#include <cstdint>
#include <math.h>

// Problem constants
#define B_   2
#define S_   2048
#define D_   2048
#define H_   16
#define HD_  128
#define M_   (B_ * S_)     // 4096
#define F_   (H_ * HD_)    // 2048
#define NQKV (3 * F_)      // 6144

typedef unsigned long long u64;
typedef unsigned int u32;

__device__ __forceinline__ u32 smem_u32(const void* p) {
    u32 a; asm("{ .reg .u64 t; cvta.to.shared.u64 t, %1; cvt.u32.u64 %0, t; }" : "=r"(a) : "l"(p));
    return a;
}

// ---- mma.sync / ldmatrix / cp.async ----
__device__ __forceinline__ void ldsm4(u32* r, u32 addr) {
    asm volatile("ldmatrix.sync.aligned.m8n8.x4.shared.b16 {%0,%1,%2,%3}, [%4];"
        : "=r"(r[0]), "=r"(r[1]), "=r"(r[2]), "=r"(r[3]) : "r"(addr));
}
__device__ __forceinline__ void ldsm4t(u32* r, u32 addr) {
    asm volatile("ldmatrix.sync.aligned.m8n8.x4.trans.shared.b16 {%0,%1,%2,%3}, [%4];"
        : "=r"(r[0]), "=r"(r[1]), "=r"(r[2]), "=r"(r[3]) : "r"(addr));
}
__device__ __forceinline__ void mma16816(float* d, const u32* a, const u32* b) {
    asm volatile("mma.sync.aligned.m16n8k16.row.col.f32.f16.f16.f32 "
        "{%0,%1,%2,%3}, {%4,%5,%6,%7}, {%8,%9}, {%0,%1,%2,%3};"
        : "+f"(d[0]), "+f"(d[1]), "+f"(d[2]), "+f"(d[3])
        : "r"(a[0]), "r"(a[1]), "r"(a[2]), "r"(a[3]), "r"(b[0]), "r"(b[1]));
}
__device__ __forceinline__ void cp_async16(u32 dst, const void* src) {
    asm volatile("cp.async.cg.shared.global [%0], [%1], 16;" :: "r"(dst), "l"(src));
}
#define CP_COMMIT() asm volatile("cp.async.commit_group;" ::: "memory")
#define CP_WAIT0()  asm volatile("cp.async.wait_group 0;" ::: "memory")
#define CP_WAIT1()  asm volatile("cp.async.wait_group 1;" ::: "memory")

// split f32 pair -> packed f16x2 hi (returned) and lo (out-param)
__device__ __forceinline__ u32 split_pack(float x, float y, u32& lo) {
    float hx = __half2float(__float2half_rn(x));
    float hy = __half2float(__float2half_rn(y));
    u32 hi;
    asm("cvt.rn.f16x2.f32 %0, %1, %2;" : "=r"(hi) : "f"(hy), "f"(hx));
    asm("cvt.rn.f16x2.f32 %0, %1, %2;" : "=r"(lo) : "f"(y - hy), "f"(x - hx));
    return hi;
}
// round f32 pair -> packed f16x2 (hi only)
__device__ __forceinline__ u32 round_pack(float x, float y) {
    u32 hi;
    asm("cvt.rn.f16x2.f32 %0, %1, %2;" : "=r"(hi) : "f"(y), "f"(x));
    return hi;
}

// ---------------- device scratch ----------------
__device__ __half g_Qhi[(size_t)B_ * H_ * S_ * HD_];
__device__ __half g_Khi[(size_t)B_ * H_ * S_ * HD_], g_Klo[(size_t)B_ * H_ * S_ * HD_];
__device__ __half g_Vhi[(size_t)B_ * H_ * S_ * HD_];
__device__ __half g_Ahi[(size_t)M_ * D_],   g_Alo[(size_t)M_ * D_];
__device__ __half g_Whi[(size_t)NQKV * D_];
__device__ __half g_Wohi[(size_t)D_ * F_];
__device__ __half g_AThi[(size_t)M_ * F_];

// ---------------------------------------------------------------------------
// Split fp32 -> fp16 (hi, lo) ; and hi-only variant for weights
// ---------------------------------------------------------------------------
__global__ void split_f16_kernel(const float4* __restrict__ x,
                                 uint2* __restrict__ hi, uint2* __restrict__ lo, int n4)
{
    int i = blockIdx.x * blockDim.x + threadIdx.x;
    if (i >= n4) return;
    float4 v = x[i];
    u32 l0, l1, h0, h1;
    h0 = split_pack(v.x, v.y, l0);
    h1 = split_pack(v.z, v.w, l1);
    hi[i] = make_uint2(h0, h1);
    lo[i] = make_uint2(l0, l1);
}
__global__ void round_f16_kernel(const float4* __restrict__ x,
                                 uint2* __restrict__ hi, int n4)
{
    int i = blockIdx.x * blockDim.x + threadIdx.x;
    if (i >= n4) return;
    float4 v = x[i];
    hi[i] = make_uint2(round_pack(v.x, v.y), round_pack(v.z, v.w));
}

// ---------------------------------------------------------------------------
// fp16 GEMM via mma.sync. Tile 128x128, K chunks of 64. 8 warps (4m x 2n),
// warp tile 32x64, term-major. 2-stage pipeline, 96KB -> 2 CTAs/SM.
// Products: Ahi*Bhi (+ Alo*Bhi when useAlo).
//   MODE 0 (QKV + RoPE): useAlo = (tile is q or k); V tiles single-product.
//   MODE 1 (out proj):   useAlo = false.
// ---------------------------------------------------------------------------
#define NCHUNK 32
#define TILEB 16384
#define STAGEB (3 * TILEB)                 // 48KB
#define MMA_SMEM_BYTES (2 * STAGEB)        // 96KB -> occ 2

__device__ __forceinline__ u32 swz(u32 row, u32 cb) {
    return row * 128u + (cb ^ ((row & 7u) << 4));
}

template <int MODE>
__global__ void __launch_bounds__(256, 2) mma_gemm_kernel(
    const __half* __restrict__ Ahi, const __half* __restrict__ Alo,
    const __half* __restrict__ Bhi,
    const float* __restrict__ cs, const float* __restrict__ sn,
    float* __restrict__ out)
{
    extern __shared__ char dyn_smem[];
    const u32 smb = smem_u32(dyn_smem);

    const int tid = threadIdx.x;
    const int wid = tid >> 5;
    const int lane = tid & 31;
    const int wm = wid >> 1, wn = wid & 1;   // 4(m) x 2(n) warp grid
    const int m0 = blockIdx.y << 7;
    const int n0 = blockIdx.x << 7;

    const int sub = (MODE == 0) ? ((n0 % 384) >> 7) : 3;   // 0=q,1=k,2=v
    const bool useAlo = (MODE == 0) && (sub != 2);

    auto load_chunk = [&](int st, int k0) {
        const u32 sb = smb + (u32)st * STAGEB;
#pragma unroll
        for (int rep = 0; rep < 4; rep++) {
            int lin = rep * 256 + tid;
            int row = lin >> 3, u = lin & 7;
            const u32 so = swz(row, u * 16);
            cp_async16(sb + so, Ahi + (size_t)(m0 + row) * 2048 + k0 + u * 8);
            if (useAlo)
                cp_async16(sb + TILEB + so, Alo + (size_t)(m0 + row) * 2048 + k0 + u * 8);
            cp_async16(sb + 2 * TILEB + so, Bhi + (size_t)(n0 + row) * 2048 + k0 + u * 8);
        }
    };

    load_chunk(0, 0);  CP_COMMIT();
    load_chunk(1, 64); CP_COMMIT();

    const u32 aRow = (u32)(wm * 32 + (lane & 15));
    const u32 aSw = (aRow & 7u) << 4;
    const u32 aColSel = (u32)((lane >> 4) << 4);
    u32 aOff[2];
#pragma unroll
    for (int fm = 0; fm < 2; fm++) aOff[fm] = (aRow + fm * 16) * 128u;

    u32 bOff[4], bSw[4];
#pragma unroll
    for (int p = 0; p < 4; p++) {
        u32 brow = (u32)(wn * 64 + p * 16 + ((lane >> 4) << 3) + (lane & 7));
        bOff[p] = brow * 128u;
        bSw[p] = (brow & 7u) << 4;
    }
    const u32 bColSel = (u32)(((lane >> 3) & 1) << 4);

    float acc[2][8][4];
#pragma unroll
    for (int i = 0; i < 2; i++)
#pragma unroll
        for (int j = 0; j < 8; j++)
#pragma unroll
            for (int q = 0; q < 4; q++) acc[i][j][q] = 0.f;

    for (int c = 0; c < NCHUNK; c++) {
        if (c + 1 < NCHUNK) { CP_WAIT1(); } else { CP_WAIT0(); }
        __syncthreads();
        const u32 stage = smb + (u32)(c & 1) * STAGEB;
#pragma unroll
        for (int ks = 0; ks < 4; ks++) {
            const u32 cbA = (u32)(ks * 32) + aColSel;
            const u32 cbB = (u32)(ks * 32) + bColSel;
            u32 ah[2][4], al[2][4], bh[4][4];
#pragma unroll
            for (int fm = 0; fm < 2; fm++)
                ldsm4(ah[fm], stage + aOff[fm] + (cbA ^ aSw));
            if (useAlo) {
#pragma unroll
                for (int fm = 0; fm < 2; fm++)
                    ldsm4(al[fm], stage + TILEB + aOff[fm] + (cbA ^ aSw));
            }
#pragma unroll
            for (int p = 0; p < 4; p++)
                ldsm4(bh[p], stage + 2 * TILEB + bOff[p] + (cbB ^ bSw[p]));
#pragma unroll
            for (int fm = 0; fm < 2; fm++)
#pragma unroll
                for (int p = 0; p < 4; p++)
#pragma unroll
                    for (int q = 0; q < 2; q++)
                        mma16816(acc[fm][p * 2 + q], ah[fm], &bh[p][q * 2]);
            if (useAlo) {
#pragma unroll
                for (int fm = 0; fm < 2; fm++)
#pragma unroll
                    for (int p = 0; p < 4; p++)
#pragma unroll
                        for (int q = 0; q < 2; q++)
                            mma16816(acc[fm][p * 2 + q], al[fm], &bh[p][q * 2]);
            }
        }
        __syncthreads();
        if (c + 2 < NCHUNK) {
            load_chunk(c & 1, (c + 2) * 64);
            CP_COMMIT();
        }
    }

    // epilogue: accum -> smem fp32 (pitch 132), then scatter
    float* S = (float*)dyn_smem;
    const int er = lane >> 2, ec = (lane & 3) << 1;
#pragma unroll
    for (int fm = 0; fm < 2; fm++)
#pragma unroll
        for (int fn = 0; fn < 8; fn++) {
            const int r0 = wm * 32 + fm * 16 + er;
            const int c0 = wn * 64 + fn * 8 + ec;
            S[r0 * 132 + c0] = acc[fm][fn][0];
            S[r0 * 132 + c0 + 1] = acc[fm][fn][1];
            S[(r0 + 8) * 132 + c0] = acc[fm][fn][2];
            S[(r0 + 8) * 132 + c0 + 1] = acc[fm][fn][3];
        }
    __syncthreads();

    const int r = tid >> 1, t2 = tid & 1;
    const int m = m0 + r;
    if (MODE == 0) {
        const int h = n0 / 384;
        const int b = m >> 11, s = m & 2047;
        const size_t doff = ((size_t)(b * H_ + h) * S_ + s) * HD_;
        if (sub == 2) {
            const int cb = t2 * 64;
#pragma unroll
            for (int g = 0; g < 8; g++) {
                u32 hw[4];
#pragma unroll
                for (int p = 0; p < 4; p++) {
                    float x = S[r * 132 + cb + g * 8 + p * 2];
                    float y = S[r * 132 + cb + g * 8 + p * 2 + 1];
                    hw[p] = round_pack(x, y);
                }
                *(uint4*)(g_Vhi + doff + cb + g * 8) = make_uint4(hw[0], hw[1], hw[2], hw[3]);
            }
        } else {
            const float scl = (sub == 0) ? 0.08838834764831845f : 1.0f;
            const float* crow = cs + (size_t)s * HD_;
            const float* srow = sn + (size_t)s * HD_;
#pragma unroll
            for (int g = 0; g < 4; g++) {
                const int cA = t2 * 32 + g * 8;
                const int cB = cA + 64;
                float oa[8], ob[8];
#pragma unroll
                for (int p = 0; p < 4; p++) {
                    const int c0 = cA + p * 2, c1 = cA + p * 2 + 1;
                    float xa0 = S[r * 132 + c0], xa1 = S[r * 132 + c1];
                    float xb0 = S[r * 132 + c0 + 64], xb1 = S[r * 132 + c1 + 64];
                    oa[2*p]   = (xa0 * crow[c0] - xb0 * srow[c0]) * scl;
                    oa[2*p+1] = (xa1 * crow[c1] - xb1 * srow[c1]) * scl;
                    ob[2*p]   = (xb0 * crow[c0 + 64] + xa0 * srow[c0 + 64]) * scl;
                    ob[2*p+1] = (xb1 * crow[c1 + 64] + xa1 * srow[c1 + 64]) * scl;
                }
                if (sub == 0) {
                    // Q: rounded fp16 only
                    u32 hA[4], hB[4];
#pragma unroll
                    for (int p = 0; p < 4; p++) {
                        hA[p] = round_pack(oa[2*p], oa[2*p+1]);
                        hB[p] = round_pack(ob[2*p], ob[2*p+1]);
                    }
                    *(uint4*)(g_Qhi + doff + cA) = make_uint4(hA[0], hA[1], hA[2], hA[3]);
                    *(uint4*)(g_Qhi + doff + cB) = make_uint4(hB[0], hB[1], hB[2], hB[3]);
                } else {
                    // K: split hi/lo
                    u32 hA[4], lA[4], hB[4], lB[4];
#pragma unroll
                    for (int p = 0; p < 4; p++) {
                        hA[p] = split_pack(oa[2*p], oa[2*p+1], lA[p]);
                        hB[p] = split_pack(ob[2*p], ob[2*p+1], lB[p]);
                    }
                    *(uint4*)(g_Khi + doff + cA) = make_uint4(hA[0], hA[1], hA[2], hA[3]);
                    *(uint4*)(g_Klo + doff + cA) = make_uint4(lA[0], lA[1], lA[2], lA[3]);
                    *(uint4*)(g_Khi + doff + cB) = make_uint4(hB[0], hB[1], hB[2], hB[3]);
                    *(uint4*)(g_Klo + doff + cB) = make_uint4(lB[0], lB[1], lB[2], lB[3]);
                }
            }
        }
    } else {
        float* dst = out + (size_t)m * D_ + n0;
        const int cbase = t2 * 64;
#pragma unroll
        for (int q4 = 0; q4 < 16; q4++) {
            float4 w = *(const float4*)(S + r * 132 + cbase + q4 * 4);
            *(float4*)(dst + cbase + q4 * 4) = w;
        }
    }
}

// ---------------------------------------------------------------------------
// Tensor-core causal flash attention.
// QK fp16x2: qhi*khi + qhi*klo (Q rounded, K split). PV fp16x1: phi*vhi.
// LPT: longest q-tiles first. Epilogue emits fp16 (hi only).
// SMEM: Qhi 32K | 2 stages x (Khi|Klo|Vhi = 48K) = 128KB.
// ---------------------------------------------------------------------------
#define ASTG0 32768
#define ASTGB 49152
#define AKLO 16384
#define AVHI 32768
#define ATT_SMEM_BYTES (ASTG0 + 2 * ASTGB)   // 128KB

__device__ __forceinline__ u32 aswz(u32 row, u32 cb) {
    return row * 256u + (cb ^ ((row & 7u) << 4));
}

__global__ void __launch_bounds__(256, 1) attn_mma_kernel()
{
    extern __shared__ char dyn_smem[];
    const u32 smb = smem_u32(dyn_smem);
    const int tid = threadIdx.x, wid = tid >> 5, lane = tid & 31;
    const int qt = (int)gridDim.x - 1 - (int)blockIdx.x;   // LPT: longest first
    const int h = blockIdx.y, b = blockIdx.z;
    const int qg0 = qt << 7;
    const size_t bh = (size_t)(b * H_ + h) * S_;

    {
        const __half* qh = g_Qhi + (bh + qg0) * HD_;
#pragma unroll
        for (int rep = 0; rep < 8; rep++) {
            int lin = rep * 256 + tid;
            int row = lin >> 4, u = lin & 15;
            cp_async16(smb + aswz(row, u * 16), qh + (size_t)row * HD_ + u * 8);
        }
        CP_COMMIT();
    }

    const __half* khg = g_Khi + bh * HD_;
    const __half* klg = g_Klo + bh * HD_;
    const __half* vhg = g_Vhi + bh * HD_;

    auto load_stage = [&](int st, int kg0) {
        const u32 dst = smb + ASTG0 + (u32)st * ASTGB;
        const __half* srcs[3] = {khg + (size_t)kg0 * HD_, klg + (size_t)kg0 * HD_,
                                 vhg + (size_t)kg0 * HD_};
#pragma unroll
        for (int op = 0; op < 3; op++) {
#pragma unroll
            for (int rep = 0; rep < 4; rep++) {
                int lin = rep * 256 + tid;
                int row = lin >> 4, u = lin & 15;
                cp_async16(dst + op * 16384 + aswz(row, u * 16),
                           srcs[op] + (size_t)row * HD_ + u * 8);
            }
        }
    };

    const int nkt = 2 * qt + 2;
    load_stage(0, 0);
    CP_COMMIT();

    const u32 aRow = (u32)(wid * 16 + (lane & 15));
    const u32 aSw = (aRow & 7u) << 4;
    const u32 aCol = (u32)((lane >> 4) << 4);
    const u32 aBase = aRow * 256u;
    const u32 kRow = (u32)(((lane >> 4) << 3) + (lane & 7));
    const u32 kSw = (u32)((lane & 7) << 4);
    const u32 kColT = (u32)(((lane >> 3) & 1) << 4);
    const u32 vRow = (u32)(lane & 15);
    const u32 vColT = (u32)((lane >> 4) << 4);

    u32 qhf[8][4];
    float o[16][4];
#pragma unroll
    for (int f = 0; f < 16; f++)
#pragma unroll
        for (int q = 0; q < 4; q++) o[f][q] = 0.f;
    float m0r = -1e30f, m1r = -1e30f, l0 = 0.f, l1 = 0.f;

    for (int kt = 0; kt < nkt; kt++) {
        if (kt + 1 < nkt) {
            load_stage((kt + 1) & 1, (kt + 1) * 64);
            CP_COMMIT();
            CP_WAIT1();
        } else {
            CP_WAIT0();
        }
        __syncthreads();
        if (kt == 0) {
#pragma unroll
            for (int ks = 0; ks < 8; ks++)
                ldsm4(qhf[ks], smb + aBase + (((u32)(ks * 32) + aCol) ^ aSw));
        }
        const int kg0 = kt * 64;
        const bool skip = kg0 > qg0 + wid * 16 + 15;
        if (!skip) {
            const u32 stg = smb + ASTG0 + (u32)(kt & 1) * ASTGB;
            float s[8][4];
#pragma unroll
            for (int f = 0; f < 8; f++)
#pragma unroll
                for (int q = 0; q < 4; q++) s[f][q] = 0.f;

            // QK^T (fp16x2: qhi*khi + qhi*klo), term-major per ks
#pragma unroll
            for (int ks = 0; ks < 8; ks++) {
                u32 kh[4][4], kl[4][4];
#pragma unroll
                for (int p = 0; p < 4; p++) {
                    u32 addr = stg + (u32)(p * 16 + kRow) * 256u + (((u32)(ks * 32) + kColT) ^ kSw);
                    ldsm4(kh[p], addr);
                    ldsm4(kl[p], addr + AKLO);
                }
#pragma unroll
                for (int p = 0; p < 4; p++) {
                    mma16816(s[2 * p], qhf[ks], &kh[p][0]);
                    mma16816(s[2 * p + 1], qhf[ks], &kh[p][2]);
                }
#pragma unroll
                for (int p = 0; p < 4; p++) {
                    mma16816(s[2 * p], qhf[ks], &kl[p][0]);
                    mma16816(s[2 * p + 1], qhf[ks], &kl[p][2]);
                }
            }

            const int row0 = qg0 + wid * 16 + (lane >> 2);
            if (kg0 + 63 > qg0 + wid * 16) {
#pragma unroll
                for (int f = 0; f < 8; f++) {
                    const int col = kg0 + f * 8 + (lane & 3) * 2;
                    if (col > row0)     s[f][0] = -1e30f;
                    if (col + 1 > row0) s[f][1] = -1e30f;
                    if (col > row0 + 8)     s[f][2] = -1e30f;
                    if (col + 1 > row0 + 8) s[f][3] = -1e30f;
                }
            }

            float mx0 = -1e30f, mx1 = -1e30f;
#pragma unroll
            for (int f = 0; f < 8; f++) {
                mx0 = fmaxf(mx0, fmaxf(s[f][0], s[f][1]));
                mx1 = fmaxf(mx1, fmaxf(s[f][2], s[f][3]));
            }
            mx0 = fmaxf(mx0, __shfl_xor_sync(0xffffffffu, mx0, 1));
            mx0 = fmaxf(mx0, __shfl_xor_sync(0xffffffffu, mx0, 2));
            mx1 = fmaxf(mx1, __shfl_xor_sync(0xffffffffu, mx1, 1));
            mx1 = fmaxf(mx1, __shfl_xor_sync(0xffffffffu, mx1, 2));
            const float mn0 = fmaxf(m0r, mx0), mn1 = fmaxf(m1r, mx1);
            const float al0 = __expf(m0r - mn0), al1 = __expf(m1r - mn1);
            m0r = mn0; m1r = mn1;
            float s0 = 0.f, s1 = 0.f;
#pragma unroll
            for (int f = 0; f < 8; f++) {
                s[f][0] = __expf(s[f][0] - mn0);
                s[f][1] = __expf(s[f][1] - mn0);
                s[f][2] = __expf(s[f][2] - mn1);
                s[f][3] = __expf(s[f][3] - mn1);
                s0 += s[f][0] + s[f][1];
                s1 += s[f][2] + s[f][3];
            }
            s0 += __shfl_xor_sync(0xffffffffu, s0, 1);
            s0 += __shfl_xor_sync(0xffffffffu, s0, 2);
            s1 += __shfl_xor_sync(0xffffffffu, s1, 1);
            s1 += __shfl_xor_sync(0xffffffffu, s1, 2);
            l0 = l0 * al0 + s0;
            l1 = l1 * al1 + s1;
#pragma unroll
            for (int f = 0; f < 16; f++) {
                o[f][0] *= al0; o[f][1] *= al0;
                o[f][2] *= al1; o[f][3] *= al1;
            }

            // P rounded to fp16 A-frags
            u32 ph[4][4];
#pragma unroll
            for (int j = 0; j < 4; j++) {
                ph[j][0] = round_pack(s[2 * j][0], s[2 * j][1]);
                ph[j][1] = round_pack(s[2 * j][2], s[2 * j][3]);
                ph[j][2] = round_pack(s[2 * j + 1][0], s[2 * j + 1][1]);
                ph[j][3] = round_pack(s[2 * j + 1][2], s[2 * j + 1][3]);
            }

            // PV (fp16 single product: phi*vhi), ep-pair grouping
#pragma unroll
            for (int j = 0; j < 4; j++) {
#pragma unroll
                for (int epp = 0; epp < 4; epp++) {
                    u32 vh[2][4];
#pragma unroll
                    for (int e2 = 0; e2 < 2; e2++) {
                        const int ep = epp * 2 + e2;
                        u32 va = stg + AVHI + (u32)(j * 16 + vRow) * 256u + (((u32)(ep * 32) + vColT) ^ kSw);
                        ldsm4t(vh[e2], va);
                    }
                    mma16816(o[4 * epp + 0], ph[j], &vh[0][0]);
                    mma16816(o[4 * epp + 1], ph[j], &vh[0][2]);
                    mma16816(o[4 * epp + 2], ph[j], &vh[1][0]);
                    mma16816(o[4 * epp + 3], ph[j], &vh[1][2]);
                }
            }
        }
        __syncthreads();
    }

    // epilogue: normalize, round to fp16 (hi only), store
    const float inv0 = 1.0f / l0, inv1 = 1.0f / l1;
    const int srow0 = qg0 + wid * 16 + (lane >> 2);
    const size_t ro0 = ((size_t)b * S_ + srow0) * F_ + h * HD_;
    const size_t ro1 = ro0 + (size_t)8 * F_;
#pragma unroll
    for (int f = 0; f < 16; f++) {
        const int e = f * 8 + (lane & 3) * 2;
        *(u32*)(g_AThi + ro0 + e) = round_pack(o[f][0] * inv0, o[f][1] * inv0);
        *(u32*)(g_AThi + ro1 + e) = round_pack(o[f][2] * inv1, o[f][3] * inv1);
    }
}

// ---------------------------------------------------------------------------
extern "C" void kernel_launch(void* const* d_in, const int* in_sizes, int n_in,
                              void* d_out, int out_size)
{
    const float* hs = (const float*)d_in[0];
    const float* cs = (const float*)d_in[1];
    const float* sn = (const float*)d_in[2];
    const float* wq = (const float*)d_in[3];
    const float* wo = (const float*)d_in[4];
    float* out = (float*)d_out;

    cudaFuncSetAttribute(mma_gemm_kernel<0>, cudaFuncAttributeMaxDynamicSharedMemorySize, MMA_SMEM_BYTES);
    cudaFuncSetAttribute(mma_gemm_kernel<1>, cudaFuncAttributeMaxDynamicSharedMemorySize, MMA_SMEM_BYTES);
    cudaFuncSetAttribute(attn_mma_kernel, cudaFuncAttributeMaxDynamicSharedMemorySize, ATT_SMEM_BYTES);

    __half *ahi, *alo, *whi, *wohi, *athi;
    cudaGetSymbolAddress((void**)&ahi, g_Ahi);   cudaGetSymbolAddress((void**)&alo, g_Alo);
    cudaGetSymbolAddress((void**)&whi, g_Whi);
    cudaGetSymbolAddress((void**)&wohi, g_Wohi);
    cudaGetSymbolAddress((void**)&athi, g_AThi);

    {
        int n4 = (M_ * D_) / 4;
        split_f16_kernel<<<(n4 + 255) / 256, 256>>>((const float4*)hs, (uint2*)ahi, (uint2*)alo, n4);
        n4 = (NQKV * D_) / 4;
        round_f16_kernel<<<(n4 + 255) / 256, 256>>>((const float4*)wq, (uint2*)whi, n4);
        n4 = (D_ * F_) / 4;
        round_f16_kernel<<<(n4 + 255) / 256, 256>>>((const float4*)wo, (uint2*)wohi, n4);
    }

    // QKV projection (fp16, 2-prod q/k, 1-prod v) + RoPE
    mma_gemm_kernel<0><<<dim3(NQKV / 128, M_ / 128), 256, MMA_SMEM_BYTES>>>(
        ahi, alo, whi, cs, sn, nullptr);

    // Causal flash attention (QK fp16x2, PV fp16x1) -> g_AThi (fp16)
    attn_mma_kernel<<<dim3(S_ / 128, H_, B_), 256, ATT_SMEM_BYTES>>>();

    // Output projection (fp16 single-product) -> d_out
    mma_gemm_kernel<1><<<dim3(D_ / 128, M_ / 128), 256, MMA_SMEM_BYTES>>>(
        athi, athi, wohi, nullptr, nullptr, out);
}

// round 14
// speedup vs baseline: 2.1851x; 1.2077x over previous
#include <cuda_runtime.h>
#include <cuda_fp16.h>
#include <cstdint>
#include <math.h>

// Problem constants
#define B_   2
#define S_   2048
#define D_   2048
#define H_   16
#define HD_  128
#define M_   (B_ * S_)     // 4096
#define F_   (H_ * HD_)    // 2048
#define NQKV (3 * F_)      // 6144

typedef unsigned long long u64;
typedef unsigned int u32;

__device__ __forceinline__ u32 smem_u32(const void* p) {
    u32 a; asm("{ .reg .u64 t; cvta.to.shared.u64 t, %1; cvt.u32.u64 %0, t; }" : "=r"(a) : "l"(p));
    return a;
}

// ---- mma.sync / ldmatrix / cp.async ----
__device__ __forceinline__ void ldsm4(u32* r, u32 addr) {
    asm volatile("ldmatrix.sync.aligned.m8n8.x4.shared.b16 {%0,%1,%2,%3}, [%4];"
        : "=r"(r[0]), "=r"(r[1]), "=r"(r[2]), "=r"(r[3]) : "r"(addr));
}
__device__ __forceinline__ void ldsm4t(u32* r, u32 addr) {
    asm volatile("ldmatrix.sync.aligned.m8n8.x4.trans.shared.b16 {%0,%1,%2,%3}, [%4];"
        : "=r"(r[0]), "=r"(r[1]), "=r"(r[2]), "=r"(r[3]) : "r"(addr));
}
__device__ __forceinline__ void mma16816(float* d, const u32* a, const u32* b) {
    asm volatile("mma.sync.aligned.m16n8k16.row.col.f32.f16.f16.f32 "
        "{%0,%1,%2,%3}, {%4,%5,%6,%7}, {%8,%9}, {%0,%1,%2,%3};"
        : "+f"(d[0]), "+f"(d[1]), "+f"(d[2]), "+f"(d[3])
        : "r"(a[0]), "r"(a[1]), "r"(a[2]), "r"(a[3]), "r"(b[0]), "r"(b[1]));
}
__device__ __forceinline__ void cp_async16(u32 dst, const void* src) {
    asm volatile("cp.async.cg.shared.global [%0], [%1], 16;" :: "r"(dst), "l"(src));
}
#define CP_COMMIT() asm volatile("cp.async.commit_group;" ::: "memory")
#define CP_WAIT0()  asm volatile("cp.async.wait_group 0;" ::: "memory")
#define CP_WAIT1()  asm volatile("cp.async.wait_group 1;" ::: "memory")
#define CP_WAIT2()  asm volatile("cp.async.wait_group 2;" ::: "memory")

// split f32 pair -> packed f16x2 hi (returned) and lo (out-param)
__device__ __forceinline__ u32 split_pack(float x, float y, u32& lo) {
    float hx = __half2float(__float2half_rn(x));
    float hy = __half2float(__float2half_rn(y));
    u32 hi;
    asm("cvt.rn.f16x2.f32 %0, %1, %2;" : "=r"(hi) : "f"(hy), "f"(hx));
    asm("cvt.rn.f16x2.f32 %0, %1, %2;" : "=r"(lo) : "f"(y - hy), "f"(x - hx));
    return hi;
}
// round f32 pair -> packed f16x2 (hi only)
__device__ __forceinline__ u32 round_pack(float x, float y) {
    u32 hi;
    asm("cvt.rn.f16x2.f32 %0, %1, %2;" : "=r"(hi) : "f"(y), "f"(x));
    return hi;
}

// ---------------- device scratch ----------------
__device__ __half g_Qhi[(size_t)B_ * H_ * S_ * HD_];
__device__ __half g_Khi[(size_t)B_ * H_ * S_ * HD_], g_Klo[(size_t)B_ * H_ * S_ * HD_];
__device__ __half g_Vhi[(size_t)B_ * H_ * S_ * HD_];
__device__ __half g_Ahi[(size_t)M_ * D_];
__device__ __half g_Whi[(size_t)NQKV * D_];
__device__ __half g_Wohi[(size_t)D_ * F_];
__device__ __half g_AThi[(size_t)M_ * F_];

// ---------------------------------------------------------------------------
// Round fp32 -> fp16
// ---------------------------------------------------------------------------
__global__ void round_f16_kernel(const float4* __restrict__ x,
                                 uint2* __restrict__ hi, int n4)
{
    int i = blockIdx.x * blockDim.x + threadIdx.x;
    if (i >= n4) return;
    float4 v = x[i];
    hi[i] = make_uint2(round_pack(v.x, v.y), round_pack(v.z, v.w));
}

// ---------------------------------------------------------------------------
// fp16 single-product GEMM via mma.sync. Tile 128x128, K chunks of 64.
// 8 warps (4m x 2n), warp tile 32x64, 3-stage cp.async pipeline
// (3 x 32KB = 96KB -> 2 CTAs/SM, 2-chunks-ahead prefetch).
//   MODE 0: QKV + RoPE -> Q fp16, K fp16 hi/lo, V fp16.
//   MODE 1: out proj -> fp32 out.
// ---------------------------------------------------------------------------
#define NCHUNK 32
#define TILEB 16384
#define STAGEB (2 * TILEB)                 // 32KB (A,B)
#define MMA_SMEM_BYTES (3 * STAGEB)        // 96KB -> occ 2

__device__ __forceinline__ u32 swz(u32 row, u32 cb) {
    return row * 128u + (cb ^ ((row & 7u) << 4));
}

template <int MODE>
__global__ void __launch_bounds__(256, 2) mma_gemm_kernel(
    const __half* __restrict__ Ahi,
    const __half* __restrict__ Bhi,
    const float* __restrict__ cs, const float* __restrict__ sn,
    float* __restrict__ out)
{
    extern __shared__ char dyn_smem[];
    const u32 smb = smem_u32(dyn_smem);

    const int tid = threadIdx.x;
    const int wid = tid >> 5;
    const int lane = tid & 31;
    const int wm = wid >> 1, wn = wid & 1;   // 4(m) x 2(n) warp grid
    const int m0 = blockIdx.y << 7;
    const int n0 = blockIdx.x << 7;

    auto load_chunk = [&](int st, int k0) {
        const u32 sb = smb + (u32)st * STAGEB;
#pragma unroll
        for (int rep = 0; rep < 4; rep++) {
            int lin = rep * 256 + tid;
            int row = lin >> 3, u = lin & 7;
            const u32 so = swz(row, u * 16);
            cp_async16(sb + so, Ahi + (size_t)(m0 + row) * 2048 + k0 + u * 8);
            cp_async16(sb + TILEB + so, Bhi + (size_t)(n0 + row) * 2048 + k0 + u * 8);
        }
    };

    load_chunk(0, 0);  CP_COMMIT();
    load_chunk(1, 64); CP_COMMIT();

    const u32 aRow = (u32)(wm * 32 + (lane & 15));
    const u32 aSw = (aRow & 7u) << 4;
    const u32 aColSel = (u32)((lane >> 4) << 4);
    u32 aOff[2];
#pragma unroll
    for (int fm = 0; fm < 2; fm++) aOff[fm] = (aRow + fm * 16) * 128u;

    u32 bOff[4], bSw[4];
#pragma unroll
    for (int p = 0; p < 4; p++) {
        u32 brow = (u32)(wn * 64 + p * 16 + ((lane >> 4) << 3) + (lane & 7));
        bOff[p] = brow * 128u;
        bSw[p] = (brow & 7u) << 4;
    }
    const u32 bColSel = (u32)(((lane >> 3) & 1) << 4);

    float acc[2][8][4];
#pragma unroll
    for (int i = 0; i < 2; i++)
#pragma unroll
        for (int j = 0; j < 8; j++)
#pragma unroll
            for (int q = 0; q < 4; q++) acc[i][j][q] = 0.f;

    int stage = 0;
    for (int c = 0; c < NCHUNK; c++) {
        if (c + 2 < NCHUNK) {
            int nst = stage + 2; if (nst >= 3) nst -= 3;
            load_chunk(nst, (c + 2) * 64);
            CP_COMMIT();
            CP_WAIT2();           // chunk c arrived (c+1, c+2 pending)
        } else if (c + 1 < NCHUNK) {
            CP_WAIT1();
        } else {
            CP_WAIT0();
        }
        __syncthreads();
        const u32 stg = smb + (u32)stage * STAGEB;
#pragma unroll
        for (int ks = 0; ks < 4; ks++) {
            const u32 cbA = (u32)(ks * 32) + aColSel;
            const u32 cbB = (u32)(ks * 32) + bColSel;
            u32 ah[2][4], bh[4][4];
#pragma unroll
            for (int fm = 0; fm < 2; fm++)
                ldsm4(ah[fm], stg + aOff[fm] + (cbA ^ aSw));
#pragma unroll
            for (int p = 0; p < 4; p++)
                ldsm4(bh[p], stg + TILEB + bOff[p] + (cbB ^ bSw[p]));
#pragma unroll
            for (int fm = 0; fm < 2; fm++)
#pragma unroll
                for (int p = 0; p < 4; p++)
#pragma unroll
                    for (int q = 0; q < 2; q++)
                        mma16816(acc[fm][p * 2 + q], ah[fm], &bh[p][q * 2]);
        }
        __syncthreads();          // all warps done with stage before it is reloaded
        stage++; if (stage >= 3) stage = 0;
    }

    // epilogue: accum -> smem fp32 (pitch 132), then scatter
    float* S = (float*)dyn_smem;
    const int er = lane >> 2, ec = (lane & 3) << 1;
#pragma unroll
    for (int fm = 0; fm < 2; fm++)
#pragma unroll
        for (int fn = 0; fn < 8; fn++) {
            const int r0 = wm * 32 + fm * 16 + er;
            const int c0 = wn * 64 + fn * 8 + ec;
            S[r0 * 132 + c0] = acc[fm][fn][0];
            S[r0 * 132 + c0 + 1] = acc[fm][fn][1];
            S[(r0 + 8) * 132 + c0] = acc[fm][fn][2];
            S[(r0 + 8) * 132 + c0 + 1] = acc[fm][fn][3];
        }
    __syncthreads();

    const int r = tid >> 1, t2 = tid & 1;
    const int m = m0 + r;
    if (MODE == 0) {
        const int sub = (n0 % 384) >> 7;          // 0=q,1=k,2=v
        const int h = n0 / 384;
        const int b = m >> 11, s = m & 2047;
        const size_t doff = ((size_t)(b * H_ + h) * S_ + s) * HD_;
        if (sub == 2) {
            const int cb = t2 * 64;
#pragma unroll
            for (int g = 0; g < 8; g++) {
                u32 hw[4];
#pragma unroll
                for (int p = 0; p < 4; p++) {
                    float x = S[r * 132 + cb + g * 8 + p * 2];
                    float y = S[r * 132 + cb + g * 8 + p * 2 + 1];
                    hw[p] = round_pack(x, y);
                }
                *(uint4*)(g_Vhi + doff + cb + g * 8) = make_uint4(hw[0], hw[1], hw[2], hw[3]);
            }
        } else {
            const float scl = (sub == 0) ? 0.08838834764831845f : 1.0f;
            const float* crow = cs + (size_t)s * HD_;
            const float* srow = sn + (size_t)s * HD_;
#pragma unroll
            for (int g = 0; g < 4; g++) {
                const int cA = t2 * 32 + g * 8;
                const int cB = cA + 64;
                float oa[8], ob[8];
#pragma unroll
                for (int p = 0; p < 4; p++) {
                    const int c0 = cA + p * 2, c1 = cA + p * 2 + 1;
                    float xa0 = S[r * 132 + c0], xa1 = S[r * 132 + c1];
                    float xb0 = S[r * 132 + c0 + 64], xb1 = S[r * 132 + c1 + 64];
                    oa[2*p]   = (xa0 * crow[c0] - xb0 * srow[c0]) * scl;
                    oa[2*p+1] = (xa1 * crow[c1] - xb1 * srow[c1]) * scl;
                    ob[2*p]   = (xb0 * crow[c0 + 64] + xa0 * srow[c0 + 64]) * scl;
                    ob[2*p+1] = (xb1 * crow[c1 + 64] + xa1 * srow[c1 + 64]) * scl;
                }
                if (sub == 0) {
                    u32 hA[4], hB[4];
#pragma unroll
                    for (int p = 0; p < 4; p++) {
                        hA[p] = round_pack(oa[2*p], oa[2*p+1]);
                        hB[p] = round_pack(ob[2*p], ob[2*p+1]);
                    }
                    *(uint4*)(g_Qhi + doff + cA) = make_uint4(hA[0], hA[1], hA[2], hA[3]);
                    *(uint4*)(g_Qhi + doff + cB) = make_uint4(hB[0], hB[1], hB[2], hB[3]);
                } else {
                    u32 hA[4], lA[4], hB[4], lB[4];
#pragma unroll
                    for (int p = 0; p < 4; p++) {
                        hA[p] = split_pack(oa[2*p], oa[2*p+1], lA[p]);
                        hB[p] = split_pack(ob[2*p], ob[2*p+1], lB[p]);
                    }
                    *(uint4*)(g_Khi + doff + cA) = make_uint4(hA[0], hA[1], hA[2], hA[3]);
                    *(uint4*)(g_Klo + doff + cA) = make_uint4(lA[0], lA[1], lA[2], lA[3]);
                    *(uint4*)(g_Khi + doff + cB) = make_uint4(hB[0], hB[1], hB[2], hB[3]);
                    *(uint4*)(g_Klo + doff + cB) = make_uint4(lB[0], lB[1], lB[2], lB[3]);
                }
            }
        }
    } else {
        float* dst = out + (size_t)m * D_ + n0;
        const int cbase = t2 * 64;
#pragma unroll
        for (int q4 = 0; q4 < 16; q4++) {
            float4 w = *(const float4*)(S + r * 132 + cbase + q4 * 4);
            *(float4*)(dst + cbase + q4 * 4) = w;
        }
    }
}

// ---------------------------------------------------------------------------
// Tensor-core causal flash attention (unchanged from R13).
// QK fp16x2: qhi*khi + qhi*klo. PV fp16x1: phi*vhi.
// LPT: longest q-tiles first. Epilogue emits fp16 (hi only).
// SMEM: Qhi 32K | 2 stages x (Khi|Klo|Vhi = 48K) = 128KB.
// ---------------------------------------------------------------------------
#define ASTG0 32768
#define ASTGB 49152
#define AKLO 16384
#define AVHI 32768
#define ATT_SMEM_BYTES (ASTG0 + 2 * ASTGB)   // 128KB

__device__ __forceinline__ u32 aswz(u32 row, u32 cb) {
    return row * 256u + (cb ^ ((row & 7u) << 4));
}

__global__ void __launch_bounds__(256, 1) attn_mma_kernel()
{
    extern __shared__ char dyn_smem[];
    const u32 smb = smem_u32(dyn_smem);
    const int tid = threadIdx.x, wid = tid >> 5, lane = tid & 31;
    const int qt = (int)gridDim.x - 1 - (int)blockIdx.x;   // LPT: longest first
    const int h = blockIdx.y, b = blockIdx.z;
    const int qg0 = qt << 7;
    const size_t bh = (size_t)(b * H_ + h) * S_;

    {
        const __half* qh = g_Qhi + (bh + qg0) * HD_;
#pragma unroll
        for (int rep = 0; rep < 8; rep++) {
            int lin = rep * 256 + tid;
            int row = lin >> 4, u = lin & 15;
            cp_async16(smb + aswz(row, u * 16), qh + (size_t)row * HD_ + u * 8);
        }
        CP_COMMIT();
    }

    const __half* khg = g_Khi + bh * HD_;
    const __half* klg = g_Klo + bh * HD_;
    const __half* vhg = g_Vhi + bh * HD_;

    auto load_stage = [&](int st, int kg0) {
        const u32 dst = smb + ASTG0 + (u32)st * ASTGB;
        const __half* srcs[3] = {khg + (size_t)kg0 * HD_, klg + (size_t)kg0 * HD_,
                                 vhg + (size_t)kg0 * HD_};
#pragma unroll
        for (int op = 0; op < 3; op++) {
#pragma unroll
            for (int rep = 0; rep < 4; rep++) {
                int lin = rep * 256 + tid;
                int row = lin >> 4, u = lin & 15;
                cp_async16(dst + op * 16384 + aswz(row, u * 16),
                           srcs[op] + (size_t)row * HD_ + u * 8);
            }
        }
    };

    const int nkt = 2 * qt + 2;
    load_stage(0, 0);
    CP_COMMIT();

    const u32 aRow = (u32)(wid * 16 + (lane & 15));
    const u32 aSw = (aRow & 7u) << 4;
    const u32 aCol = (u32)((lane >> 4) << 4);
    const u32 aBase = aRow * 256u;
    const u32 kRow = (u32)(((lane >> 4) << 3) + (lane & 7));
    const u32 kSw = (u32)((lane & 7) << 4);
    const u32 kColT = (u32)(((lane >> 3) & 1) << 4);
    const u32 vRow = (u32)(lane & 15);
    const u32 vColT = (u32)((lane >> 4) << 4);

    u32 qhf[8][4];
    float o[16][4];
#pragma unroll
    for (int f = 0; f < 16; f++)
#pragma unroll
        for (int q = 0; q < 4; q++) o[f][q] = 0.f;
    float m0r = -1e30f, m1r = -1e30f, l0 = 0.f, l1 = 0.f;

    for (int kt = 0; kt < nkt; kt++) {
        if (kt + 1 < nkt) {
            load_stage((kt + 1) & 1, (kt + 1) * 64);
            CP_COMMIT();
            CP_WAIT1();
        } else {
            CP_WAIT0();
        }
        __syncthreads();
        if (kt == 0) {
#pragma unroll
            for (int ks = 0; ks < 8; ks++)
                ldsm4(qhf[ks], smb + aBase + (((u32)(ks * 32) + aCol) ^ aSw));
        }
        const int kg0 = kt * 64;
        const bool skip = kg0 > qg0 + wid * 16 + 15;
        if (!skip) {
            const u32 stg = smb + ASTG0 + (u32)(kt & 1) * ASTGB;
            float s[8][4];
#pragma unroll
            for (int f = 0; f < 8; f++)
#pragma unroll
                for (int q = 0; q < 4; q++) s[f][q] = 0.f;

            // QK^T (fp16x2: qhi*khi + qhi*klo), term-major per ks
#pragma unroll
            for (int ks = 0; ks < 8; ks++) {
                u32 kh[4][4], kl[4][4];
#pragma unroll
                for (int p = 0; p < 4; p++) {
                    u32 addr = stg + (u32)(p * 16 + kRow) * 256u + (((u32)(ks * 32) + kColT) ^ kSw);
                    ldsm4(kh[p], addr);
                    ldsm4(kl[p], addr + AKLO);
                }
#pragma unroll
                for (int p = 0; p < 4; p++) {
                    mma16816(s[2 * p], qhf[ks], &kh[p][0]);
                    mma16816(s[2 * p + 1], qhf[ks], &kh[p][2]);
                }
#pragma unroll
                for (int p = 0; p < 4; p++) {
                    mma16816(s[2 * p], qhf[ks], &kl[p][0]);
                    mma16816(s[2 * p + 1], qhf[ks], &kl[p][2]);
                }
            }

            const int row0 = qg0 + wid * 16 + (lane >> 2);
            if (kg0 + 63 > qg0 + wid * 16) {
#pragma unroll
                for (int f = 0; f < 8; f++) {
                    const int col = kg0 + f * 8 + (lane & 3) * 2;
                    if (col > row0)     s[f][0] = -1e30f;
                    if (col + 1 > row0) s[f][1] = -1e30f;
                    if (col > row0 + 8)     s[f][2] = -1e30f;
                    if (col + 1 > row0 + 8) s[f][3] = -1e30f;
                }
            }

            float mx0 = -1e30f, mx1 = -1e30f;
#pragma unroll
            for (int f = 0; f < 8; f++) {
                mx0 = fmaxf(mx0, fmaxf(s[f][0], s[f][1]));
                mx1 = fmaxf(mx1, fmaxf(s[f][2], s[f][3]));
            }
            mx0 = fmaxf(mx0, __shfl_xor_sync(0xffffffffu, mx0, 1));
            mx0 = fmaxf(mx0, __shfl_xor_sync(0xffffffffu, mx0, 2));
            mx1 = fmaxf(mx1, __shfl_xor_sync(0xffffffffu, mx1, 1));
            mx1 = fmaxf(mx1, __shfl_xor_sync(0xffffffffu, mx1, 2));
            const float mn0 = fmaxf(m0r, mx0), mn1 = fmaxf(m1r, mx1);
            const float al0 = __expf(m0r - mn0), al1 = __expf(m1r - mn1);
            m0r = mn0; m1r = mn1;
            float s0 = 0.f, s1 = 0.f;
#pragma unroll
            for (int f = 0; f < 8; f++) {
                s[f][0] = __expf(s[f][0] - mn0);
                s[f][1] = __expf(s[f][1] - mn0);
                s[f][2] = __expf(s[f][2] - mn1);
                s[f][3] = __expf(s[f][3] - mn1);
                s0 += s[f][0] + s[f][1];
                s1 += s[f][2] + s[f][3];
            }
            s0 += __shfl_xor_sync(0xffffffffu, s0, 1);
            s0 += __shfl_xor_sync(0xffffffffu, s0, 2);
            s1 += __shfl_xor_sync(0xffffffffu, s1, 1);
            s1 += __shfl_xor_sync(0xffffffffu, s1, 2);
            l0 = l0 * al0 + s0;
            l1 = l1 * al1 + s1;
#pragma unroll
            for (int f = 0; f < 16; f++) {
                o[f][0] *= al0; o[f][1] *= al0;
                o[f][2] *= al1; o[f][3] *= al1;
            }

            u32 ph[4][4];
#pragma unroll
            for (int j = 0; j < 4; j++) {
                ph[j][0] = round_pack(s[2 * j][0], s[2 * j][1]);
                ph[j][1] = round_pack(s[2 * j][2], s[2 * j][3]);
                ph[j][2] = round_pack(s[2 * j + 1][0], s[2 * j + 1][1]);
                ph[j][3] = round_pack(s[2 * j + 1][2], s[2 * j + 1][3]);
            }

            // PV (fp16 single product: phi*vhi)
#pragma unroll
            for (int j = 0; j < 4; j++) {
#pragma unroll
                for (int epp = 0; epp < 4; epp++) {
                    u32 vh[2][4];
#pragma unroll
                    for (int e2 = 0; e2 < 2; e2++) {
                        const int ep = epp * 2 + e2;
                        u32 va = stg + AVHI + (u32)(j * 16 + vRow) * 256u + (((u32)(ep * 32) + vColT) ^ kSw);
                        ldsm4t(vh[e2], va);
                    }
                    mma16816(o[4 * epp + 0], ph[j], &vh[0][0]);
                    mma16816(o[4 * epp + 1], ph[j], &vh[0][2]);
                    mma16816(o[4 * epp + 2], ph[j], &vh[1][0]);
                    mma16816(o[4 * epp + 3], ph[j], &vh[1][2]);
                }
            }
        }
        __syncthreads();
    }

    const float inv0 = 1.0f / l0, inv1 = 1.0f / l1;
    const int srow0 = qg0 + wid * 16 + (lane >> 2);
    const size_t ro0 = ((size_t)b * S_ + srow0) * F_ + h * HD_;
    const size_t ro1 = ro0 + (size_t)8 * F_;
#pragma unroll
    for (int f = 0; f < 16; f++) {
        const int e = f * 8 + (lane & 3) * 2;
        *(u32*)(g_AThi + ro0 + e) = round_pack(o[f][0] * inv0, o[f][1] * inv0);
        *(u32*)(g_AThi + ro1 + e) = round_pack(o[f][2] * inv1, o[f][3] * inv1);
    }
}

// ---------------------------------------------------------------------------
extern "C" void kernel_launch(void* const* d_in, const int* in_sizes, int n_in,
                              void* d_out, int out_size)
{
    const float* hs = (const float*)d_in[0];
    const float* cs = (const float*)d_in[1];
    const float* sn = (const float*)d_in[2];
    const float* wq = (const float*)d_in[3];
    const float* wo = (const float*)d_in[4];
    float* out = (float*)d_out;

    cudaFuncSetAttribute(mma_gemm_kernel<0>, cudaFuncAttributeMaxDynamicSharedMemorySize, MMA_SMEM_BYTES);
    cudaFuncSetAttribute(mma_gemm_kernel<1>, cudaFuncAttributeMaxDynamicSharedMemorySize, MMA_SMEM_BYTES);
    cudaFuncSetAttribute(attn_mma_kernel, cudaFuncAttributeMaxDynamicSharedMemorySize, ATT_SMEM_BYTES);

    __half *ahi, *whi, *wohi, *athi;
    cudaGetSymbolAddress((void**)&ahi, g_Ahi);
    cudaGetSymbolAddress((void**)&whi, g_Whi);
    cudaGetSymbolAddress((void**)&wohi, g_Wohi);
    cudaGetSymbolAddress((void**)&athi, g_AThi);

    {
        int n4 = (M_ * D_) / 4;
        round_f16_kernel<<<(n4 + 255) / 256, 256>>>((const float4*)hs, (uint2*)ahi, n4);
        n4 = (NQKV * D_) / 4;
        round_f16_kernel<<<(n4 + 255) / 256, 256>>>((const float4*)wq, (uint2*)whi, n4);
        n4 = (D_ * F_) / 4;
        round_f16_kernel<<<(n4 + 255) / 256, 256>>>((const float4*)wo, (uint2*)wohi, n4);
    }

    // QKV projection (fp16 single-product) + RoPE
    mma_gemm_kernel<0><<<dim3(NQKV / 128, M_ / 128), 256, MMA_SMEM_BYTES>>>(
        ahi, whi, cs, sn, nullptr);

    // Causal flash attention (QK fp16x2, PV fp16x1) -> g_AThi (fp16)
    attn_mma_kernel<<<dim3(S_ / 128, H_, B_), 256, ATT_SMEM_BYTES>>>();

    // Output projection (fp16 single-product) -> d_out
    mma_gemm_kernel<1><<<dim3(D_ / 128, M_ / 128), 256, MMA_SMEM_BYTES>>>(
        athi, wohi, nullptr, nullptr, out);
}

// round 15
// speedup vs baseline: 2.2244x; 1.0179x over previous
#include <cuda_runtime.h>
#include <cuda_fp16.h>
#include <cstdint>
#include <math.h>

// Problem constants
#define B_   2
#define S_   2048
#define D_   2048
#define H_   16
#define HD_  128
#define M_   (B_ * S_)     // 4096
#define F_   (H_ * HD_)    // 2048
#define NQKV (3 * F_)      // 6144

typedef unsigned long long u64;
typedef unsigned int u32;

__device__ __forceinline__ u32 smem_u32(const void* p) {
    u32 a; asm("{ .reg .u64 t; cvta.to.shared.u64 t, %1; cvt.u32.u64 %0, t; }" : "=r"(a) : "l"(p));
    return a;
}

// ---- mma.sync / ldmatrix / cp.async ----
__device__ __forceinline__ void ldsm4(u32* r, u32 addr) {
    asm volatile("ldmatrix.sync.aligned.m8n8.x4.shared.b16 {%0,%1,%2,%3}, [%4];"
        : "=r"(r[0]), "=r"(r[1]), "=r"(r[2]), "=r"(r[3]) : "r"(addr));
}
__device__ __forceinline__ void ldsm4t(u32* r, u32 addr) {
    asm volatile("ldmatrix.sync.aligned.m8n8.x4.trans.shared.b16 {%0,%1,%2,%3}, [%4];"
        : "=r"(r[0]), "=r"(r[1]), "=r"(r[2]), "=r"(r[3]) : "r"(addr));
}
__device__ __forceinline__ void mma16816(float* d, const u32* a, const u32* b) {
    asm volatile("mma.sync.aligned.m16n8k16.row.col.f32.f16.f16.f32 "
        "{%0,%1,%2,%3}, {%4,%5,%6,%7}, {%8,%9}, {%0,%1,%2,%3};"
        : "+f"(d[0]), "+f"(d[1]), "+f"(d[2]), "+f"(d[3])
        : "r"(a[0]), "r"(a[1]), "r"(a[2]), "r"(a[3]), "r"(b[0]), "r"(b[1]));
}
__device__ __forceinline__ void cp_async16(u32 dst, const void* src) {
    asm volatile("cp.async.cg.shared.global [%0], [%1], 16;" :: "r"(dst), "l"(src));
}
#define CP_COMMIT() asm volatile("cp.async.commit_group;" ::: "memory")
#define CP_WAIT0()  asm volatile("cp.async.wait_group 0;" ::: "memory")
#define CP_WAIT1()  asm volatile("cp.async.wait_group 1;" ::: "memory")
#define CP_WAIT2()  asm volatile("cp.async.wait_group 2;" ::: "memory")

// split f32 pair -> packed f16x2 hi (returned) and lo (out-param)
__device__ __forceinline__ u32 split_pack(float x, float y, u32& lo) {
    float hx = __half2float(__float2half_rn(x));
    float hy = __half2float(__float2half_rn(y));
    u32 hi;
    asm("cvt.rn.f16x2.f32 %0, %1, %2;" : "=r"(hi) : "f"(hy), "f"(hx));
    asm("cvt.rn.f16x2.f32 %0, %1, %2;" : "=r"(lo) : "f"(y - hy), "f"(x - hx));
    return hi;
}
// round f32 pair -> packed f16x2 (hi only)
__device__ __forceinline__ u32 round_pack(float x, float y) {
    u32 hi;
    asm("cvt.rn.f16x2.f32 %0, %1, %2;" : "=r"(hi) : "f"(y), "f"(x));
    return hi;
}

// ---------------- device scratch ----------------
__device__ __half g_Qhi[(size_t)B_ * H_ * S_ * HD_];
__device__ __half g_Khi[(size_t)B_ * H_ * S_ * HD_], g_Klo[(size_t)B_ * H_ * S_ * HD_];
__device__ __half g_Vhi[(size_t)B_ * H_ * S_ * HD_];
__device__ __half g_Ahi[(size_t)M_ * D_];
__device__ __half g_Whi[(size_t)NQKV * D_];
__device__ __half g_Wohi[(size_t)D_ * F_];
__device__ __half g_AThi[(size_t)M_ * F_];

// ---------------------------------------------------------------------------
// Round fp32 -> fp16
// ---------------------------------------------------------------------------
__global__ void round_f16_kernel(const float4* __restrict__ x,
                                 uint2* __restrict__ hi, int n4)
{
    int i = blockIdx.x * blockDim.x + threadIdx.x;
    if (i >= n4) return;
    float4 v = x[i];
    hi[i] = make_uint2(round_pack(v.x, v.y), round_pack(v.z, v.w));
}

// ---------------------------------------------------------------------------
// fp16 single-product GEMM via mma.sync. Tile 128x128, K chunks of 64.
// 4 warps (2m x 2n), 128 threads, warp tile 64x64 (8 ldsm : 32 MMA = 1.0
// wavefront/MMA vs 1.5 before -> smem crossbar relief). 3-stage pipeline,
// 96KB, occ 2 (2 x 128thr x ~200regs fits 64K RF).
//   MODE 0: QKV + RoPE -> Q fp16, K fp16 hi/lo, V fp16.
//   MODE 1: out proj -> fp32 out.
// ---------------------------------------------------------------------------
#define NCHUNK 32
#define TILEB 16384
#define STAGEB (2 * TILEB)                 // 32KB (A,B)
#define MMA_SMEM_BYTES (3 * STAGEB)        // 96KB -> occ 2

__device__ __forceinline__ u32 swz(u32 row, u32 cb) {
    return row * 128u + (cb ^ ((row & 7u) << 4));
}

template <int MODE>
__global__ void __launch_bounds__(128, 2) mma_gemm_kernel(
    const __half* __restrict__ Ahi,
    const __half* __restrict__ Bhi,
    const float* __restrict__ cs, const float* __restrict__ sn,
    float* __restrict__ out)
{
    extern __shared__ char dyn_smem[];
    const u32 smb = smem_u32(dyn_smem);

    const int tid = threadIdx.x;
    const int wid = tid >> 5;
    const int lane = tid & 31;
    const int wm = wid >> 1, wn = wid & 1;   // 2(m) x 2(n) warp grid
    const int m0 = blockIdx.y << 7;
    const int n0 = blockIdx.x << 7;

    auto load_chunk = [&](int st, int k0) {
        const u32 sb = smb + (u32)st * STAGEB;
#pragma unroll
        for (int rep = 0; rep < 8; rep++) {
            int lin = rep * 128 + tid;
            int row = lin >> 3, u = lin & 7;
            const u32 so = swz(row, u * 16);
            cp_async16(sb + so, Ahi + (size_t)(m0 + row) * 2048 + k0 + u * 8);
            cp_async16(sb + TILEB + so, Bhi + (size_t)(n0 + row) * 2048 + k0 + u * 8);
        }
    };

    load_chunk(0, 0);  CP_COMMIT();
    load_chunk(1, 64); CP_COMMIT();

    // fragment addressing: A rows wm*64.., B rows wn*64..
    const u32 aRow = (u32)(wm * 64 + (lane & 15));
    const u32 aSw = (aRow & 7u) << 4;
    const u32 aColSel = (u32)((lane >> 4) << 4);
    u32 aOff[4];
#pragma unroll
    for (int fm = 0; fm < 4; fm++) aOff[fm] = (aRow + fm * 16) * 128u;

    u32 bOff[4], bSw[4];
#pragma unroll
    for (int p = 0; p < 4; p++) {
        u32 brow = (u32)(wn * 64 + p * 16 + ((lane >> 4) << 3) + (lane & 7));
        bOff[p] = brow * 128u;
        bSw[p] = (brow & 7u) << 4;
    }
    const u32 bColSel = (u32)(((lane >> 3) & 1) << 4);

    float acc[4][8][4];
#pragma unroll
    for (int i = 0; i < 4; i++)
#pragma unroll
        for (int j = 0; j < 8; j++)
#pragma unroll
            for (int q = 0; q < 4; q++) acc[i][j][q] = 0.f;

    int stage = 0;
    for (int c = 0; c < NCHUNK; c++) {
        if (c + 2 < NCHUNK) {
            int nst = stage + 2; if (nst >= 3) nst -= 3;
            load_chunk(nst, (c + 2) * 64);
            CP_COMMIT();
            CP_WAIT2();
        } else if (c + 1 < NCHUNK) {
            CP_WAIT1();
        } else {
            CP_WAIT0();
        }
        __syncthreads();
        const u32 stg = smb + (u32)stage * STAGEB;
#pragma unroll
        for (int ks = 0; ks < 4; ks++) {
            const u32 cbA = (u32)(ks * 32) + aColSel;
            const u32 cbB = (u32)(ks * 32) + bColSel;
            u32 ah[4][4], bh[4][4];
#pragma unroll
            for (int fm = 0; fm < 4; fm++)
                ldsm4(ah[fm], stg + aOff[fm] + (cbA ^ aSw));
#pragma unroll
            for (int p = 0; p < 4; p++)
                ldsm4(bh[p], stg + TILEB + bOff[p] + (cbB ^ bSw[p]));
#pragma unroll
            for (int fm = 0; fm < 4; fm++)
#pragma unroll
                for (int p = 0; p < 4; p++)
#pragma unroll
                    for (int q = 0; q < 2; q++)
                        mma16816(acc[fm][p * 2 + q], ah[fm], &bh[p][q * 2]);
        }
        __syncthreads();
        stage++; if (stage >= 3) stage = 0;
    }

    // epilogue: accum -> smem fp32 (pitch 132), then scatter (128 threads)
    float* S = (float*)dyn_smem;
    const int er = lane >> 2, ec = (lane & 3) << 1;
#pragma unroll
    for (int fm = 0; fm < 4; fm++)
#pragma unroll
        for (int fn = 0; fn < 8; fn++) {
            const int r0 = wm * 64 + fm * 16 + er;
            const int c0 = wn * 64 + fn * 8 + ec;
            S[r0 * 132 + c0] = acc[fm][fn][0];
            S[r0 * 132 + c0 + 1] = acc[fm][fn][1];
            S[(r0 + 8) * 132 + c0] = acc[fm][fn][2];
            S[(r0 + 8) * 132 + c0 + 1] = acc[fm][fn][3];
        }
    __syncthreads();

    const int r = tid;               // one full row per thread
    const int m = m0 + r;
    if (MODE == 0) {
        const int sub = (n0 % 384) >> 7;          // 0=q,1=k,2=v
        const int h = n0 / 384;
        const int b = m >> 11, s = m & 2047;
        const size_t doff = ((size_t)(b * H_ + h) * S_ + s) * HD_;
        if (sub == 2) {
#pragma unroll
            for (int g = 0; g < 16; g++) {
                u32 hw[4];
#pragma unroll
                for (int p = 0; p < 4; p++) {
                    float x = S[r * 132 + g * 8 + p * 2];
                    float y = S[r * 132 + g * 8 + p * 2 + 1];
                    hw[p] = round_pack(x, y);
                }
                *(uint4*)(g_Vhi + doff + g * 8) = make_uint4(hw[0], hw[1], hw[2], hw[3]);
            }
        } else {
            const float scl = (sub == 0) ? 0.08838834764831845f : 1.0f;
            const float* crow = cs + (size_t)s * HD_;
            const float* srow = sn + (size_t)s * HD_;
#pragma unroll
            for (int g = 0; g < 8; g++) {
                const int cA = g * 8;
                const int cB = cA + 64;
                float oa[8], ob[8];
#pragma unroll
                for (int p = 0; p < 4; p++) {
                    const int c0 = cA + p * 2, c1 = cA + p * 2 + 1;
                    float xa0 = S[r * 132 + c0], xa1 = S[r * 132 + c1];
                    float xb0 = S[r * 132 + c0 + 64], xb1 = S[r * 132 + c1 + 64];
                    oa[2*p]   = (xa0 * crow[c0] - xb0 * srow[c0]) * scl;
                    oa[2*p+1] = (xa1 * crow[c1] - xb1 * srow[c1]) * scl;
                    ob[2*p]   = (xb0 * crow[c0 + 64] + xa0 * srow[c0 + 64]) * scl;
                    ob[2*p+1] = (xb1 * crow[c1 + 64] + xa1 * srow[c1 + 64]) * scl;
                }
                if (sub == 0) {
                    u32 hA[4], hB[4];
#pragma unroll
                    for (int p = 0; p < 4; p++) {
                        hA[p] = round_pack(oa[2*p], oa[2*p+1]);
                        hB[p] = round_pack(ob[2*p], ob[2*p+1]);
                    }
                    *(uint4*)(g_Qhi + doff + cA) = make_uint4(hA[0], hA[1], hA[2], hA[3]);
                    *(uint4*)(g_Qhi + doff + cB) = make_uint4(hB[0], hB[1], hB[2], hB[3]);
                } else {
                    u32 hA[4], lA[4], hB[4], lB[4];
#pragma unroll
                    for (int p = 0; p < 4; p++) {
                        hA[p] = split_pack(oa[2*p], oa[2*p+1], lA[p]);
                        hB[p] = split_pack(ob[2*p], ob[2*p+1], lB[p]);
                    }
                    *(uint4*)(g_Khi + doff + cA) = make_uint4(hA[0], hA[1], hA[2], hA[3]);
                    *(uint4*)(g_Klo + doff + cA) = make_uint4(lA[0], lA[1], lA[2], lA[3]);
                    *(uint4*)(g_Khi + doff + cB) = make_uint4(hB[0], hB[1], hB[2], hB[3]);
                    *(uint4*)(g_Klo + doff + cB) = make_uint4(lB[0], lB[1], lB[2], lB[3]);
                }
            }
        }
    } else {
        float* dst = out + (size_t)m * D_ + n0;
#pragma unroll
        for (int q4 = 0; q4 < 32; q4++) {
            float4 w = *(const float4*)(S + r * 132 + q4 * 4);
            *(float4*)(dst + q4 * 4) = w;
        }
    }
}

// ---------------------------------------------------------------------------
// Tensor-core causal flash attention (unchanged from R14).
// QK fp16x2: qhi*khi + qhi*klo. PV fp16x1: phi*vhi.
// LPT: longest q-tiles first. Epilogue emits fp16 (hi only).
// SMEM: Qhi 32K | 2 stages x (Khi|Klo|Vhi = 48K) = 128KB.
// ---------------------------------------------------------------------------
#define ASTG0 32768
#define ASTGB 49152
#define AKLO 16384
#define AVHI 32768
#define ATT_SMEM_BYTES (ASTG0 + 2 * ASTGB)   // 128KB

__device__ __forceinline__ u32 aswz(u32 row, u32 cb) {
    return row * 256u + (cb ^ ((row & 7u) << 4));
}

__global__ void __launch_bounds__(256, 1) attn_mma_kernel()
{
    extern __shared__ char dyn_smem[];
    const u32 smb = smem_u32(dyn_smem);
    const int tid = threadIdx.x, wid = tid >> 5, lane = tid & 31;
    const int qt = (int)gridDim.x - 1 - (int)blockIdx.x;   // LPT: longest first
    const int h = blockIdx.y, b = blockIdx.z;
    const int qg0 = qt << 7;
    const size_t bh = (size_t)(b * H_ + h) * S_;

    {
        const __half* qh = g_Qhi + (bh + qg0) * HD_;
#pragma unroll
        for (int rep = 0; rep < 8; rep++) {
            int lin = rep * 256 + tid;
            int row = lin >> 4, u = lin & 15;
            cp_async16(smb + aswz(row, u * 16), qh + (size_t)row * HD_ + u * 8);
        }
        CP_COMMIT();
    }

    const __half* khg = g_Khi + bh * HD_;
    const __half* klg = g_Klo + bh * HD_;
    const __half* vhg = g_Vhi + bh * HD_;

    auto load_stage = [&](int st, int kg0) {
        const u32 dst = smb + ASTG0 + (u32)st * ASTGB;
        const __half* srcs[3] = {khg + (size_t)kg0 * HD_, klg + (size_t)kg0 * HD_,
                                 vhg + (size_t)kg0 * HD_};
#pragma unroll
        for (int op = 0; op < 3; op++) {
#pragma unroll
            for (int rep = 0; rep < 4; rep++) {
                int lin = rep * 256 + tid;
                int row = lin >> 4, u = lin & 15;
                cp_async16(dst + op * 16384 + aswz(row, u * 16),
                           srcs[op] + (size_t)row * HD_ + u * 8);
            }
        }
    };

    const int nkt = 2 * qt + 2;
    load_stage(0, 0);
    CP_COMMIT();

    const u32 aRow = (u32)(wid * 16 + (lane & 15));
    const u32 aSw = (aRow & 7u) << 4;
    const u32 aCol = (u32)((lane >> 4) << 4);
    const u32 aBase = aRow * 256u;
    const u32 kRow = (u32)(((lane >> 4) << 3) + (lane & 7));
    const u32 kSw = (u32)((lane & 7) << 4);
    const u32 kColT = (u32)(((lane >> 3) & 1) << 4);
    const u32 vRow = (u32)(lane & 15);
    const u32 vColT = (u32)((lane >> 4) << 4);

    u32 qhf[8][4];
    float o[16][4];
#pragma unroll
    for (int f = 0; f < 16; f++)
#pragma unroll
        for (int q = 0; q < 4; q++) o[f][q] = 0.f;
    float m0r = -1e30f, m1r = -1e30f, l0 = 0.f, l1 = 0.f;

    for (int kt = 0; kt < nkt; kt++) {
        if (kt + 1 < nkt) {
            load_stage((kt + 1) & 1, (kt + 1) * 64);
            CP_COMMIT();
            CP_WAIT1();
        } else {
            CP_WAIT0();
        }
        __syncthreads();
        if (kt == 0) {
#pragma unroll
            for (int ks = 0; ks < 8; ks++)
                ldsm4(qhf[ks], smb + aBase + (((u32)(ks * 32) + aCol) ^ aSw));
        }
        const int kg0 = kt * 64;
        const bool skip = kg0 > qg0 + wid * 16 + 15;
        if (!skip) {
            const u32 stg = smb + ASTG0 + (u32)(kt & 1) * ASTGB;
            float s[8][4];
#pragma unroll
            for (int f = 0; f < 8; f++)
#pragma unroll
                for (int q = 0; q < 4; q++) s[f][q] = 0.f;

#pragma unroll
            for (int ks = 0; ks < 8; ks++) {
                u32 kh[4][4], kl[4][4];
#pragma unroll
                for (int p = 0; p < 4; p++) {
                    u32 addr = stg + (u32)(p * 16 + kRow) * 256u + (((u32)(ks * 32) + kColT) ^ kSw);
                    ldsm4(kh[p], addr);
                    ldsm4(kl[p], addr + AKLO);
                }
#pragma unroll
                for (int p = 0; p < 4; p++) {
                    mma16816(s[2 * p], qhf[ks], &kh[p][0]);
                    mma16816(s[2 * p + 1], qhf[ks], &kh[p][2]);
                }
#pragma unroll
                for (int p = 0; p < 4; p++) {
                    mma16816(s[2 * p], qhf[ks], &kl[p][0]);
                    mma16816(s[2 * p + 1], qhf[ks], &kl[p][2]);
                }
            }

            const int row0 = qg0 + wid * 16 + (lane >> 2);
            if (kg0 + 63 > qg0 + wid * 16) {
#pragma unroll
                for (int f = 0; f < 8; f++) {
                    const int col = kg0 + f * 8 + (lane & 3) * 2;
                    if (col > row0)     s[f][0] = -1e30f;
                    if (col + 1 > row0) s[f][1] = -1e30f;
                    if (col > row0 + 8)     s[f][2] = -1e30f;
                    if (col + 1 > row0 + 8) s[f][3] = -1e30f;
                }
            }

            float mx0 = -1e30f, mx1 = -1e30f;
#pragma unroll
            for (int f = 0; f < 8; f++) {
                mx0 = fmaxf(mx0, fmaxf(s[f][0], s[f][1]));
                mx1 = fmaxf(mx1, fmaxf(s[f][2], s[f][3]));
            }
            mx0 = fmaxf(mx0, __shfl_xor_sync(0xffffffffu, mx0, 1));
            mx0 = fmaxf(mx0, __shfl_xor_sync(0xffffffffu, mx0, 2));
            mx1 = fmaxf(mx1, __shfl_xor_sync(0xffffffffu, mx1, 1));
            mx1 = fmaxf(mx1, __shfl_xor_sync(0xffffffffu, mx1, 2));
            const float mn0 = fmaxf(m0r, mx0), mn1 = fmaxf(m1r, mx1);
            const float al0 = __expf(m0r - mn0), al1 = __expf(m1r - mn1);
            m0r = mn0; m1r = mn1;
            float s0 = 0.f, s1 = 0.f;
#pragma unroll
            for (int f = 0; f < 8; f++) {
                s[f][0] = __expf(s[f][0] - mn0);
                s[f][1] = __expf(s[f][1] - mn0);
                s[f][2] = __expf(s[f][2] - mn1);
                s[f][3] = __expf(s[f][3] - mn1);
                s0 += s[f][0] + s[f][1];
                s1 += s[f][2] + s[f][3];
            }
            s0 += __shfl_xor_sync(0xffffffffu, s0, 1);
            s0 += __shfl_xor_sync(0xffffffffu, s0, 2);
            s1 += __shfl_xor_sync(0xffffffffu, s1, 1);
            s1 += __shfl_xor_sync(0xffffffffu, s1, 2);
            l0 = l0 * al0 + s0;
            l1 = l1 * al1 + s1;
#pragma unroll
            for (int f = 0; f < 16; f++) {
                o[f][0] *= al0; o[f][1] *= al0;
                o[f][2] *= al1; o[f][3] *= al1;
            }

            u32 ph[4][4];
#pragma unroll
            for (int j = 0; j < 4; j++) {
                ph[j][0] = round_pack(s[2 * j][0], s[2 * j][1]);
                ph[j][1] = round_pack(s[2 * j][2], s[2 * j][3]);
                ph[j][2] = round_pack(s[2 * j + 1][0], s[2 * j + 1][1]);
                ph[j][3] = round_pack(s[2 * j + 1][2], s[2 * j + 1][3]);
            }

#pragma unroll
            for (int j = 0; j < 4; j++) {
#pragma unroll
                for (int epp = 0; epp < 4; epp++) {
                    u32 vh[2][4];
#pragma unroll
                    for (int e2 = 0; e2 < 2; e2++) {
                        const int ep = epp * 2 + e2;
                        u32 va = stg + AVHI + (u32)(j * 16 + vRow) * 256u + (((u32)(ep * 32) + vColT) ^ kSw);
                        ldsm4t(vh[e2], va);
                    }
                    mma16816(o[4 * epp + 0], ph[j], &vh[0][0]);
                    mma16816(o[4 * epp + 1], ph[j], &vh[0][2]);
                    mma16816(o[4 * epp + 2], ph[j], &vh[1][0]);
                    mma16816(o[4 * epp + 3], ph[j], &vh[1][2]);
                }
            }
        }
        __syncthreads();
    }

    const float inv0 = 1.0f / l0, inv1 = 1.0f / l1;
    const int srow0 = qg0 + wid * 16 + (lane >> 2);
    const size_t ro0 = ((size_t)b * S_ + srow0) * F_ + h * HD_;
    const size_t ro1 = ro0 + (size_t)8 * F_;
#pragma unroll
    for (int f = 0; f < 16; f++) {
        const int e = f * 8 + (lane & 3) * 2;
        *(u32*)(g_AThi + ro0 + e) = round_pack(o[f][0] * inv0, o[f][1] * inv0);
        *(u32*)(g_AThi + ro1 + e) = round_pack(o[f][2] * inv1, o[f][3] * inv1);
    }
}

// ---------------------------------------------------------------------------
extern "C" void kernel_launch(void* const* d_in, const int* in_sizes, int n_in,
                              void* d_out, int out_size)
{
    const float* hs = (const float*)d_in[0];
    const float* cs = (const float*)d_in[1];
    const float* sn = (const float*)d_in[2];
    const float* wq = (const float*)d_in[3];
    const float* wo = (const float*)d_in[4];
    float* out = (float*)d_out;

    cudaFuncSetAttribute(mma_gemm_kernel<0>, cudaFuncAttributeMaxDynamicSharedMemorySize, MMA_SMEM_BYTES);
    cudaFuncSetAttribute(mma_gemm_kernel<1>, cudaFuncAttributeMaxDynamicSharedMemorySize, MMA_SMEM_BYTES);
    cudaFuncSetAttribute(attn_mma_kernel, cudaFuncAttributeMaxDynamicSharedMemorySize, ATT_SMEM_BYTES);

    __half *ahi, *whi, *wohi, *athi;
    cudaGetSymbolAddress((void**)&ahi, g_Ahi);
    cudaGetSymbolAddress((void**)&whi, g_Whi);
    cudaGetSymbolAddress((void**)&wohi, g_Wohi);
    cudaGetSymbolAddress((void**)&athi, g_AThi);

    {
        int n4 = (M_ * D_) / 4;
        round_f16_kernel<<<(n4 + 255) / 256, 256>>>((const float4*)hs, (uint2*)ahi, n4);
        n4 = (NQKV * D_) / 4;
        round_f16_kernel<<<(n4 + 255) / 256, 256>>>((const float4*)wq, (uint2*)whi, n4);
        n4 = (D_ * F_) / 4;
        round_f16_kernel<<<(n4 + 255) / 256, 256>>>((const float4*)wo, (uint2*)wohi, n4);
    }

    // QKV projection (fp16 single-product, 64x64 warp tiles) + RoPE
    mma_gemm_kernel<0><<<dim3(NQKV / 128, M_ / 128), 128, MMA_SMEM_BYTES>>>(
        ahi, whi, cs, sn, nullptr);

    // Causal flash attention (QK fp16x2, PV fp16x1) -> g_AThi (fp16)
    attn_mma_kernel<<<dim3(S_ / 128, H_, B_), 256, ATT_SMEM_BYTES>>>();

    // Output projection (fp16 single-product) -> d_out
    mma_gemm_kernel<1><<<dim3(D_ / 128, M_ / 128), 128, MMA_SMEM_BYTES>>>(
        athi, wohi, nullptr, nullptr, out);
}

// round 16
// speedup vs baseline: 2.4745x; 1.1125x over previous
#include <cuda_runtime.h>
#include <cuda_fp16.h>
#include <cstdint>
#include <math.h>

// Problem constants
#define B_   2
#define S_   2048
#define D_   2048
#define H_   16
#define HD_  128
#define M_   (B_ * S_)     // 4096
#define F_   (H_ * HD_)    // 2048
#define NQKV (3 * F_)      // 6144

typedef unsigned long long u64;
typedef unsigned int u32;

__device__ __forceinline__ u32 smem_u32(const void* p) {
    u32 a; asm("{ .reg .u64 t; cvta.to.shared.u64 t, %1; cvt.u32.u64 %0, t; }" : "=r"(a) : "l"(p));
    return a;
}

// ---- mma.sync / ldmatrix / cp.async ----
__device__ __forceinline__ void ldsm4(u32* r, u32 addr) {
    asm volatile("ldmatrix.sync.aligned.m8n8.x4.shared.b16 {%0,%1,%2,%3}, [%4];"
        : "=r"(r[0]), "=r"(r[1]), "=r"(r[2]), "=r"(r[3]) : "r"(addr));
}
__device__ __forceinline__ void ldsm4t(u32* r, u32 addr) {
    asm volatile("ldmatrix.sync.aligned.m8n8.x4.trans.shared.b16 {%0,%1,%2,%3}, [%4];"
        : "=r"(r[0]), "=r"(r[1]), "=r"(r[2]), "=r"(r[3]) : "r"(addr));
}
__device__ __forceinline__ void mma16816(float* d, const u32* a, const u32* b) {
    asm volatile("mma.sync.aligned.m16n8k16.row.col.f32.f16.f16.f32 "
        "{%0,%1,%2,%3}, {%4,%5,%6,%7}, {%8,%9}, {%0,%1,%2,%3};"
        : "+f"(d[0]), "+f"(d[1]), "+f"(d[2]), "+f"(d[3])
        : "r"(a[0]), "r"(a[1]), "r"(a[2]), "r"(a[3]), "r"(b[0]), "r"(b[1]));
}
__device__ __forceinline__ void cp_async16(u32 dst, const void* src) {
    asm volatile("cp.async.cg.shared.global [%0], [%1], 16;" :: "r"(dst), "l"(src));
}
#define CP_COMMIT() asm volatile("cp.async.commit_group;" ::: "memory")
#define CP_WAIT0()  asm volatile("cp.async.wait_group 0;" ::: "memory")
#define CP_WAIT1()  asm volatile("cp.async.wait_group 1;" ::: "memory")

// round f32 pair -> packed f16x2
__device__ __forceinline__ u32 round_pack(float x, float y) {
    u32 hi;
    asm("cvt.rn.f16x2.f32 %0, %1, %2;" : "=r"(hi) : "f"(y), "f"(x));
    return hi;
}

// ---------------- device scratch ----------------
__device__ __half g_Qhi[(size_t)B_ * H_ * S_ * HD_];
__device__ __half g_Khi[(size_t)B_ * H_ * S_ * HD_];
__device__ __half g_Vhi[(size_t)B_ * H_ * S_ * HD_];
__device__ __half g_Ahi[(size_t)M_ * D_];
__device__ __half g_Whi[(size_t)NQKV * D_];
__device__ __half g_Wohi[(size_t)D_ * F_];
__device__ __half g_AThi[(size_t)M_ * F_];

// ---------------------------------------------------------------------------
// Merged round fp32 -> fp16 over three tensors (one launch)
// ---------------------------------------------------------------------------
__global__ void round3_f16_kernel(const float4* __restrict__ x0, uint2* __restrict__ h0, int n0,
                                  const float4* __restrict__ x1, uint2* __restrict__ h1, int n1,
                                  const float4* __restrict__ x2, uint2* __restrict__ h2, int n2)
{
    int i = blockIdx.x * blockDim.x + threadIdx.x;
    const float4* src; uint2* dst; int j;
    if (i < n0)           { src = x0; dst = h0; j = i; }
    else if (i < n0 + n1) { src = x1; dst = h1; j = i - n0; }
    else if (i < n0 + n1 + n2) { src = x2; dst = h2; j = i - n0 - n1; }
    else return;
    float4 v = src[j];
    dst[j] = make_uint2(round_pack(v.x, v.y), round_pack(v.z, v.w));
}

// ---------------------------------------------------------------------------
// fp16 single-product GEMM via mma.sync. Tile 128x128, K chunks of 64.
// 4 warps (2m x 2n), 128 threads, warp tile 64x64. 3-stage pipeline, 96KB,
// occ 2. ONE barrier per chunk: wait -> sync -> compute -> prefetch(c+2)
// (safe: 1-iteration warp skew writes stage (c+2)%3 only).
//   MODE 0: QKV + RoPE -> Q/K/V fp16.  MODE 1: out proj -> fp32 out.
// ---------------------------------------------------------------------------
#define NCHUNK 32
#define TILEB 16384
#define STAGEB (2 * TILEB)                 // 32KB (A,B)
#define MMA_SMEM_BYTES (3 * STAGEB)        // 96KB -> occ 2

__device__ __forceinline__ u32 swz(u32 row, u32 cb) {
    return row * 128u + (cb ^ ((row & 7u) << 4));
}

template <int MODE>
__global__ void __launch_bounds__(128, 2) mma_gemm_kernel(
    const __half* __restrict__ Ahi,
    const __half* __restrict__ Bhi,
    const float* __restrict__ cs, const float* __restrict__ sn,
    float* __restrict__ out)
{
    extern __shared__ char dyn_smem[];
    const u32 smb = smem_u32(dyn_smem);

    const int tid = threadIdx.x;
    const int wid = tid >> 5;
    const int lane = tid & 31;
    const int wm = wid >> 1, wn = wid & 1;   // 2(m) x 2(n) warp grid
    const int m0 = blockIdx.y << 7;
    const int n0 = blockIdx.x << 7;

    auto load_chunk = [&](int st, int k0) {
        const u32 sb = smb + (u32)st * STAGEB;
#pragma unroll
        for (int rep = 0; rep < 8; rep++) {
            int lin = rep * 128 + tid;
            int row = lin >> 3, u = lin & 7;
            const u32 so = swz(row, u * 16);
            cp_async16(sb + so, Ahi + (size_t)(m0 + row) * 2048 + k0 + u * 8);
            cp_async16(sb + TILEB + so, Bhi + (size_t)(n0 + row) * 2048 + k0 + u * 8);
        }
    };

    load_chunk(0, 0);  CP_COMMIT();
    load_chunk(1, 64); CP_COMMIT();

    const u32 aRow = (u32)(wm * 64 + (lane & 15));
    const u32 aSw = (aRow & 7u) << 4;
    const u32 aColSel = (u32)((lane >> 4) << 4);
    u32 aOff[4];
#pragma unroll
    for (int fm = 0; fm < 4; fm++) aOff[fm] = (aRow + fm * 16) * 128u;

    u32 bOff[4], bSw[4];
#pragma unroll
    for (int p = 0; p < 4; p++) {
        u32 brow = (u32)(wn * 64 + p * 16 + ((lane >> 4) << 3) + (lane & 7));
        bOff[p] = brow * 128u;
        bSw[p] = (brow & 7u) << 4;
    }
    const u32 bColSel = (u32)(((lane >> 3) & 1) << 4);

    float acc[4][8][4];
#pragma unroll
    for (int i = 0; i < 4; i++)
#pragma unroll
        for (int j = 0; j < 8; j++)
#pragma unroll
            for (int q = 0; q < 4; q++) acc[i][j][q] = 0.f;

    int stage = 0;
    for (int c = 0; c < NCHUNK; c++) {
        if (c + 1 < NCHUNK) { CP_WAIT1(); } else { CP_WAIT0(); }
        __syncthreads();
        const u32 stg = smb + (u32)stage * STAGEB;
#pragma unroll
        for (int ks = 0; ks < 4; ks++) {
            const u32 cbA = (u32)(ks * 32) + aColSel;
            const u32 cbB = (u32)(ks * 32) + bColSel;
            u32 ah[4][4], bh[4][4];
#pragma unroll
            for (int fm = 0; fm < 4; fm++)
                ldsm4(ah[fm], stg + aOff[fm] + (cbA ^ aSw));
#pragma unroll
            for (int p = 0; p < 4; p++)
                ldsm4(bh[p], stg + TILEB + bOff[p] + (cbB ^ bSw[p]));
#pragma unroll
            for (int fm = 0; fm < 4; fm++)
#pragma unroll
                for (int p = 0; p < 4; p++)
#pragma unroll
                    for (int q = 0; q < 2; q++)
                        mma16816(acc[fm][p * 2 + q], ah[fm], &bh[p][q * 2]);
        }
        if (c + 2 < NCHUNK) {
            int nst = stage + 2; if (nst >= 3) nst -= 3;
            load_chunk(nst, (c + 2) * 64);
            CP_COMMIT();
        }
        stage++; if (stage >= 3) stage = 0;
    }
    __syncthreads();   // all warps done reading stages before S overwrites smem

    // epilogue: accum -> smem fp32 (pitch 132), then scatter (128 threads)
    float* S = (float*)dyn_smem;
    const int er = lane >> 2, ec = (lane & 3) << 1;
#pragma unroll
    for (int fm = 0; fm < 4; fm++)
#pragma unroll
        for (int fn = 0; fn < 8; fn++) {
            const int r0 = wm * 64 + fm * 16 + er;
            const int c0 = wn * 64 + fn * 8 + ec;
            S[r0 * 132 + c0] = acc[fm][fn][0];
            S[r0 * 132 + c0 + 1] = acc[fm][fn][1];
            S[(r0 + 8) * 132 + c0] = acc[fm][fn][2];
            S[(r0 + 8) * 132 + c0 + 1] = acc[fm][fn][3];
        }
    __syncthreads();

    const int r = tid;               // one full row per thread
    const int m = m0 + r;
    if (MODE == 0) {
        const int sub = (n0 % 384) >> 7;          // 0=q,1=k,2=v
        const int h = n0 / 384;
        const int b = m >> 11, s = m & 2047;
        const size_t doff = ((size_t)(b * H_ + h) * S_ + s) * HD_;
        if (sub == 2) {
#pragma unroll
            for (int g = 0; g < 16; g++) {
                u32 hw[4];
#pragma unroll
                for (int p = 0; p < 4; p++) {
                    float x = S[r * 132 + g * 8 + p * 2];
                    float y = S[r * 132 + g * 8 + p * 2 + 1];
                    hw[p] = round_pack(x, y);
                }
                *(uint4*)(g_Vhi + doff + g * 8) = make_uint4(hw[0], hw[1], hw[2], hw[3]);
            }
        } else {
            const float scl = (sub == 0) ? 0.08838834764831845f : 1.0f;
            __half* dhi = (sub == 0) ? g_Qhi : g_Khi;
            const float* crow = cs + (size_t)s * HD_;
            const float* srow = sn + (size_t)s * HD_;
#pragma unroll
            for (int g = 0; g < 8; g++) {
                const int cA = g * 8;
                const int cB = cA + 64;
                u32 hA[4], hB[4];
#pragma unroll
                for (int p = 0; p < 4; p++) {
                    const int c0 = cA + p * 2, c1 = cA + p * 2 + 1;
                    float xa0 = S[r * 132 + c0], xa1 = S[r * 132 + c1];
                    float xb0 = S[r * 132 + c0 + 64], xb1 = S[r * 132 + c1 + 64];
                    float oa0 = (xa0 * crow[c0] - xb0 * srow[c0]) * scl;
                    float oa1 = (xa1 * crow[c1] - xb1 * srow[c1]) * scl;
                    float ob0 = (xb0 * crow[c0 + 64] + xa0 * srow[c0 + 64]) * scl;
                    float ob1 = (xb1 * crow[c1 + 64] + xa1 * srow[c1 + 64]) * scl;
                    hA[p] = round_pack(oa0, oa1);
                    hB[p] = round_pack(ob0, ob1);
                }
                *(uint4*)(dhi + doff + cA) = make_uint4(hA[0], hA[1], hA[2], hA[3]);
                *(uint4*)(dhi + doff + cB) = make_uint4(hB[0], hB[1], hB[2], hB[3]);
            }
        }
    } else {
        float* dst = out + (size_t)m * D_ + n0;
#pragma unroll
        for (int q4 = 0; q4 < 32; q4++) {
            float4 w = *(const float4*)(S + r * 132 + q4 * 4);
            *(float4*)(dst + q4 * 4) = w;
        }
    }
}

// ---------------------------------------------------------------------------
// Tensor-core causal flash attention. QK fp16x1, PV fp16x1 (plain fp16).
// 3-stage K/V pipeline (32KB/stage), ONE barrier per kt.
// LPT: longest q-tiles first. SMEM: Qhi 32K | 3 x 32K = 128KB.
// ---------------------------------------------------------------------------
#define ASTG0 32768
#define ASTGB 32768
#define AVHI 16384
#define ATT_SMEM_BYTES (ASTG0 + 3 * ASTGB)   // 128KB

__device__ __forceinline__ u32 aswz(u32 row, u32 cb) {
    return row * 256u + (cb ^ ((row & 7u) << 4));
}

__global__ void __launch_bounds__(256, 1) attn_mma_kernel()
{
    extern __shared__ char dyn_smem[];
    const u32 smb = smem_u32(dyn_smem);
    const int tid = threadIdx.x, wid = tid >> 5, lane = tid & 31;
    const int qt = (int)gridDim.x - 1 - (int)blockIdx.x;   // LPT
    const int h = blockIdx.y, b = blockIdx.z;
    const int qg0 = qt << 7;
    const size_t bh = (size_t)(b * H_ + h) * S_;

    {
        const __half* qh = g_Qhi + (bh + qg0) * HD_;
#pragma unroll
        for (int rep = 0; rep < 8; rep++) {
            int lin = rep * 256 + tid;
            int row = lin >> 4, u = lin & 15;
            cp_async16(smb + aswz(row, u * 16), qh + (size_t)row * HD_ + u * 8);
        }
        CP_COMMIT();
    }

    const __half* khg = g_Khi + bh * HD_;
    const __half* vhg = g_Vhi + bh * HD_;

    auto load_stage = [&](int st, int kg0) {
        const u32 dst = smb + ASTG0 + (u32)st * ASTGB;
        const __half* k = khg + (size_t)kg0 * HD_;
        const __half* v = vhg + (size_t)kg0 * HD_;
#pragma unroll
        for (int rep = 0; rep < 4; rep++) {
            int lin = rep * 256 + tid;
            int row = lin >> 4, u = lin & 15;
            const u32 so = aswz(row, u * 16);
            cp_async16(dst + so, k + (size_t)row * HD_ + u * 8);
            cp_async16(dst + AVHI + so, v + (size_t)row * HD_ + u * 8);
        }
    };

    const int nkt = 2 * qt + 2;
    load_stage(0, 0);
    CP_COMMIT();
    if (1 < nkt) { load_stage(1, 64); CP_COMMIT(); }

    const u32 aRow = (u32)(wid * 16 + (lane & 15));
    const u32 aSw = (aRow & 7u) << 4;
    const u32 aCol = (u32)((lane >> 4) << 4);
    const u32 aBase = aRow * 256u;
    const u32 kRow = (u32)(((lane >> 4) << 3) + (lane & 7));
    const u32 kSw = (u32)((lane & 7) << 4);
    const u32 kColT = (u32)(((lane >> 3) & 1) << 4);
    const u32 vRow = (u32)(lane & 15);
    const u32 vColT = (u32)((lane >> 4) << 4);

    u32 qhf[8][4];
    float o[16][4];
#pragma unroll
    for (int f = 0; f < 16; f++)
#pragma unroll
        for (int q = 0; q < 4; q++) o[f][q] = 0.f;
    float m0r = -1e30f, m1r = -1e30f, l0 = 0.f, l1 = 0.f;

    int stage = 0;
    for (int kt = 0; kt < nkt; kt++) {
        if (kt + 1 < nkt) { CP_WAIT1(); } else { CP_WAIT0(); }
        __syncthreads();
        if (kt == 0) {
#pragma unroll
            for (int ks = 0; ks < 8; ks++)
                ldsm4(qhf[ks], smb + aBase + (((u32)(ks * 32) + aCol) ^ aSw));
        }
        const int kg0 = kt * 64;
        const bool skip = kg0 > qg0 + wid * 16 + 15;
        if (!skip) {
            const u32 stg = smb + ASTG0 + (u32)stage * ASTGB;
            float s[8][4];
#pragma unroll
            for (int f = 0; f < 8; f++)
#pragma unroll
                for (int q = 0; q < 4; q++) s[f][q] = 0.f;

            // QK^T (fp16 single product)
#pragma unroll
            for (int ks = 0; ks < 8; ks++) {
                u32 kh[4][4];
#pragma unroll
                for (int p = 0; p < 4; p++)
                    ldsm4(kh[p], stg + (u32)(p * 16 + kRow) * 256u + (((u32)(ks * 32) + kColT) ^ kSw));
#pragma unroll
                for (int p = 0; p < 4; p++) {
                    mma16816(s[2 * p], qhf[ks], &kh[p][0]);
                    mma16816(s[2 * p + 1], qhf[ks], &kh[p][2]);
                }
            }

            const int row0 = qg0 + wid * 16 + (lane >> 2);
            if (kg0 + 63 > qg0 + wid * 16) {
#pragma unroll
                for (int f = 0; f < 8; f++) {
                    const int col = kg0 + f * 8 + (lane & 3) * 2;
                    if (col > row0)     s[f][0] = -1e30f;
                    if (col + 1 > row0) s[f][1] = -1e30f;
                    if (col > row0 + 8)     s[f][2] = -1e30f;
                    if (col + 1 > row0 + 8) s[f][3] = -1e30f;
                }
            }

            float mx0 = -1e30f, mx1 = -1e30f;
#pragma unroll
            for (int f = 0; f < 8; f++) {
                mx0 = fmaxf(mx0, fmaxf(s[f][0], s[f][1]));
                mx1 = fmaxf(mx1, fmaxf(s[f][2], s[f][3]));
            }
            mx0 = fmaxf(mx0, __shfl_xor_sync(0xffffffffu, mx0, 1));
            mx0 = fmaxf(mx0, __shfl_xor_sync(0xffffffffu, mx0, 2));
            mx1 = fmaxf(mx1, __shfl_xor_sync(0xffffffffu, mx1, 1));
            mx1 = fmaxf(mx1, __shfl_xor_sync(0xffffffffu, mx1, 2));
            const float mn0 = fmaxf(m0r, mx0), mn1 = fmaxf(m1r, mx1);
            const float al0 = __expf(m0r - mn0), al1 = __expf(m1r - mn1);
            m0r = mn0; m1r = mn1;
            float s0 = 0.f, s1 = 0.f;
#pragma unroll
            for (int f = 0; f < 8; f++) {
                s[f][0] = __expf(s[f][0] - mn0);
                s[f][1] = __expf(s[f][1] - mn0);
                s[f][2] = __expf(s[f][2] - mn1);
                s[f][3] = __expf(s[f][3] - mn1);
                s0 += s[f][0] + s[f][1];
                s1 += s[f][2] + s[f][3];
            }
            s0 += __shfl_xor_sync(0xffffffffu, s0, 1);
            s0 += __shfl_xor_sync(0xffffffffu, s0, 2);
            s1 += __shfl_xor_sync(0xffffffffu, s1, 1);
            s1 += __shfl_xor_sync(0xffffffffu, s1, 2);
            l0 = l0 * al0 + s0;
            l1 = l1 * al1 + s1;
#pragma unroll
            for (int f = 0; f < 16; f++) {
                o[f][0] *= al0; o[f][1] *= al0;
                o[f][2] *= al1; o[f][3] *= al1;
            }

            u32 ph[4][4];
#pragma unroll
            for (int j = 0; j < 4; j++) {
                ph[j][0] = round_pack(s[2 * j][0], s[2 * j][1]);
                ph[j][1] = round_pack(s[2 * j][2], s[2 * j][3]);
                ph[j][2] = round_pack(s[2 * j + 1][0], s[2 * j + 1][1]);
                ph[j][3] = round_pack(s[2 * j + 1][2], s[2 * j + 1][3]);
            }

            // PV (fp16 single product)
#pragma unroll
            for (int j = 0; j < 4; j++) {
#pragma unroll
                for (int epp = 0; epp < 4; epp++) {
                    u32 vh[2][4];
#pragma unroll
                    for (int e2 = 0; e2 < 2; e2++) {
                        const int ep = epp * 2 + e2;
                        ldsm4t(vh[e2], stg + AVHI + (u32)(j * 16 + vRow) * 256u + (((u32)(ep * 32) + vColT) ^ kSw));
                    }
                    mma16816(o[4 * epp + 0], ph[j], &vh[0][0]);
                    mma16816(o[4 * epp + 1], ph[j], &vh[0][2]);
                    mma16816(o[4 * epp + 2], ph[j], &vh[1][0]);
                    mma16816(o[4 * epp + 3], ph[j], &vh[1][2]);
                }
            }
        }
        // prefetch kt+2 into stage+2 (distinct from any stage being read at <=1 skew)
        if (kt + 2 < nkt) {
            int nst = stage + 2; if (nst >= 3) nst -= 3;
            load_stage(nst, (kt + 2) * 64);
            CP_COMMIT();
        }
        stage++; if (stage >= 3) stage = 0;
    }

    const float inv0 = 1.0f / l0, inv1 = 1.0f / l1;
    const int srow0 = qg0 + wid * 16 + (lane >> 2);
    const size_t ro0 = ((size_t)b * S_ + srow0) * F_ + h * HD_;
    const size_t ro1 = ro0 + (size_t)8 * F_;
#pragma unroll
    for (int f = 0; f < 16; f++) {
        const int e = f * 8 + (lane & 3) * 2;
        *(u32*)(g_AThi + ro0 + e) = round_pack(o[f][0] * inv0, o[f][1] * inv0);
        *(u32*)(g_AThi + ro1 + e) = round_pack(o[f][2] * inv1, o[f][3] * inv1);
    }
}

// ---------------------------------------------------------------------------
extern "C" void kernel_launch(void* const* d_in, const int* in_sizes, int n_in,
                              void* d_out, int out_size)
{
    const float* hs = (const float*)d_in[0];
    const float* cs = (const float*)d_in[1];
    const float* sn = (const float*)d_in[2];
    const float* wq = (const float*)d_in[3];
    const float* wo = (const float*)d_in[4];
    float* out = (float*)d_out;

    cudaFuncSetAttribute(mma_gemm_kernel<0>, cudaFuncAttributeMaxDynamicSharedMemorySize, MMA_SMEM_BYTES);
    cudaFuncSetAttribute(mma_gemm_kernel<1>, cudaFuncAttributeMaxDynamicSharedMemorySize, MMA_SMEM_BYTES);
    cudaFuncSetAttribute(attn_mma_kernel, cudaFuncAttributeMaxDynamicSharedMemorySize, ATT_SMEM_BYTES);

    __half *ahi, *whi, *wohi, *athi;
    cudaGetSymbolAddress((void**)&ahi, g_Ahi);
    cudaGetSymbolAddress((void**)&whi, g_Whi);
    cudaGetSymbolAddress((void**)&wohi, g_Wohi);
    cudaGetSymbolAddress((void**)&athi, g_AThi);

    {
        const int n0 = (M_ * D_) / 4, n1 = (NQKV * D_) / 4, n2 = (D_ * F_) / 4;
        const int nt = n0 + n1 + n2;
        round3_f16_kernel<<<(nt + 255) / 256, 256>>>(
            (const float4*)hs, (uint2*)ahi, n0,
            (const float4*)wq, (uint2*)whi, n1,
            (const float4*)wo, (uint2*)wohi, n2);
    }

    // QKV projection (fp16 single-product, 64x64 warp tiles) + RoPE
    mma_gemm_kernel<0><<<dim3(NQKV / 128, M_ / 128), 128, MMA_SMEM_BYTES>>>(
        ahi, whi, cs, sn, nullptr);

    // Causal flash attention (fp16) -> g_AThi (fp16)
    attn_mma_kernel<<<dim3(S_ / 128, H_, B_), 256, ATT_SMEM_BYTES>>>();

    // Output projection (fp16 single-product) -> d_out
    mma_gemm_kernel<1><<<dim3(D_ / 128, M_ / 128), 128, MMA_SMEM_BYTES>>>(
        athi, wohi, nullptr, nullptr, out);
}

// round 17
// speedup vs baseline: 2.4747x; 1.0001x over previous
#include <cuda_runtime.h>
#include <cuda_fp16.h>
#include <cstdint>
#include <math.h>

// Problem constants
#define B_   2
#define S_   2048
#define D_   2048
#define H_   16
#define HD_  128
#define M_   (B_ * S_)     // 4096
#define F_   (H_ * HD_)    // 2048
#define NQKV (3 * F_)      // 6144

typedef unsigned long long u64;
typedef unsigned int u32;

__device__ __forceinline__ u32 smem_u32(const void* p) {
    u32 a; asm("{ .reg .u64 t; cvta.to.shared.u64 t, %1; cvt.u32.u64 %0, t; }" : "=r"(a) : "l"(p));
    return a;
}

// ---- mma.sync / ldmatrix / cp.async ----
__device__ __forceinline__ void ldsm4(u32* r, u32 addr) {
    asm volatile("ldmatrix.sync.aligned.m8n8.x4.shared.b16 {%0,%1,%2,%3}, [%4];"
        : "=r"(r[0]), "=r"(r[1]), "=r"(r[2]), "=r"(r[3]) : "r"(addr));
}
__device__ __forceinline__ void ldsm4t(u32* r, u32 addr) {
    asm volatile("ldmatrix.sync.aligned.m8n8.x4.trans.shared.b16 {%0,%1,%2,%3}, [%4];"
        : "=r"(r[0]), "=r"(r[1]), "=r"(r[2]), "=r"(r[3]) : "r"(addr));
}
__device__ __forceinline__ void mma16816(float* d, const u32* a, const u32* b) {
    asm volatile("mma.sync.aligned.m16n8k16.row.col.f32.f16.f16.f32 "
        "{%0,%1,%2,%3}, {%4,%5,%6,%7}, {%8,%9}, {%0,%1,%2,%3};"
        : "+f"(d[0]), "+f"(d[1]), "+f"(d[2]), "+f"(d[3])
        : "r"(a[0]), "r"(a[1]), "r"(a[2]), "r"(a[3]), "r"(b[0]), "r"(b[1]));
}
__device__ __forceinline__ void cp_async16(u32 dst, const void* src) {
    asm volatile("cp.async.cg.shared.global [%0], [%1], 16;" :: "r"(dst), "l"(src));
}
#define CP_COMMIT() asm volatile("cp.async.commit_group;" ::: "memory")
#define CP_WAIT0()  asm volatile("cp.async.wait_group 0;" ::: "memory")
#define CP_WAIT1()  asm volatile("cp.async.wait_group 1;" ::: "memory")

// round f32 pair -> packed f16x2
__device__ __forceinline__ u32 round_pack(float x, float y) {
    u32 hi;
    asm("cvt.rn.f16x2.f32 %0, %1, %2;" : "=r"(hi) : "f"(y), "f"(x));
    return hi;
}

// ---------------- device scratch ----------------
__device__ __half g_Qhi[(size_t)B_ * H_ * S_ * HD_];
__device__ __half g_Khi[(size_t)B_ * H_ * S_ * HD_];
__device__ __half g_Vhi[(size_t)B_ * H_ * S_ * HD_];
__device__ __half g_Ahi[(size_t)M_ * D_];
__device__ __half g_Whi[(size_t)NQKV * D_];
__device__ __half g_Wohi[(size_t)D_ * F_];
__device__ __half g_AThi[(size_t)M_ * F_];

// ---------------------------------------------------------------------------
// Merged round fp32 -> fp16 over three tensors (one launch)
// ---------------------------------------------------------------------------
__global__ void round3_f16_kernel(const float4* __restrict__ x0, uint2* __restrict__ h0, int n0,
                                  const float4* __restrict__ x1, uint2* __restrict__ h1, int n1,
                                  const float4* __restrict__ x2, uint2* __restrict__ h2, int n2)
{
    int i = blockIdx.x * blockDim.x + threadIdx.x;
    const float4* src; uint2* dst; int j;
    if (i < n0)           { src = x0; dst = h0; j = i; }
    else if (i < n0 + n1) { src = x1; dst = h1; j = i - n0; }
    else if (i < n0 + n1 + n2) { src = x2; dst = h2; j = i - n0 - n1; }
    else return;
    float4 v = src[j];
    dst[j] = make_uint2(round_pack(v.x, v.y), round_pack(v.z, v.w));
}

// ---------------------------------------------------------------------------
// fp16 single-product GEMM via mma.sync. Tile 128x128, K chunks of 64.
// 4 warps (2m x 2n), 128 threads, warp tile 64x64. 3-stage pipeline, 96KB,
// occ 2, one barrier per chunk. Explicit fragment double-buffering:
// ldsm(ks+1) overlaps the 32 MMAs of ks (breaks the LDS-latency serial head).
//   MODE 0: QKV + RoPE -> Q/K/V fp16.  MODE 1: out proj -> fp32 out.
// ---------------------------------------------------------------------------
#define NCHUNK 32
#define TILEB 16384
#define STAGEB (2 * TILEB)                 // 32KB (A,B)
#define MMA_SMEM_BYTES (3 * STAGEB)        // 96KB -> occ 2

__device__ __forceinline__ u32 swz(u32 row, u32 cb) {
    return row * 128u + (cb ^ ((row & 7u) << 4));
}

template <int MODE>
__global__ void __launch_bounds__(128, 2) mma_gemm_kernel(
    const __half* __restrict__ Ahi,
    const __half* __restrict__ Bhi,
    const float* __restrict__ cs, const float* __restrict__ sn,
    float* __restrict__ out)
{
    extern __shared__ char dyn_smem[];
    const u32 smb = smem_u32(dyn_smem);

    const int tid = threadIdx.x;
    const int wid = tid >> 5;
    const int lane = tid & 31;
    const int wm = wid >> 1, wn = wid & 1;   // 2(m) x 2(n) warp grid
    const int m0 = blockIdx.y << 7;
    const int n0 = blockIdx.x << 7;

    auto load_chunk = [&](int st, int k0) {
        const u32 sb = smb + (u32)st * STAGEB;
#pragma unroll
        for (int rep = 0; rep < 8; rep++) {
            int lin = rep * 128 + tid;
            int row = lin >> 3, u = lin & 7;
            const u32 so = swz(row, u * 16);
            cp_async16(sb + so, Ahi + (size_t)(m0 + row) * 2048 + k0 + u * 8);
            cp_async16(sb + TILEB + so, Bhi + (size_t)(n0 + row) * 2048 + k0 + u * 8);
        }
    };

    load_chunk(0, 0);  CP_COMMIT();
    load_chunk(1, 64); CP_COMMIT();

    const u32 aRow = (u32)(wm * 64 + (lane & 15));
    const u32 aSw = (aRow & 7u) << 4;
    const u32 aColSel = (u32)((lane >> 4) << 4);
    u32 aOff[4];
#pragma unroll
    for (int fm = 0; fm < 4; fm++) aOff[fm] = (aRow + fm * 16) * 128u;

    u32 bOff[4], bSw[4];
#pragma unroll
    for (int p = 0; p < 4; p++) {
        u32 brow = (u32)(wn * 64 + p * 16 + ((lane >> 4) << 3) + (lane & 7));
        bOff[p] = brow * 128u;
        bSw[p] = (brow & 7u) << 4;
    }
    const u32 bColSel = (u32)(((lane >> 3) & 1) << 4);

    float acc[4][8][4];
#pragma unroll
    for (int i = 0; i < 4; i++)
#pragma unroll
        for (int j = 0; j < 8; j++)
#pragma unroll
            for (int q = 0; q < 4; q++) acc[i][j][q] = 0.f;

    u32 ahf[2][4][4], bhf[2][4][4];   // fragment double buffer

    int stage = 0;
    for (int c = 0; c < NCHUNK; c++) {
        if (c + 1 < NCHUNK) { CP_WAIT1(); } else { CP_WAIT0(); }
        __syncthreads();
        const u32 stg = smb + (u32)stage * STAGEB;

        // load frags for ks=0 into buffer 0
        {
            const u32 cbA = aColSel, cbB = bColSel;
#pragma unroll
            for (int fm = 0; fm < 4; fm++)
                ldsm4(ahf[0][fm], stg + aOff[fm] + (cbA ^ aSw));
#pragma unroll
            for (int p = 0; p < 4; p++)
                ldsm4(bhf[0][p], stg + TILEB + bOff[p] + (cbB ^ bSw[p]));
        }
#pragma unroll
        for (int ks = 0; ks < 4; ks++) {
            const int cur = ks & 1, nxt = cur ^ 1;
            if (ks < 3) {
                const u32 cbA = (u32)((ks + 1) * 32) + aColSel;
                const u32 cbB = (u32)((ks + 1) * 32) + bColSel;
#pragma unroll
                for (int fm = 0; fm < 4; fm++)
                    ldsm4(ahf[nxt][fm], stg + aOff[fm] + (cbA ^ aSw));
#pragma unroll
                for (int p = 0; p < 4; p++)
                    ldsm4(bhf[nxt][p], stg + TILEB + bOff[p] + (cbB ^ bSw[p]));
            }
#pragma unroll
            for (int fm = 0; fm < 4; fm++)
#pragma unroll
                for (int p = 0; p < 4; p++)
#pragma unroll
                    for (int q = 0; q < 2; q++)
                        mma16816(acc[fm][p * 2 + q], ahf[cur][fm], &bhf[cur][p][q * 2]);
        }
        if (c + 2 < NCHUNK) {
            int nst = stage + 2; if (nst >= 3) nst -= 3;
            load_chunk(nst, (c + 2) * 64);
            CP_COMMIT();
        }
        stage++; if (stage >= 3) stage = 0;
    }
    __syncthreads();   // all warps done reading stages before S overwrites smem

    // epilogue: accum -> smem fp32 (pitch 132), then scatter (128 threads)
    float* S = (float*)dyn_smem;
    const int er = lane >> 2, ec = (lane & 3) << 1;
#pragma unroll
    for (int fm = 0; fm < 4; fm++)
#pragma unroll
        for (int fn = 0; fn < 8; fn++) {
            const int r0 = wm * 64 + fm * 16 + er;
            const int c0 = wn * 64 + fn * 8 + ec;
            S[r0 * 132 + c0] = acc[fm][fn][0];
            S[r0 * 132 + c0 + 1] = acc[fm][fn][1];
            S[(r0 + 8) * 132 + c0] = acc[fm][fn][2];
            S[(r0 + 8) * 132 + c0 + 1] = acc[fm][fn][3];
        }
    __syncthreads();

    const int r = tid;               // one full row per thread
    const int m = m0 + r;
    if (MODE == 0) {
        const int sub = (n0 % 384) >> 7;          // 0=q,1=k,2=v
        const int h = n0 / 384;
        const int b = m >> 11, s = m & 2047;
        const size_t doff = ((size_t)(b * H_ + h) * S_ + s) * HD_;
        if (sub == 2) {
#pragma unroll
            for (int g = 0; g < 16; g++) {
                u32 hw[4];
#pragma unroll
                for (int p = 0; p < 4; p++) {
                    float x = S[r * 132 + g * 8 + p * 2];
                    float y = S[r * 132 + g * 8 + p * 2 + 1];
                    hw[p] = round_pack(x, y);
                }
                *(uint4*)(g_Vhi + doff + g * 8) = make_uint4(hw[0], hw[1], hw[2], hw[3]);
            }
        } else {
            const float scl = (sub == 0) ? 0.08838834764831845f : 1.0f;
            __half* dhi = (sub == 0) ? g_Qhi : g_Khi;
            const float* crow = cs + (size_t)s * HD_;
            const float* srow = sn + (size_t)s * HD_;
#pragma unroll
            for (int g = 0; g < 8; g++) {
                const int cA = g * 8;
                const int cB = cA + 64;
                u32 hA[4], hB[4];
#pragma unroll
                for (int p = 0; p < 4; p++) {
                    const int c0 = cA + p * 2, c1 = cA + p * 2 + 1;
                    float xa0 = S[r * 132 + c0], xa1 = S[r * 132 + c1];
                    float xb0 = S[r * 132 + c0 + 64], xb1 = S[r * 132 + c1 + 64];
                    float oa0 = (xa0 * crow[c0] - xb0 * srow[c0]) * scl;
                    float oa1 = (xa1 * crow[c1] - xb1 * srow[c1]) * scl;
                    float ob0 = (xb0 * crow[c0 + 64] + xa0 * srow[c0 + 64]) * scl;
                    float ob1 = (xb1 * crow[c1 + 64] + xa1 * srow[c1 + 64]) * scl;
                    hA[p] = round_pack(oa0, oa1);
                    hB[p] = round_pack(ob0, ob1);
                }
                *(uint4*)(dhi + doff + cA) = make_uint4(hA[0], hA[1], hA[2], hA[3]);
                *(uint4*)(dhi + doff + cB) = make_uint4(hB[0], hB[1], hB[2], hB[3]);
            }
        }
    } else {
        float* dst = out + (size_t)m * D_ + n0;
#pragma unroll
        for (int q4 = 0; q4 < 32; q4++) {
            float4 w = *(const float4*)(S + r * 132 + q4 * 4);
            *(float4*)(dst + q4 * 4) = w;
        }
    }
}

// ---------------------------------------------------------------------------
// Tensor-core causal flash attention (unchanged from R16).
// QK fp16x1, PV fp16x1. 3-stage K/V pipeline, one barrier per kt. LPT.
// SMEM: Qhi 32K | 3 x 32K = 128KB.
// ---------------------------------------------------------------------------
#define ASTG0 32768
#define ASTGB 32768
#define AVHI 16384
#define ATT_SMEM_BYTES (ASTG0 + 3 * ASTGB)   // 128KB

__device__ __forceinline__ u32 aswz(u32 row, u32 cb) {
    return row * 256u + (cb ^ ((row & 7u) << 4));
}

__global__ void __launch_bounds__(256, 1) attn_mma_kernel()
{
    extern __shared__ char dyn_smem[];
    const u32 smb = smem_u32(dyn_smem);
    const int tid = threadIdx.x, wid = tid >> 5, lane = tid & 31;
    const int qt = (int)gridDim.x - 1 - (int)blockIdx.x;   // LPT
    const int h = blockIdx.y, b = blockIdx.z;
    const int qg0 = qt << 7;
    const size_t bh = (size_t)(b * H_ + h) * S_;

    {
        const __half* qh = g_Qhi + (bh + qg0) * HD_;
#pragma unroll
        for (int rep = 0; rep < 8; rep++) {
            int lin = rep * 256 + tid;
            int row = lin >> 4, u = lin & 15;
            cp_async16(smb + aswz(row, u * 16), qh + (size_t)row * HD_ + u * 8);
        }
        CP_COMMIT();
    }

    const __half* khg = g_Khi + bh * HD_;
    const __half* vhg = g_Vhi + bh * HD_;

    auto load_stage = [&](int st, int kg0) {
        const u32 dst = smb + ASTG0 + (u32)st * ASTGB;
        const __half* k = khg + (size_t)kg0 * HD_;
        const __half* v = vhg + (size_t)kg0 * HD_;
#pragma unroll
        for (int rep = 0; rep < 4; rep++) {
            int lin = rep * 256 + tid;
            int row = lin >> 4, u = lin & 15;
            const u32 so = aswz(row, u * 16);
            cp_async16(dst + so, k + (size_t)row * HD_ + u * 8);
            cp_async16(dst + AVHI + so, v + (size_t)row * HD_ + u * 8);
        }
    };

    const int nkt = 2 * qt + 2;
    load_stage(0, 0);
    CP_COMMIT();
    if (1 < nkt) { load_stage(1, 64); CP_COMMIT(); }

    const u32 aRow = (u32)(wid * 16 + (lane & 15));
    const u32 aSw = (aRow & 7u) << 4;
    const u32 aCol = (u32)((lane >> 4) << 4);
    const u32 aBase = aRow * 256u;
    const u32 kRow = (u32)(((lane >> 4) << 3) + (lane & 7));
    const u32 kSw = (u32)((lane & 7) << 4);
    const u32 kColT = (u32)(((lane >> 3) & 1) << 4);
    const u32 vRow = (u32)(lane & 15);
    const u32 vColT = (u32)((lane >> 4) << 4);

    u32 qhf[8][4];
    float o[16][4];
#pragma unroll
    for (int f = 0; f < 16; f++)
#pragma unroll
        for (int q = 0; q < 4; q++) o[f][q] = 0.f;
    float m0r = -1e30f, m1r = -1e30f, l0 = 0.f, l1 = 0.f;

    int stage = 0;
    for (int kt = 0; kt < nkt; kt++) {
        if (kt + 1 < nkt) { CP_WAIT1(); } else { CP_WAIT0(); }
        __syncthreads();
        if (kt == 0) {
#pragma unroll
            for (int ks = 0; ks < 8; ks++)
                ldsm4(qhf[ks], smb + aBase + (((u32)(ks * 32) + aCol) ^ aSw));
        }
        const int kg0 = kt * 64;
        const bool skip = kg0 > qg0 + wid * 16 + 15;
        if (!skip) {
            const u32 stg = smb + ASTG0 + (u32)stage * ASTGB;
            float s[8][4];
#pragma unroll
            for (int f = 0; f < 8; f++)
#pragma unroll
                for (int q = 0; q < 4; q++) s[f][q] = 0.f;

#pragma unroll
            for (int ks = 0; ks < 8; ks++) {
                u32 kh[4][4];
#pragma unroll
                for (int p = 0; p < 4; p++)
                    ldsm4(kh[p], stg + (u32)(p * 16 + kRow) * 256u + (((u32)(ks * 32) + kColT) ^ kSw));
#pragma unroll
                for (int p = 0; p < 4; p++) {
                    mma16816(s[2 * p], qhf[ks], &kh[p][0]);
                    mma16816(s[2 * p + 1], qhf[ks], &kh[p][2]);
                }
            }

            const int row0 = qg0 + wid * 16 + (lane >> 2);
            if (kg0 + 63 > qg0 + wid * 16) {
#pragma unroll
                for (int f = 0; f < 8; f++) {
                    const int col = kg0 + f * 8 + (lane & 3) * 2;
                    if (col > row0)     s[f][0] = -1e30f;
                    if (col + 1 > row0) s[f][1] = -1e30f;
                    if (col > row0 + 8)     s[f][2] = -1e30f;
                    if (col + 1 > row0 + 8) s[f][3] = -1e30f;
                }
            }

            float mx0 = -1e30f, mx1 = -1e30f;
#pragma unroll
            for (int f = 0; f < 8; f++) {
                mx0 = fmaxf(mx0, fmaxf(s[f][0], s[f][1]));
                mx1 = fmaxf(mx1, fmaxf(s[f][2], s[f][3]));
            }
            mx0 = fmaxf(mx0, __shfl_xor_sync(0xffffffffu, mx0, 1));
            mx0 = fmaxf(mx0, __shfl_xor_sync(0xffffffffu, mx0, 2));
            mx1 = fmaxf(mx1, __shfl_xor_sync(0xffffffffu, mx1, 1));
            mx1 = fmaxf(mx1, __shfl_xor_sync(0xffffffffu, mx1, 2));
            const float mn0 = fmaxf(m0r, mx0), mn1 = fmaxf(m1r, mx1);
            const float al0 = __expf(m0r - mn0), al1 = __expf(m1r - mn1);
            m0r = mn0; m1r = mn1;
            float s0 = 0.f, s1 = 0.f;
#pragma unroll
            for (int f = 0; f < 8; f++) {
                s[f][0] = __expf(s[f][0] - mn0);
                s[f][1] = __expf(s[f][1] - mn0);
                s[f][2] = __expf(s[f][2] - mn1);
                s[f][3] = __expf(s[f][3] - mn1);
                s0 += s[f][0] + s[f][1];
                s1 += s[f][2] + s[f][3];
            }
            s0 += __shfl_xor_sync(0xffffffffu, s0, 1);
            s0 += __shfl_xor_sync(0xffffffffu, s0, 2);
            s1 += __shfl_xor_sync(0xffffffffu, s1, 1);
            s1 += __shfl_xor_sync(0xffffffffu, s1, 2);
            l0 = l0 * al0 + s0;
            l1 = l1 * al1 + s1;
#pragma unroll
            for (int f = 0; f < 16; f++) {
                o[f][0] *= al0; o[f][1] *= al0;
                o[f][2] *= al1; o[f][3] *= al1;
            }

            u32 ph[4][4];
#pragma unroll
            for (int j = 0; j < 4; j++) {
                ph[j][0] = round_pack(s[2 * j][0], s[2 * j][1]);
                ph[j][1] = round_pack(s[2 * j][2], s[2 * j][3]);
                ph[j][2] = round_pack(s[2 * j + 1][0], s[2 * j + 1][1]);
                ph[j][3] = round_pack(s[2 * j + 1][2], s[2 * j + 1][3]);
            }

#pragma unroll
            for (int j = 0; j < 4; j++) {
#pragma unroll
                for (int epp = 0; epp < 4; epp++) {
                    u32 vh[2][4];
#pragma unroll
                    for (int e2 = 0; e2 < 2; e2++) {
                        const int ep = epp * 2 + e2;
                        ldsm4t(vh[e2], stg + AVHI + (u32)(j * 16 + vRow) * 256u + (((u32)(ep * 32) + vColT) ^ kSw));
                    }
                    mma16816(o[4 * epp + 0], ph[j], &vh[0][0]);
                    mma16816(o[4 * epp + 1], ph[j], &vh[0][2]);
                    mma16816(o[4 * epp + 2], ph[j], &vh[1][0]);
                    mma16816(o[4 * epp + 3], ph[j], &vh[1][2]);
                }
            }
        }
        if (kt + 2 < nkt) {
            int nst = stage + 2; if (nst >= 3) nst -= 3;
            load_stage(nst, (kt + 2) * 64);
            CP_COMMIT();
        }
        stage++; if (stage >= 3) stage = 0;
    }

    const float inv0 = 1.0f / l0, inv1 = 1.0f / l1;
    const int srow0 = qg0 + wid * 16 + (lane >> 2);
    const size_t ro0 = ((size_t)b * S_ + srow0) * F_ + h * HD_;
    const size_t ro1 = ro0 + (size_t)8 * F_;
#pragma unroll
    for (int f = 0; f < 16; f++) {
        const int e = f * 8 + (lane & 3) * 2;
        *(u32*)(g_AThi + ro0 + e) = round_pack(o[f][0] * inv0, o[f][1] * inv0);
        *(u32*)(g_AThi + ro1 + e) = round_pack(o[f][2] * inv1, o[f][3] * inv1);
    }
}

// ---------------------------------------------------------------------------
extern "C" void kernel_launch(void* const* d_in, const int* in_sizes, int n_in,
                              void* d_out, int out_size)
{
    const float* hs = (const float*)d_in[0];
    const float* cs = (const float*)d_in[1];
    const float* sn = (const float*)d_in[2];
    const float* wq = (const float*)d_in[3];
    const float* wo = (const float*)d_in[4];
    float* out = (float*)d_out;

    cudaFuncSetAttribute(mma_gemm_kernel<0>, cudaFuncAttributeMaxDynamicSharedMemorySize, MMA_SMEM_BYTES);
    cudaFuncSetAttribute(mma_gemm_kernel<1>, cudaFuncAttributeMaxDynamicSharedMemorySize, MMA_SMEM_BYTES);
    cudaFuncSetAttribute(attn_mma_kernel, cudaFuncAttributeMaxDynamicSharedMemorySize, ATT_SMEM_BYTES);

    __half *ahi, *whi, *wohi, *athi;
    cudaGetSymbolAddress((void**)&ahi, g_Ahi);
    cudaGetSymbolAddress((void**)&whi, g_Whi);
    cudaGetSymbolAddress((void**)&wohi, g_Wohi);
    cudaGetSymbolAddress((void**)&athi, g_AThi);

    {
        const int n0 = (M_ * D_) / 4, n1 = (NQKV * D_) / 4, n2 = (D_ * F_) / 4;
        const int nt = n0 + n1 + n2;
        round3_f16_kernel<<<(nt + 255) / 256, 256>>>(
            (const float4*)hs, (uint2*)ahi, n0,
            (const float4*)wq, (uint2*)whi, n1,
            (const float4*)wo, (uint2*)wohi, n2);
    }

    // QKV projection (fp16 single-product, frag double-buffered) + RoPE
    mma_gemm_kernel<0><<<dim3(NQKV / 128, M_ / 128), 128, MMA_SMEM_BYTES>>>(
        ahi, whi, cs, sn, nullptr);

    // Causal flash attention (fp16) -> g_AThi (fp16)
    attn_mma_kernel<<<dim3(S_ / 128, H_, B_), 256, ATT_SMEM_BYTES>>>();

    // Output projection (fp16 single-product, frag double-buffered) -> d_out
    mma_gemm_kernel<1><<<dim3(D_ / 128, M_ / 128), 128, MMA_SMEM_BYTES>>>(
        athi, wohi, nullptr, nullptr, out);
}